// round 1
// baseline (speedup 1.0000x reference)
#include <cuda_runtime.h>
#include <cuda_bf16.h>
#include <math_constants.h>

// Problem constants
#define BATCH 4
#define SEQ   2048
#define DIN   1024
#define HD    1024
#define N3    3072   // 3*HD

// ---------------- device scratch (no allocations allowed) ----------------
__device__ __align__(16) float g_q[BATCH * SEQ * HD];   // 32 MB (pre-scaled by sqrt(H)=32)
__device__ __align__(16) float g_k[BATCH * SEQ * HD];   // 32 MB
__device__ __align__(16) float g_v[BATCH * SEQ * HD];   // 32 MB
__device__ __align__(16) float g_p[(size_t)BATCH * SEQ * SEQ]; // 64 MB scores -> probs
__device__ int g_mask[BATCH * SEQ];  // normalized 0/1 (1 = masked out)
__device__ int g_mask_flag;          // 0=int32, 1=float32, 2=uint8

// ---------------- mask dtype detection + normalization ----------------
__global__ void detect_mask_kernel(const void* mptr) {
    // Scan first 2048 32-bit words (== 8192 bytes, safe for all candidate dtypes).
    const unsigned int* w = (const unsigned int*)mptr;
    __shared__ int okInt, okFloat;
    if (threadIdx.x == 0) { okInt = 1; okFloat = 1; }
    __syncthreads();
    for (int i = threadIdx.x; i < 2048; i += blockDim.x) {
        unsigned int x = w[i];
        if (!(x == 0u || x == 1u))           okInt = 0;
        if (!(x == 0u || x == 0x3F800000u))  okFloat = 0;
    }
    __syncthreads();
    if (threadIdx.x == 0)
        g_mask_flag = okInt ? 0 : (okFloat ? 1 : 2);
}

__global__ void normalize_mask_kernel(const void* mptr) {
    int i = blockIdx.x * blockDim.x + threadIdx.x;  // 8192 total
    if (i >= BATCH * SEQ) return;
    int f = g_mask_flag;
    int v;
    if (f == 0)      v = (((const int*)mptr)[i] != 0);
    else if (f == 1) v = (((const float*)mptr)[i] != 0.0f);
    else             v = (((const unsigned char*)mptr)[i] != 0);
    g_mask[i] = v;
}

// ---------------- tiled SGEMM (128x128x8, 8x8 microtile, 256 threads) ----------------
// MODE 0: proj = qkv[8192,1024] @ W[1024,3072] + b ; route to g_q (x32), g_k, g_v
// MODE 1: scores = q_b[2048,1024] @ k_b[2048,1024]^T -> g_p (per batch z)
// MODE 2: out = p_b[2048,2048] @ v_b[2048,1024] -> d_out (per batch z)
template <int MODE>
__global__ __launch_bounds__(256)
void sgemm_kernel(const float* __restrict__ Ain,
                  const float* __restrict__ Bin,
                  const float* __restrict__ bias,
                  float* __restrict__ Cout)
{
    constexpr int BM = 128, BN = 128, BK = 8;
    constexpr int K  = (MODE == 2) ? 2048 : 1024;

    const int z = blockIdx.z;
    const float* A;
    const float* Bm;
    int lda, ldb;
    if constexpr (MODE == 0) {
        A = Ain; lda = DIN; Bm = Bin; ldb = N3;
    } else if constexpr (MODE == 1) {
        A  = g_q + (size_t)z * SEQ * HD; lda = HD;
        Bm = g_k + (size_t)z * SEQ * HD; ldb = HD;
    } else {
        A  = g_p + (size_t)z * SEQ * SEQ; lda = SEQ;
        Bm = g_v + (size_t)z * SEQ * HD;  ldb = HD;
    }

    const int tid   = threadIdx.x;
    const int mBase = blockIdx.y * BM;
    const int nBase = blockIdx.x * BN;

    __shared__ float As[BK][BM];
    __shared__ float Bs[BK][BN];

    // A tile loader: 128 rows x 8 cols, one float4 per thread, stored transposed
    const int aRow = tid >> 1;           // 0..127
    const int aCol = (tid & 1) << 2;     // 0 or 4
    // B tile loader (row-major case): 8 rows x 128 cols, one float4 per thread
    const int bRow = tid >> 5;           // 0..7
    const int bCol = (tid & 31) << 2;    // 0..124

    const int tr = tid >> 4;             // 0..15
    const int tc = tid & 15;             // 0..15

    float acc[8][8] = {};

    for (int k0 = 0; k0 < K; k0 += BK) {
        float4 a4 = *reinterpret_cast<const float4*>(
            A + (size_t)(mBase + aRow) * lda + k0 + aCol);
        As[aCol + 0][aRow] = a4.x;
        As[aCol + 1][aRow] = a4.y;
        As[aCol + 2][aRow] = a4.z;
        As[aCol + 3][aRow] = a4.w;

        if constexpr (MODE == 1) {
            // B^T access: Bs[k][n] = Bm[n*ldb + k]
            float4 b4 = *reinterpret_cast<const float4*>(
                Bm + (size_t)(nBase + aRow) * ldb + k0 + aCol);
            Bs[aCol + 0][aRow] = b4.x;
            Bs[aCol + 1][aRow] = b4.y;
            Bs[aCol + 2][aRow] = b4.z;
            Bs[aCol + 3][aRow] = b4.w;
        } else {
            float4 b4 = *reinterpret_cast<const float4*>(
                Bm + (size_t)(k0 + bRow) * ldb + nBase + bCol);
            *reinterpret_cast<float4*>(&Bs[bRow][bCol]) = b4;
        }
        __syncthreads();

#pragma unroll
        for (int k = 0; k < BK; k++) {
            float ra[8], rb[8];
            *(float4*)(ra)     = *(const float4*)(&As[k][tr * 8]);
            *(float4*)(ra + 4) = *(const float4*)(&As[k][tr * 8 + 4]);
            *(float4*)(rb)     = *(const float4*)(&Bs[k][tc * 8]);
            *(float4*)(rb + 4) = *(const float4*)(&Bs[k][tc * 8 + 4]);
#pragma unroll
            for (int i = 0; i < 8; i++)
#pragma unroll
                for (int j = 0; j < 8; j++)
                    acc[i][j] = fmaf(ra[i], rb[j], acc[i][j]);
        }
        __syncthreads();
    }

    // ---------------- epilogue ----------------
    if constexpr (MODE == 0) {
        // whole 128-wide n-tile lies in exactly one of q/k/v segments (128 | 1024)
        const int seg  = nBase >> 10;            // 0=q 1=k 2=v
        const int nLoc = (nBase & 1023) + tc * 8;
        float* dst = (seg == 0) ? g_q : (seg == 1) ? g_k : g_v;
        const float scale = (seg == 0) ? 32.0f : 1.0f;  // sqrt(1024)
        float bv[8];
#pragma unroll
        for (int j = 0; j < 8; j++) bv[j] = bias[nBase + tc * 8 + j];
#pragma unroll
        for (int i = 0; i < 8; i++) {
            const int m = mBase + tr * 8 + i;
            float4 o0, o1;
            o0.x = (acc[i][0] + bv[0]) * scale;
            o0.y = (acc[i][1] + bv[1]) * scale;
            o0.z = (acc[i][2] + bv[2]) * scale;
            o0.w = (acc[i][3] + bv[3]) * scale;
            o1.x = (acc[i][4] + bv[4]) * scale;
            o1.y = (acc[i][5] + bv[5]) * scale;
            o1.z = (acc[i][6] + bv[6]) * scale;
            o1.w = (acc[i][7] + bv[7]) * scale;
            float* drow = dst + (size_t)m * HD + nLoc;
            *reinterpret_cast<float4*>(drow)     = o0;
            *reinterpret_cast<float4*>(drow + 4) = o1;
        }
    } else if constexpr (MODE == 1) {
        float* Cb = g_p + (size_t)z * SEQ * SEQ;
#pragma unroll
        for (int i = 0; i < 8; i++) {
            const int m = mBase + tr * 8 + i;
            float* drow = Cb + (size_t)m * SEQ + nBase + tc * 8;
            *reinterpret_cast<float4*>(drow)     = *(const float4*)(&acc[i][0]);
            *reinterpret_cast<float4*>(drow + 4) = *(const float4*)(&acc[i][4]);
        }
    } else {
        float* Cb = Cout + (size_t)z * SEQ * HD;
#pragma unroll
        for (int i = 0; i < 8; i++) {
            const int m = mBase + tr * 8 + i;
            float* drow = Cb + (size_t)m * HD + nBase + tc * 8;
            *reinterpret_cast<float4*>(drow)     = *(const float4*)(&acc[i][0]);
            *reinterpret_cast<float4*>(drow + 4) = *(const float4*)(&acc[i][4]);
        }
    }
}

// ---------------- masked softmax over rows of g_p ----------------
__global__ __launch_bounds__(256)
void softmax_kernel()
{
    const int row = blockIdx.x;          // 0..8191 (= b*SEQ + q)
    const int b   = row >> 11;           // / 2048
    float* p = g_p + (size_t)row * SEQ;
    const int* mk = g_mask + (b << 11);
    const int tid = threadIdx.x;
    __shared__ float red[256];

    // pass 1: masked max
    float mx = -CUDART_INF_F;
#pragma unroll
    for (int t = 0; t < 8; t++) {
        int j = tid + t * 256;
        if (!mk[j]) mx = fmaxf(mx, p[j]);
    }
    red[tid] = mx;
    __syncthreads();
    for (int s = 128; s > 0; s >>= 1) {
        if (tid < s) red[tid] = fmaxf(red[tid], red[tid + s]);
        __syncthreads();
    }
    mx = red[0];
    __syncthreads();

    // pass 2: exp + sum (keep exps in registers)
    float vals[8];
    float sm = 0.0f;
#pragma unroll
    for (int t = 0; t < 8; t++) {
        int j = tid + t * 256;
        float e = mk[j] ? 0.0f : __expf(p[j] - mx);
        vals[t] = e;
        sm += e;
    }
    red[tid] = sm;
    __syncthreads();
    for (int s = 128; s > 0; s >>= 1) {
        if (tid < s) red[tid] += red[tid + s];
        __syncthreads();
    }
    const float inv = 1.0f / red[0];

    // pass 3: write normalized probabilities
#pragma unroll
    for (int t = 0; t < 8; t++)
        p[tid + t * 256] = vals[t] * inv;
}

// ---------------- launch ----------------
extern "C" void kernel_launch(void* const* d_in, const int* in_sizes, int n_in,
                              void* d_out, int out_size)
{
    const float* qkv  = (const float*)d_in[0];
    const void*  mask = d_in[1];
    const float* W    = (const float*)d_in[2];
    const float* bqkv = (const float*)d_in[3];
    float* out = (float*)d_out;

    detect_mask_kernel<<<1, 256>>>(mask);
    normalize_mask_kernel<<<(BATCH * SEQ + 255) / 256, 256>>>(mask);

    // GEMM1: QKV projection  (M=8192, N=3072, K=1024)
    {
        dim3 grid(N3 / 128, (BATCH * SEQ) / 128, 1);
        sgemm_kernel<0><<<grid, 256>>>(qkv, W, bqkv, nullptr);
    }
    // GEMM2: scores = q @ k^T per batch
    {
        dim3 grid(SEQ / 128, SEQ / 128, BATCH);
        sgemm_kernel<1><<<grid, 256>>>(nullptr, nullptr, nullptr, nullptr);
    }
    // masked softmax over 8192 rows
    softmax_kernel<<<BATCH * SEQ, 256>>>();

    // GEMM3: out = P @ v per batch
    {
        dim3 grid(HD / 128, SEQ / 128, BATCH);
        sgemm_kernel<2><<<grid, 256>>>(nullptr, nullptr, nullptr, out);
    }
}

// round 3
// speedup vs baseline: 1.5009x; 1.5009x over previous
#include <cuda_runtime.h>
#include <cuda_fp16.h>
#include <math_constants.h>
#include <cstdint>

// Problem constants
#define BATCH 4
#define SEQ   2048
#define DIN   1024
#define HD    1024
#define N3    3072   // 3*HD

// ---------------- device scratch (no allocations allowed) ----------------
__device__ __align__(16) float g_q[BATCH * SEQ * HD];   // q (pre-scaled by 32)
__device__ __align__(16) float g_k[BATCH * SEQ * HD];
__device__ __align__(16) float g_v[BATCH * SEQ * HD];
__device__ __align__(16) float g_vt[BATCH * HD * SEQ];  // V^T per batch
__device__ __align__(16) float g_wt[N3 * DIN];          // W^T
__device__ __align__(16) float g_p[(size_t)BATCH * SEQ * SEQ]; // scores -> probs
__device__ int g_mask[BATCH * SEQ];
__device__ int g_mask_flag;

// ---------------- helpers ----------------
__device__ __forceinline__ uint32_t smem_u32(const void* p) {
    uint32_t a;
    asm("{ .reg .u64 t; cvta.to.shared.u64 t, %1; cvt.u32.u64 %0, t; }" : "=r"(a) : "l"(p));
    return a;
}

__device__ __forceinline__ void ldm4(uint32_t* r, uint32_t addr) {
    asm volatile("ldmatrix.sync.aligned.m8n8.x4.shared.b16 {%0,%1,%2,%3}, [%4];"
                 : "=r"(r[0]), "=r"(r[1]), "=r"(r[2]), "=r"(r[3]) : "r"(addr));
}

__device__ __forceinline__ void mma16816(float* c, const uint32_t* a,
                                         uint32_t b0, uint32_t b1) {
    asm volatile(
        "mma.sync.aligned.m16n8k16.row.col.f32.f16.f16.f32 "
        "{%0,%1,%2,%3}, {%4,%5,%6,%7}, {%8,%9}, {%0,%1,%2,%3};"
        : "+f"(c[0]), "+f"(c[1]), "+f"(c[2]), "+f"(c[3])
        : "r"(a[0]), "r"(a[1]), "r"(a[2]), "r"(a[3]), "r"(b0), "r"(b1));
}

// ---------------- mask dtype detection + normalization ----------------
__global__ void detect_mask_kernel(const void* mptr) {
    const unsigned int* w = (const unsigned int*)mptr;
    __shared__ int okInt, okFloat;
    if (threadIdx.x == 0) { okInt = 1; okFloat = 1; }
    __syncthreads();
    for (int i = threadIdx.x; i < 2048; i += blockDim.x) {
        unsigned int x = w[i];
        if (!(x == 0u || x == 1u))          okInt = 0;
        if (!(x == 0u || x == 0x3F800000u)) okFloat = 0;
    }
    __syncthreads();
    if (threadIdx.x == 0) g_mask_flag = okInt ? 0 : (okFloat ? 1 : 2);
}

__global__ void normalize_mask_kernel(const void* mptr) {
    int i = blockIdx.x * blockDim.x + threadIdx.x;
    if (i >= BATCH * SEQ) return;
    int f = g_mask_flag, v;
    if (f == 0)      v = (((const int*)mptr)[i] != 0);
    else if (f == 1) v = (((const float*)mptr)[i] != 0.0f);
    else             v = (((const unsigned char*)mptr)[i] != 0);
    g_mask[i] = v;
}

// ---------------- transpose: out[C][R] = in[R][C] (per batch z) ----------------
__global__ void transpose_kernel(const float* __restrict__ in, float* __restrict__ out,
                                 int R, int C, size_t inBatch, size_t outBatch)
{
    in  += (size_t)blockIdx.z * inBatch;
    out += (size_t)blockIdx.z * outBatch;
    __shared__ float t[32][33];
    int bx = blockIdx.x * 32, by = blockIdx.y * 32;
    int x = threadIdx.x, y = threadIdx.y;
#pragma unroll
    for (int i = y; i < 32; i += 8) t[i][x] = in[(size_t)(by + i) * C + bx + x];
    __syncthreads();
#pragma unroll
    for (int i = y; i < 32; i += 8) out[(size_t)(bx + i) * R + by + x] = t[x][i];
}

// ---------------- fp16x3 split GEMM via mma.sync, 128x128x32 tile ----------------
// C[M,N] = A[M,K] (row-major) @ B[N,K]^T (row-major, K-contig)
// MODE 0: qkv[8192,1024] @ g_wt[3072,1024]^T + bias, route q*32/k/v
// MODE 1: q_b[2048,1024] @ k_b[2048,1024]^T -> g_p
// MODE 2: p_b[2048,2048] @ g_vt_b[1024,2048]^T -> out
#define ROWB   80                         // smem row pitch (bytes) for 32 halfs
#define TILE_B (128 * ROWB)               // 10240 B per half-tile
#define STAGE_B (4 * TILE_B)              // Ah, Al, Bh, Bl
#define SMEM_TOT (2 * STAGE_B)            // 81920

template <int MODE>
__global__ __launch_bounds__(256, 1)
void hmma_gemm(const float* __restrict__ Ag, const float* __restrict__ bias,
               float* __restrict__ Cout)
{
    constexpr int K  = (MODE == 2) ? 2048 : 1024;
    constexpr int NT = K / 32;

    extern __shared__ char smem[];
    const uint32_t sbase = smem_u32(smem);
    const int tid  = threadIdx.x;
    const int wid  = tid >> 5;
    const int lane = tid & 31;
    const int wm   = wid & 1;        // 2 m-blocks of 64
    const int wn   = wid >> 1;       // 4 n-blocks of 32
    const int z    = blockIdx.z;

    const float* A; const float* B; int lda, ldb;
    if constexpr (MODE == 0) { A = Ag; lda = DIN; B = g_wt; ldb = DIN; }
    else if constexpr (MODE == 1) {
        A = g_q + (size_t)z * SEQ * HD; lda = HD;
        B = g_k + (size_t)z * SEQ * HD; ldb = HD;
    } else {
        A = g_p  + (size_t)z * SEQ * SEQ; lda = SEQ;
        B = g_vt + (size_t)z * HD * SEQ;  ldb = SEQ;
    }
    const int mBase = blockIdx.y * 128;
    const int nBase = blockIdx.x * 128;

    // global loader coords: thread t -> row (t&127), 16-float column group (t>>7)
    const int lrow = tid & 127;
    const int lcol = (tid >> 7) * 16;
    const float* Arow = A + (size_t)(mBase + lrow) * lda + lcol;
    const float* Brow = B + (size_t)(nBase + lrow) * ldb + lcol;
    const uint32_t so = (uint32_t)lrow * ROWB + lcol * 2;   // smem byte offset

    // ldmatrix per-lane offsets (bytes, relative to tile base)
    const int r8   = lane & 7;
    const int hi8  = (lane >> 3) & 1;
    const int kq   = (lane >> 4) * 8;        // 0 or 8 halfs
    const int roff = r8 + hi8 * 8;
    uint32_t aoffs[4], boffs[2];
#pragma unroll
    for (int mt = 0; mt < 4; mt++)
        aoffs[mt] = (uint32_t)(wm * 64 + mt * 16 + roff) * ROWB + kq * 2;
#pragma unroll
    for (int ng = 0; ng < 2; ng++)
        boffs[ng] = (uint32_t)(wn * 32 + ng * 16 + roff) * ROWB + kq * 2;

    float acc[4][4][4] = {};   // [m-tile][n8-tile][frag]

    float4 pa[4], pb[4];
    // prologue: load kt=0
#pragma unroll
    for (int i = 0; i < 4; i++) {
        pa[i] = *(const float4*)(Arow + 4 * i);
        pb[i] = *(const float4*)(Brow + 4 * i);
    }
    // split + store stage 0
    {
        char* st = smem;
        __half h[16], l[16];
#pragma unroll
        for (int i = 0; i < 4; i++) {
            const float* f = (const float*)&pa[i];
#pragma unroll
            for (int j = 0; j < 4; j++) {
                __half hh = __float2half_rn(f[j]);
                h[4 * i + j] = hh;
                l[4 * i + j] = __float2half_rn(f[j] - __half2float(hh));
            }
        }
        *(uint4*)(st + so)               = *(uint4*)(h);
        *(uint4*)(st + so + 16)          = *(uint4*)(h + 8);
        *(uint4*)(st + TILE_B + so)      = *(uint4*)(l);
        *(uint4*)(st + TILE_B + so + 16) = *(uint4*)(l + 8);
#pragma unroll
        for (int i = 0; i < 4; i++) {
            const float* f = (const float*)&pb[i];
#pragma unroll
            for (int j = 0; j < 4; j++) {
                __half hh = __float2half_rn(f[j]);
                h[4 * i + j] = hh;
                l[4 * i + j] = __float2half_rn(f[j] - __half2float(hh));
            }
        }
        *(uint4*)(st + 2 * TILE_B + so)      = *(uint4*)(h);
        *(uint4*)(st + 2 * TILE_B + so + 16) = *(uint4*)(h + 8);
        *(uint4*)(st + 3 * TILE_B + so)      = *(uint4*)(l);
        *(uint4*)(st + 3 * TILE_B + so + 16) = *(uint4*)(l + 8);
    }
    __syncthreads();

    for (int kt = 0; kt < NT; kt++) {
        const int s = kt & 1;
        // prefetch next k-tile from global
        if (kt + 1 < NT) {
#pragma unroll
            for (int i = 0; i < 4; i++) {
                pa[i] = *(const float4*)(Arow + (kt + 1) * 32 + 4 * i);
                pb[i] = *(const float4*)(Brow + (kt + 1) * 32 + 4 * i);
            }
        }

        // compute on stage s
        const uint32_t stb = sbase + s * STAGE_B;
#pragma unroll
        for (int ks = 0; ks < 2; ks++) {
            uint32_t ah[4][4], al[4][4], bh[2][4], bl[2][4];
#pragma unroll
            for (int mt = 0; mt < 4; mt++) {
                ldm4(ah[mt], stb + aoffs[mt] + ks * 32);
                ldm4(al[mt], stb + TILE_B + aoffs[mt] + ks * 32);
            }
#pragma unroll
            for (int ng = 0; ng < 2; ng++) {
                ldm4(bh[ng], stb + 2 * TILE_B + boffs[ng] + ks * 32);
                ldm4(bl[ng], stb + 3 * TILE_B + boffs[ng] + ks * 32);
            }
#pragma unroll
            for (int mt = 0; mt < 4; mt++) {
#pragma unroll
                for (int nt = 0; nt < 4; nt++) {
                    const int ng = nt >> 1, nb = nt & 1;
                    mma16816(acc[mt][nt], ah[mt], bh[ng][nb], bh[ng][nb + 2]);
                    mma16816(acc[mt][nt], ah[mt], bl[ng][nb], bl[ng][nb + 2]);
                    mma16816(acc[mt][nt], al[mt], bh[ng][nb], bh[ng][nb + 2]);
                }
            }
        }

        // store next stage
        if (kt + 1 < NT) {
            char* st = smem + (s ^ 1) * STAGE_B;
            __half h[16], l[16];
#pragma unroll
            for (int i = 0; i < 4; i++) {
                const float* f = (const float*)&pa[i];
#pragma unroll
                for (int j = 0; j < 4; j++) {
                    __half hh = __float2half_rn(f[j]);
                    h[4 * i + j] = hh;
                    l[4 * i + j] = __float2half_rn(f[j] - __half2float(hh));
                }
            }
            *(uint4*)(st + so)               = *(uint4*)(h);
            *(uint4*)(st + so + 16)          = *(uint4*)(h + 8);
            *(uint4*)(st + TILE_B + so)      = *(uint4*)(l);
            *(uint4*)(st + TILE_B + so + 16) = *(uint4*)(l + 8);
#pragma unroll
            for (int i = 0; i < 4; i++) {
                const float* f = (const float*)&pb[i];
#pragma unroll
                for (int j = 0; j < 4; j++) {
                    __half hh = __float2half_rn(f[j]);
                    h[4 * i + j] = hh;
                    l[4 * i + j] = __float2half_rn(f[j] - __half2float(hh));
                }
            }
            *(uint4*)(st + 2 * TILE_B + so)      = *(uint4*)(h);
            *(uint4*)(st + 2 * TILE_B + so + 16) = *(uint4*)(h + 8);
            *(uint4*)(st + 3 * TILE_B + so)      = *(uint4*)(l);
            *(uint4*)(st + 3 * TILE_B + so + 16) = *(uint4*)(l + 8);
        }
        __syncthreads();
    }

    // ---------------- epilogue ----------------
    const int rl = lane >> 2;            // 0..7
    const int cl = 2 * (lane & 3);       // 0,2,4,6
#pragma unroll
    for (int mt = 0; mt < 4; mt++) {
#pragma unroll
        for (int nt = 0; nt < 4; nt++) {
            const int r0 = mBase + wm * 64 + mt * 16 + rl;
            const int c0 = nBase + wn * 32 + nt * 8 + cl;
            float* cc = acc[mt][nt];
            if constexpr (MODE == 0) {
                const int seg = c0 >> 10;             // 0=q 1=k 2=v
                float* dst = (seg == 0) ? g_q : (seg == 1) ? g_k : g_v;
                const float scale = (seg == 0) ? 32.0f : 1.0f;
                const int lc = c0 & 1023;
                const float bx = bias[c0], by = bias[c0 + 1];
                float2 o0 = { (cc[0] + bx) * scale, (cc[1] + by) * scale };
                float2 o1 = { (cc[2] + bx) * scale, (cc[3] + by) * scale };
                *(float2*)(dst + (size_t)r0 * HD + lc)       = o0;
                *(float2*)(dst + (size_t)(r0 + 8) * HD + lc) = o1;
            } else if constexpr (MODE == 1) {
                float* Cb = g_p + (size_t)z * SEQ * SEQ;
                *(float2*)(Cb + (size_t)r0 * SEQ + c0)       = make_float2(cc[0], cc[1]);
                *(float2*)(Cb + (size_t)(r0 + 8) * SEQ + c0) = make_float2(cc[2], cc[3]);
            } else {
                float* Cb = Cout + (size_t)z * SEQ * HD;
                *(float2*)(Cb + (size_t)r0 * HD + c0)        = make_float2(cc[0], cc[1]);
                *(float2*)(Cb + (size_t)(r0 + 8) * HD + c0)  = make_float2(cc[2], cc[3]);
            }
        }
    }
}

// ---------------- masked softmax over rows of g_p ----------------
__global__ __launch_bounds__(256)
void softmax_kernel()
{
    const int row = blockIdx.x;          // 0..8191
    const int b   = row >> 11;
    float* p = g_p + (size_t)row * SEQ;
    const int* mk = g_mask + (b << 11);
    const int tid = threadIdx.x;
    __shared__ float red[256];

    float mx = -CUDART_INF_F;
#pragma unroll
    for (int t = 0; t < 8; t++) {
        int j = tid + t * 256;
        if (!mk[j]) mx = fmaxf(mx, p[j]);
    }
    red[tid] = mx;
    __syncthreads();
    for (int s = 128; s > 0; s >>= 1) {
        if (tid < s) red[tid] = fmaxf(red[tid], red[tid + s]);
        __syncthreads();
    }
    mx = red[0];
    __syncthreads();

    float vals[8];
    float sm = 0.0f;
#pragma unroll
    for (int t = 0; t < 8; t++) {
        int j = tid + t * 256;
        float e = mk[j] ? 0.0f : __expf(p[j] - mx);
        vals[t] = e;
        sm += e;
    }
    red[tid] = sm;
    __syncthreads();
    for (int s = 128; s > 0; s >>= 1) {
        if (tid < s) red[tid] += red[tid + s];
        __syncthreads();
    }
    const float inv = 1.0f / red[0];
#pragma unroll
    for (int t = 0; t < 8; t++)
        p[tid + t * 256] = vals[t] * inv;
}

// ---------------- launch ----------------
extern "C" void kernel_launch(void* const* d_in, const int* in_sizes, int n_in,
                              void* d_out, int out_size)
{
    const float* qkv  = (const float*)d_in[0];
    const void*  mask = d_in[1];
    const float* W    = (const float*)d_in[2];
    const float* bqkv = (const float*)d_in[3];
    float* out = (float*)d_out;

    cudaFuncSetAttribute(hmma_gemm<0>, cudaFuncAttributeMaxDynamicSharedMemorySize, SMEM_TOT);
    cudaFuncSetAttribute(hmma_gemm<1>, cudaFuncAttributeMaxDynamicSharedMemorySize, SMEM_TOT);
    cudaFuncSetAttribute(hmma_gemm<2>, cudaFuncAttributeMaxDynamicSharedMemorySize, SMEM_TOT);

    detect_mask_kernel<<<1, 256>>>(mask);
    normalize_mask_kernel<<<(BATCH * SEQ + 255) / 256, 256>>>(mask);

    // transpose W: [1024,3072] -> g_wt [3072,1024]
    {
        float* wt; cudaGetSymbolAddress((void**)&wt, g_wt);
        dim3 grid(N3 / 32, DIN / 32, 1);
        transpose_kernel<<<grid, dim3(32, 8)>>>(W, wt, DIN, N3, 0, 0);
    }

    // GEMM1: QKV projection (M=8192, N=3072, K=1024)
    {
        dim3 grid(N3 / 128, (BATCH * SEQ) / 128, 1);
        hmma_gemm<0><<<grid, 256, SMEM_TOT>>>(qkv, bqkv, nullptr);
    }

    // transpose V per batch: [2048,1024] -> g_vt [1024,2048]
    {
        float *v, *vt;
        cudaGetSymbolAddress((void**)&v, g_v);
        cudaGetSymbolAddress((void**)&vt, g_vt);
        dim3 grid(DIN / 32, SEQ / 32, BATCH);
        transpose_kernel<<<grid, dim3(32, 8)>>>(v, vt, SEQ, HD,
                                                (size_t)SEQ * HD, (size_t)HD * SEQ);
    }

    // GEMM2: scores = q @ k^T per batch
    {
        dim3 grid(SEQ / 128, SEQ / 128, BATCH);
        hmma_gemm<1><<<grid, 256, SMEM_TOT>>>(nullptr, nullptr, nullptr);
    }

    softmax_kernel<<<BATCH * SEQ, 256>>>();

    // GEMM3: out = P @ v per batch
    {
        dim3 grid(HD / 128, SEQ / 128, BATCH);
        hmma_gemm<2><<<grid, 256, SMEM_TOT>>>(nullptr, nullptr, out);
    }
}

// round 4
// speedup vs baseline: 2.3863x; 1.5899x over previous
#include <cuda_runtime.h>
#include <cuda_fp16.h>
#include <math_constants.h>
#include <cstdint>

// Problem constants
#define BATCH 4
#define SEQ   2048
#define DIN   1024
#define HD    1024
#define N3    3072   // 3*HD

// ---------------- device scratch (no allocations allowed) ----------------
__device__ __align__(16) __half g_qkvh[BATCH * SEQ * DIN];
__device__ __align__(16) __half g_qkvl[BATCH * SEQ * DIN];
__device__ __align__(16) __half g_wth[N3 * DIN];
__device__ __align__(16) __half g_wtl[N3 * DIN];
__device__ __align__(16) __half g_qh[BATCH * SEQ * HD];
__device__ __align__(16) __half g_ql[BATCH * SEQ * HD];
__device__ __align__(16) __half g_kh[BATCH * SEQ * HD];
__device__ __align__(16) __half g_kl[BATCH * SEQ * HD];
__device__ __align__(16) float  g_v[BATCH * SEQ * HD];
__device__ __align__(16) __half g_vth[BATCH * HD * SEQ];
__device__ __align__(16) __half g_vtl[BATCH * HD * SEQ];
__device__ __align__(16) float  g_p[(size_t)BATCH * SEQ * SEQ];
__device__ __align__(16) __half g_ph[(size_t)BATCH * SEQ * SEQ];
__device__ __align__(16) __half g_pl[(size_t)BATCH * SEQ * SEQ];
__device__ int g_mask[BATCH * SEQ];
__device__ int g_mask_flag;

// ---------------- helpers ----------------
__device__ __forceinline__ uint32_t smem_u32(const void* p) {
    uint32_t a;
    asm("{ .reg .u64 t; cvta.to.shared.u64 t, %1; cvt.u32.u64 %0, t; }" : "=r"(a) : "l"(p));
    return a;
}
__device__ __forceinline__ void ldm4(uint32_t* r, uint32_t addr) {
    asm volatile("ldmatrix.sync.aligned.m8n8.x4.shared.b16 {%0,%1,%2,%3}, [%4];"
                 : "=r"(r[0]), "=r"(r[1]), "=r"(r[2]), "=r"(r[3]) : "r"(addr));
}
__device__ __forceinline__ void mma16816(float* c, const uint32_t* a,
                                         uint32_t b0, uint32_t b1) {
    asm volatile(
        "mma.sync.aligned.m16n8k16.row.col.f32.f16.f16.f32 "
        "{%0,%1,%2,%3}, {%4,%5,%6,%7}, {%8,%9}, {%0,%1,%2,%3};"
        : "+f"(c[0]), "+f"(c[1]), "+f"(c[2]), "+f"(c[3])
        : "r"(a[0]), "r"(a[1]), "r"(a[2]), "r"(a[3]), "r"(b0), "r"(b1));
}
__device__ __forceinline__ void cpa16(uint32_t dst, const void* src) {
    asm volatile("cp.async.cg.shared.global [%0], [%1], 16;" :: "r"(dst), "l"(src));
}
#define CP_COMMIT() asm volatile("cp.async.commit_group;" ::: "memory")
#define CP_WAIT(n)  asm volatile("cp.async.wait_group %0;" :: "n"(n) : "memory")

// ---------------- mask dtype detection + normalization ----------------
__global__ void detect_mask_kernel(const void* mptr) {
    const unsigned int* w = (const unsigned int*)mptr;
    __shared__ int okInt, okFloat;
    if (threadIdx.x == 0) { okInt = 1; okFloat = 1; }
    __syncthreads();
    for (int i = threadIdx.x; i < 2048; i += blockDim.x) {
        unsigned int x = w[i];
        if (!(x == 0u || x == 1u))          okInt = 0;
        if (!(x == 0u || x == 0x3F800000u)) okFloat = 0;
    }
    __syncthreads();
    if (threadIdx.x == 0) g_mask_flag = okInt ? 0 : (okFloat ? 1 : 2);
}
__global__ void normalize_mask_kernel(const void* mptr) {
    int i = blockIdx.x * blockDim.x + threadIdx.x;
    if (i >= BATCH * SEQ) return;
    int f = g_mask_flag, v;
    if (f == 0)      v = (((const int*)mptr)[i] != 0);
    else if (f == 1) v = (((const float*)mptr)[i] != 0.0f);
    else             v = (((const unsigned char*)mptr)[i] != 0);
    g_mask[i] = v;
}

// ---------------- elementwise split: fp32 -> (hi, lo) fp16 ----------------
__global__ __launch_bounds__(256)
void split_kernel(const float* __restrict__ in, __half* __restrict__ oh,
                  __half* __restrict__ ol, int n4)
{
    int i = blockIdx.x * blockDim.x + threadIdx.x;
    if (i >= n4) return;
    float4 v = ((const float4*)in)[i];
    __half h0 = __float2half_rn(v.x), h1 = __float2half_rn(v.y);
    __half h2 = __float2half_rn(v.z), h3 = __float2half_rn(v.w);
    __half l0 = __float2half_rn(v.x - __half2float(h0));
    __half l1 = __float2half_rn(v.y - __half2float(h1));
    __half l2 = __float2half_rn(v.z - __half2float(h2));
    __half l3 = __float2half_rn(v.w - __half2float(h3));
    ((__half2*)oh)[2 * i]     = __halves2half2(h0, h1);
    ((__half2*)oh)[2 * i + 1] = __halves2half2(h2, h3);
    ((__half2*)ol)[2 * i]     = __halves2half2(l0, l1);
    ((__half2*)ol)[2 * i + 1] = __halves2half2(l2, l3);
}

// ---------------- transpose + split: out[c][r] = split(in[r][c]) ----------------
__global__ void transpose_split_kernel(const float* __restrict__ in,
                                       __half* __restrict__ oh, __half* __restrict__ ol,
                                       int R, int C, size_t inBatch, size_t outBatch)
{
    in += (size_t)blockIdx.z * inBatch;
    oh += (size_t)blockIdx.z * outBatch;
    ol += (size_t)blockIdx.z * outBatch;
    __shared__ float t[32][33];
    int bx = blockIdx.x * 32, by = blockIdx.y * 32;
    int x = threadIdx.x, y = threadIdx.y;
#pragma unroll
    for (int i = y; i < 32; i += 8) t[i][x] = in[(size_t)(by + i) * C + bx + x];
    __syncthreads();
#pragma unroll
    for (int i = y; i < 32; i += 8) {
        float w = t[x][i];
        __half h = __float2half_rn(w);
        size_t idx = (size_t)(bx + i) * R + by + x;
        oh[idx] = h;
        ol[idx] = __float2half_rn(w - __half2float(h));
    }
}

// ---------------- fp16x3 split GEMM, CTA 256x128x32, warp 64x64, cp.async ----
// C[M,N] = A[M,K] @ B[N,K]^T, A/B pre-split into fp16 hi/lo, K-major rows.
// MODE 0: qkv_split @ wt_split + bias -> route q(h,l)*32 / k(h,l) / v(fp32)
// MODE 1: q_split @ k_split -> g_p (fp32, per batch z)
// MODE 2: p_split @ vt_split -> out (fp32, per batch z)
#define NSTAGE   3
#define ST_AH    0
#define ST_AL    16384
#define ST_BH    32768
#define ST_BL    40960
#define STAGE_SZ 49152
#define SMEM_TOT (NSTAGE * STAGE_SZ)   // 147456

template <int MODE>
__global__ __launch_bounds__(256, 1)
void hmma_gemm(const float* __restrict__ bias, float* __restrict__ Cout)
{
    constexpr int K  = (MODE == 2) ? 2048 : 1024;
    constexpr int NT = K / 32;

    extern __shared__ char smem[];
    const uint32_t sbase = smem_u32(smem);
    const int tid  = threadIdx.x;
    const int wid  = tid >> 5;
    const int lane = tid & 31;
    const int wm   = wid >> 1;       // 0..3 : 64-row block
    const int wn   = wid & 1;        // 0..1 : 64-col block
    const int z    = blockIdx.z;

    const __half *Ah, *Al, *Bh, *Bl;
    if constexpr (MODE == 0) {
        Ah = g_qkvh; Al = g_qkvl; Bh = g_wth; Bl = g_wtl;
    } else if constexpr (MODE == 1) {
        Ah = g_qh + (size_t)z * SEQ * HD; Al = g_ql + (size_t)z * SEQ * HD;
        Bh = g_kh + (size_t)z * SEQ * HD; Bl = g_kl + (size_t)z * SEQ * HD;
    } else {
        Ah = g_ph + (size_t)z * SEQ * SEQ; Al = g_pl + (size_t)z * SEQ * SEQ;
        Bh = g_vth + (size_t)z * HD * SEQ; Bl = g_vtl + (size_t)z * HD * SEQ;
    }
    const int mBase = blockIdx.y * 256;
    const int nBase = blockIdx.x * 128;

    // ---- cp.async loader state ----
    const int lrow = tid >> 2;                       // 0..63 (tile-local base row)
    const int lc   = tid & 3;                        // 16B chunk in 64B row
    const uint32_t swc = (uint32_t)((lc ^ ((lrow >> 1) & 3)) << 4);
    const uint32_t dA0 = (uint32_t)lrow * 64 + swc;  // chunk i adds i*4096 (64 rows)
    const __half* pAh = Ah + (size_t)(mBase + lrow) * K + lc * 8;
    const __half* pAl = Al + (size_t)(mBase + lrow) * K + lc * 8;
    const __half* pBh = Bh + (size_t)(nBase + lrow) * K + lc * 8;
    const __half* pBl = Bl + (size_t)(nBase + lrow) * K + lc * 8;

    // ---- ldmatrix fragment addressing ----
    const int roff = (lane & 7) + ((lane >> 3) & 1) * 8;  // 0..15
    const int cq   = lane >> 4;                           // 0..1
    const int xr   = (roff >> 1) & 3;
    const uint32_t abase = (uint32_t)(wm * 64 + roff) * 64;
    const uint32_t bbase = (uint32_t)(wn * 64 + roff) * 64;
    uint32_t kc[2];
    kc[0] = (uint32_t)(((0 * 2 + cq) ^ xr) << 4);
    kc[1] = (uint32_t)(((1 * 2 + cq) ^ xr) << 4);

    float acc[4][8][4] = {};

    // ---- prologue: issue NSTAGE-1 stages ----
#pragma unroll
    for (int s = 0; s < NSTAGE - 1; s++) {
        const uint32_t sb = sbase + s * STAGE_SZ;
#pragma unroll
        for (int i = 0; i < 4; i++) {
            cpa16(sb + ST_AH + dA0 + i * 4096, pAh + (size_t)i * 64 * K);
            cpa16(sb + ST_AL + dA0 + i * 4096, pAl + (size_t)i * 64 * K);
        }
#pragma unroll
        for (int i = 0; i < 2; i++) {
            cpa16(sb + ST_BH + dA0 + i * 4096, pBh + (size_t)i * 64 * K);
            cpa16(sb + ST_BL + dA0 + i * 4096, pBl + (size_t)i * 64 * K);
        }
        pAh += 32; pAl += 32; pBh += 32; pBl += 32;
        CP_COMMIT();
    }

    for (int kt = 0; kt < NT; kt++) {
        CP_WAIT(NSTAGE - 2);
        __syncthreads();

        // issue stage kt+NSTAGE-1
        if (kt + NSTAGE - 1 < NT) {
            const uint32_t sb = sbase + ((kt + NSTAGE - 1) % NSTAGE) * STAGE_SZ;
#pragma unroll
            for (int i = 0; i < 4; i++) {
                cpa16(sb + ST_AH + dA0 + i * 4096, pAh + (size_t)i * 64 * K);
                cpa16(sb + ST_AL + dA0 + i * 4096, pAl + (size_t)i * 64 * K);
            }
#pragma unroll
            for (int i = 0; i < 2; i++) {
                cpa16(sb + ST_BH + dA0 + i * 4096, pBh + (size_t)i * 64 * K);
                cpa16(sb + ST_BL + dA0 + i * 4096, pBl + (size_t)i * 64 * K);
            }
            pAh += 32; pAl += 32; pBh += 32; pBl += 32;
        }
        CP_COMMIT();

        // compute on stage kt
        const uint32_t stb = sbase + (kt % NSTAGE) * STAGE_SZ;
#pragma unroll
        for (int ks = 0; ks < 2; ks++) {
            uint32_t ah[4][4], al[4][4], bh[4][4], bl[4][4];
#pragma unroll
            for (int mt = 0; mt < 4; mt++) {
                ldm4(ah[mt], stb + ST_AH + abase + mt * 1024 + kc[ks]);
                ldm4(al[mt], stb + ST_AL + abase + mt * 1024 + kc[ks]);
            }
#pragma unroll
            for (int ng = 0; ng < 4; ng++) {
                ldm4(bh[ng], stb + ST_BH + bbase + ng * 1024 + kc[ks]);
                ldm4(bl[ng], stb + ST_BL + bbase + ng * 1024 + kc[ks]);
            }
#pragma unroll
            for (int mt = 0; mt < 4; mt++) {
#pragma unroll
                for (int ng = 0; ng < 4; ng++) {
#pragma unroll
                    for (int nb = 0; nb < 2; nb++) {
                        float* cc = acc[mt][ng * 2 + nb];
                        mma16816(cc, ah[mt], bh[ng][nb], bh[ng][nb + 2]);
                        mma16816(cc, ah[mt], bl[ng][nb], bl[ng][nb + 2]);
                        mma16816(cc, al[mt], bh[ng][nb], bh[ng][nb + 2]);
                    }
                }
            }
        }
    }

    // ---------------- epilogue ----------------
    const int rl = lane >> 2;            // 0..7
    const int cl = 2 * (lane & 3);       // 0,2,4,6
#pragma unroll
    for (int mt = 0; mt < 4; mt++) {
#pragma unroll
        for (int nt = 0; nt < 8; nt++) {
            const int r0 = mBase + wm * 64 + mt * 16 + rl;
            const int c0 = nBase + wn * 64 + nt * 8 + cl;
            float* cc = acc[mt][nt];
            if constexpr (MODE == 0) {
                const int seg = c0 >> 10;             // 0=q 1=k 2=v
                const int lcc = c0 & 1023;
                const float b0 = bias[c0], b1 = bias[c0 + 1];
                if (seg == 2) {
                    *(float2*)(g_v + (size_t)r0 * HD + lcc)       = make_float2(cc[0] + b0, cc[1] + b1);
                    *(float2*)(g_v + (size_t)(r0 + 8) * HD + lcc) = make_float2(cc[2] + b0, cc[3] + b1);
                } else {
                    __half* dh = (seg == 0) ? g_qh : g_kh;
                    __half* dl = (seg == 0) ? g_ql : g_kl;
                    const float sc = (seg == 0) ? 32.0f : 1.0f;
#pragma unroll
                    for (int rr = 0; rr < 2; rr++) {
                        float w0 = (cc[2 * rr + 0] + b0) * sc;
                        float w1 = (cc[2 * rr + 1] + b1) * sc;
                        __half h0 = __float2half_rn(w0), h1 = __float2half_rn(w1);
                        __half l0 = __float2half_rn(w0 - __half2float(h0));
                        __half l1 = __float2half_rn(w1 - __half2float(h1));
                        size_t idx = (size_t)(r0 + 8 * rr) * HD + lcc;
                        *(__half2*)(dh + idx) = __halves2half2(h0, h1);
                        *(__half2*)(dl + idx) = __halves2half2(l0, l1);
                    }
                }
            } else if constexpr (MODE == 1) {
                float* Cb = g_p + (size_t)z * SEQ * SEQ;
                *(float2*)(Cb + (size_t)r0 * SEQ + c0)       = make_float2(cc[0], cc[1]);
                *(float2*)(Cb + (size_t)(r0 + 8) * SEQ + c0) = make_float2(cc[2], cc[3]);
            } else {
                float* Cb = Cout + (size_t)z * SEQ * HD;
                *(float2*)(Cb + (size_t)r0 * HD + c0)        = make_float2(cc[0], cc[1]);
                *(float2*)(Cb + (size_t)(r0 + 8) * HD + c0)  = make_float2(cc[2], cc[3]);
            }
        }
    }
}

// ---------------- masked softmax: g_p (fp32) -> g_ph/g_pl (fp16 split) ------
__global__ __launch_bounds__(256)
void softmax_kernel()
{
    const int row = blockIdx.x;          // 0..8191
    const int b   = row >> 11;
    float* p = g_p + (size_t)row * SEQ;
    __half* ph = g_ph + (size_t)row * SEQ;
    __half* pl = g_pl + (size_t)row * SEQ;
    const int* mk = g_mask + (b << 11);
    const int tid = threadIdx.x;
    __shared__ float red[256];

    float mx = -CUDART_INF_F;
#pragma unroll
    for (int t = 0; t < 8; t++) {
        int j = tid + t * 256;
        if (!mk[j]) mx = fmaxf(mx, p[j]);
    }
    red[tid] = mx;
    __syncthreads();
    for (int s = 128; s > 0; s >>= 1) {
        if (tid < s) red[tid] = fmaxf(red[tid], red[tid + s]);
        __syncthreads();
    }
    mx = red[0];
    __syncthreads();

    float vals[8];
    float sm = 0.0f;
#pragma unroll
    for (int t = 0; t < 8; t++) {
        int j = tid + t * 256;
        float e = mk[j] ? 0.0f : __expf(p[j] - mx);
        vals[t] = e;
        sm += e;
    }
    red[tid] = sm;
    __syncthreads();
    for (int s = 128; s > 0; s >>= 1) {
        if (tid < s) red[tid] += red[tid + s];
        __syncthreads();
    }
    const float inv = 1.0f / red[0];
#pragma unroll
    for (int t = 0; t < 8; t++) {
        int j = tid + t * 256;
        float w = vals[t] * inv;
        __half h = __float2half_rn(w);
        ph[j] = h;
        pl[j] = __float2half_rn(w - __half2float(h));
    }
}

// ---------------- launch ----------------
extern "C" void kernel_launch(void* const* d_in, const int* in_sizes, int n_in,
                              void* d_out, int out_size)
{
    const float* qkv  = (const float*)d_in[0];
    const void*  mask = d_in[1];
    const float* W    = (const float*)d_in[2];
    const float* bqkv = (const float*)d_in[3];
    float* out = (float*)d_out;

    cudaFuncSetAttribute(hmma_gemm<0>, cudaFuncAttributeMaxDynamicSharedMemorySize, SMEM_TOT);
    cudaFuncSetAttribute(hmma_gemm<1>, cudaFuncAttributeMaxDynamicSharedMemorySize, SMEM_TOT);
    cudaFuncSetAttribute(hmma_gemm<2>, cudaFuncAttributeMaxDynamicSharedMemorySize, SMEM_TOT);

    detect_mask_kernel<<<1, 256>>>(mask);
    normalize_mask_kernel<<<(BATCH * SEQ + 255) / 256, 256>>>(mask);

    // split qkv input: fp32 -> fp16 hi/lo
    {
        __half *qh, *ql;
        cudaGetSymbolAddress((void**)&qh, g_qkvh);
        cudaGetSymbolAddress((void**)&ql, g_qkvl);
        int n4 = BATCH * SEQ * DIN / 4;
        split_kernel<<<(n4 + 255) / 256, 256>>>(qkv, qh, ql, n4);
    }
    // transpose + split W: [1024,3072] -> [3072,1024] fp16 hi/lo
    {
        __half *wh, *wl;
        cudaGetSymbolAddress((void**)&wh, g_wth);
        cudaGetSymbolAddress((void**)&wl, g_wtl);
        dim3 grid(N3 / 32, DIN / 32, 1);
        transpose_split_kernel<<<grid, dim3(32, 8)>>>(W, wh, wl, DIN, N3, 0, 0);
    }
    // GEMM1: QKV projection (M=8192, N=3072, K=1024)
    {
        dim3 grid(N3 / 128, (BATCH * SEQ) / 256, 1);
        hmma_gemm<0><<<grid, 256, SMEM_TOT>>>(bqkv, nullptr);
    }
    // transpose + split V per batch: [2048,1024] -> [1024,2048] fp16 hi/lo
    {
        float* v;
        __half *vh, *vl;
        cudaGetSymbolAddress((void**)&v, g_v);
        cudaGetSymbolAddress((void**)&vh, g_vth);
        cudaGetSymbolAddress((void**)&vl, g_vtl);
        dim3 grid(DIN / 32, SEQ / 32, BATCH);
        transpose_split_kernel<<<grid, dim3(32, 8)>>>(v, vh, vl, SEQ, HD,
                                                      (size_t)SEQ * HD, (size_t)HD * SEQ);
    }
    // GEMM2: scores = q @ k^T per batch
    {
        dim3 grid(SEQ / 128, SEQ / 256, BATCH);
        hmma_gemm<1><<<grid, 256, SMEM_TOT>>>(nullptr, nullptr);
    }
    softmax_kernel<<<BATCH * SEQ, 256>>>();
    // GEMM3: out = P @ v per batch
    {
        dim3 grid(HD / 128, SEQ / 256, BATCH);
        hmma_gemm<2><<<grid, 256, SMEM_TOT>>>(nullptr, out);
    }
}

// round 5
// speedup vs baseline: 3.2207x; 1.3497x over previous
#include <cuda_runtime.h>
#include <cuda_fp16.h>
#include <math_constants.h>
#include <cstdint>

// Problem constants
#define BATCH 4
#define SEQ   2048
#define DIN   1024
#define HD    1024
#define N3    3072   // 3*HD

// ---------------- device scratch (no allocations allowed) ----------------
__device__ __align__(16) __half g_qkvh[BATCH * SEQ * DIN];
__device__ __align__(16) __half g_qkvl[BATCH * SEQ * DIN];
__device__ __align__(16) __half g_wth[N3 * DIN];
__device__ __align__(16) __half g_wtl[N3 * DIN];
__device__ __align__(16) __half g_qh[BATCH * SEQ * HD];
__device__ __align__(16) __half g_ql[BATCH * SEQ * HD];
__device__ __align__(16) __half g_kch[BATCH * SEQ * HD];   // compacted keys
__device__ __align__(16) __half g_kcl[BATCH * SEQ * HD];
__device__ __align__(16) float  g_v[BATCH * SEQ * HD];
__device__ __align__(16) __half g_vth[BATCH * HD * SEQ];   // compacted V^T
__device__ __align__(16) __half g_vtl[BATCH * HD * SEQ];
__device__ __align__(16) float  g_p[(size_t)BATCH * SEQ * SEQ];
__device__ __align__(16) __half g_ph[(size_t)BATCH * SEQ * SEQ];
__device__ __align__(16) __half g_pl[(size_t)BATCH * SEQ * SEQ];
__device__ int g_mask[BATCH * SEQ];
__device__ int g_mask_flag;
__device__ int g_srcidx[BATCH * SEQ];   // compact j -> original key s
__device__ int g_dstidx[BATCH * SEQ];   // original s -> compact j (or -1)
__device__ int g_nk[BATCH];
__device__ int g_nkpad[BATCH];          // ceil128(nk)

// ---------------- helpers ----------------
__device__ __forceinline__ uint32_t smem_u32(const void* p) {
    uint32_t a;
    asm("{ .reg .u64 t; cvta.to.shared.u64 t, %1; cvt.u32.u64 %0, t; }" : "=r"(a) : "l"(p));
    return a;
}
__device__ __forceinline__ void ldm4(uint32_t* r, uint32_t addr) {
    asm volatile("ldmatrix.sync.aligned.m8n8.x4.shared.b16 {%0,%1,%2,%3}, [%4];"
                 : "=r"(r[0]), "=r"(r[1]), "=r"(r[2]), "=r"(r[3]) : "r"(addr));
}
__device__ __forceinline__ void mma16816(float* c, const uint32_t* a,
                                         uint32_t b0, uint32_t b1) {
    asm volatile(
        "mma.sync.aligned.m16n8k16.row.col.f32.f16.f16.f32 "
        "{%0,%1,%2,%3}, {%4,%5,%6,%7}, {%8,%9}, {%0,%1,%2,%3};"
        : "+f"(c[0]), "+f"(c[1]), "+f"(c[2]), "+f"(c[3])
        : "r"(a[0]), "r"(a[1]), "r"(a[2]), "r"(a[3]), "r"(b0), "r"(b1));
}
__device__ __forceinline__ void cpa16(uint32_t dst, const void* src) {
    asm volatile("cp.async.cg.shared.global [%0], [%1], 16;" :: "r"(dst), "l"(src));
}
#define CP_COMMIT() asm volatile("cp.async.commit_group;" ::: "memory")
#define CP_WAIT(n)  asm volatile("cp.async.wait_group %0;" :: "n"(n) : "memory")

// ---------------- mask dtype detection + normalization ----------------
__global__ void detect_mask_kernel(const void* mptr) {
    const unsigned int* w = (const unsigned int*)mptr;
    __shared__ int okInt, okFloat;
    if (threadIdx.x == 0) { okInt = 1; okFloat = 1; }
    __syncthreads();
    for (int i = threadIdx.x; i < 2048; i += blockDim.x) {
        unsigned int x = w[i];
        if (!(x == 0u || x == 1u))          okInt = 0;
        if (!(x == 0u || x == 0x3F800000u)) okFloat = 0;
    }
    __syncthreads();
    if (threadIdx.x == 0) g_mask_flag = okInt ? 0 : (okFloat ? 1 : 2);
}
__global__ void normalize_mask_kernel(const void* mptr) {
    int i = blockIdx.x * blockDim.x + threadIdx.x;
    if (i >= BATCH * SEQ) return;
    int f = g_mask_flag, v;
    if (f == 0)      v = (((const int*)mptr)[i] != 0);
    else if (f == 1) v = (((const float*)mptr)[i] != 0.0f);
    else             v = (((const unsigned char*)mptr)[i] != 0);
    g_mask[i] = v;
}

// ---------------- per-batch stable compaction scan ----------------
__global__ __launch_bounds__(256)
void scan_mask_kernel()
{
    const int b   = blockIdx.x;
    const int tid = threadIdx.x;
    __shared__ int sums[256];
    int keep[8], loc[8];
    int s = 0;
    const int base = b * SEQ + tid * 8;
#pragma unroll
    for (int i = 0; i < 8; i++) {
        keep[i] = !g_mask[base + i];
        loc[i]  = s;
        s += keep[i];
    }
    sums[tid] = s;
    __syncthreads();
    // Hillis-Steele inclusive scan
    for (int d = 1; d < 256; d <<= 1) {
        int v = (tid >= d) ? sums[tid - d] : 0;
        __syncthreads();
        sums[tid] += v;
        __syncthreads();
    }
    const int offs = sums[tid] - s;   // exclusive
#pragma unroll
    for (int i = 0; i < 8; i++) {
        const int orig = tid * 8 + i;
        if (keep[i]) {
            const int j = offs + loc[i];
            g_srcidx[b * SEQ + j]    = orig;
            g_dstidx[b * SEQ + orig] = j;
        } else {
            g_dstidx[b * SEQ + orig] = -1;
        }
    }
    if (tid == 255) {
        const int total = sums[255];
        g_nk[b]    = total;
        g_nkpad[b] = (total + 127) & ~127;
    }
}

// zero the pad rows [nk, nkpad) of compacted K
__global__ __launch_bounds__(256)
void zero_kc_pad_kernel()
{
    const int b   = blockIdx.z;
    const int row = g_nk[b] + blockIdx.x;
    if (row >= g_nkpad[b]) return;
    const size_t idx = ((size_t)b * SEQ + row) * HD + threadIdx.x * 4;
    *(uint2*)(g_kch + idx) = make_uint2(0, 0);
    *(uint2*)(g_kcl + idx) = make_uint2(0, 0);
}

// ---------------- elementwise split: fp32 -> (hi, lo) fp16 ----------------
__global__ __launch_bounds__(256)
void split_kernel(const float* __restrict__ in, __half* __restrict__ oh,
                  __half* __restrict__ ol, int n4)
{
    int i = blockIdx.x * blockDim.x + threadIdx.x;
    if (i >= n4) return;
    float4 v = ((const float4*)in)[i];
    __half h0 = __float2half_rn(v.x), h1 = __float2half_rn(v.y);
    __half h2 = __float2half_rn(v.z), h3 = __float2half_rn(v.w);
    __half l0 = __float2half_rn(v.x - __half2float(h0));
    __half l1 = __float2half_rn(v.y - __half2float(h1));
    __half l2 = __float2half_rn(v.z - __half2float(h2));
    __half l3 = __float2half_rn(v.w - __half2float(h3));
    ((__half2*)oh)[2 * i]     = __halves2half2(h0, h1);
    ((__half2*)oh)[2 * i + 1] = __halves2half2(h2, h3);
    ((__half2*)ol)[2 * i]     = __halves2half2(l0, l1);
    ((__half2*)ol)[2 * i + 1] = __halves2half2(l2, l3);
}

// ---------------- transpose + split W ----------------
__global__ void transpose_split_kernel(const float* __restrict__ in,
                                       __half* __restrict__ oh, __half* __restrict__ ol,
                                       int R, int C)
{
    __shared__ float t[32][33];
    int bx = blockIdx.x * 32, by = blockIdx.y * 32;
    int x = threadIdx.x, y = threadIdx.y;
#pragma unroll
    for (int i = y; i < 32; i += 8) t[i][x] = in[(size_t)(by + i) * C + bx + x];
    __syncthreads();
#pragma unroll
    for (int i = y; i < 32; i += 8) {
        float w = t[x][i];
        __half h = __float2half_rn(w);
        size_t idx = (size_t)(bx + i) * R + by + x;
        oh[idx] = h;
        ol[idx] = __float2half_rn(w - __half2float(h));
    }
}

// ---- transpose + split + key-gather: vt_c[h][j] = split(v[src[j]][h]), j<nk else 0
__global__ void transpose_split_gather_kernel()
{
    const int b = blockIdx.z;
    const float* in = g_v + (size_t)b * SEQ * HD;
    __half* oh = g_vth + (size_t)b * HD * SEQ;
    __half* ol = g_vtl + (size_t)b * HD * SEQ;
    const int nk = g_nk[b];
    const int* src = g_srcidx + b * SEQ;

    __shared__ float t[32][33];
    int bx = blockIdx.x * 32;   // head dim
    int by = blockIdx.y * 32;   // compact key dim
    int x = threadIdx.x, y = threadIdx.y;
#pragma unroll
    for (int i = y; i < 32; i += 8) {
        const int j = by + i;
        t[i][x] = (j < nk) ? in[(size_t)src[j] * HD + bx + x] : 0.0f;
    }
    __syncthreads();
#pragma unroll
    for (int i = y; i < 32; i += 8) {
        float w = t[x][i];
        __half h = __float2half_rn(w);
        size_t idx = (size_t)(bx + i) * SEQ + by + x;
        oh[idx] = h;
        ol[idx] = __float2half_rn(w - __half2float(h));
    }
}

// ---------------- fp16x3 split GEMM, CTA 256x128x32, warp 64x64, cp.async ----
// MODE 0: qkv_split @ wt_split + bias -> q(h,l)*32 / k compacted (h,l) / v fp32
// MODE 1: q_split @ kc_split -> g_p (N limited to nkpad, per batch z)
// MODE 2: p_split @ vtc_split -> out (K = nkpad dynamic, per batch z)
#define NSTAGE   3
#define ST_AH    0
#define ST_AL    16384
#define ST_BH    32768
#define ST_BL    40960
#define STAGE_SZ 49152
#define SMEM_TOT (NSTAGE * STAGE_SZ)   // 147456

template <int MODE>
__global__ __launch_bounds__(256, 1)
void hmma_gemm(const float* __restrict__ bias, float* __restrict__ Cout)
{
    constexpr int K = (MODE == 2) ? 2048 : 1024;   // memory stride of operand rows
    const int z = blockIdx.z;
    int NT;
    if constexpr (MODE == 2) NT = g_nkpad[z] >> 5;
    else NT = 1024 / 32;

    const int nBase = blockIdx.x * 128;
    if constexpr (MODE == 1) {
        if (nBase >= g_nkpad[z]) return;
    }
    const int mBase = blockIdx.y * 256;

    extern __shared__ char smem[];
    const uint32_t sbase = smem_u32(smem);
    const int tid  = threadIdx.x;
    const int wid  = tid >> 5;
    const int lane = tid & 31;
    const int wm   = wid >> 1;
    const int wn   = wid & 1;

    const __half *Ah, *Al, *Bh, *Bl;
    if constexpr (MODE == 0) {
        Ah = g_qkvh; Al = g_qkvl; Bh = g_wth; Bl = g_wtl;
    } else if constexpr (MODE == 1) {
        Ah = g_qh  + (size_t)z * SEQ * HD; Al = g_ql  + (size_t)z * SEQ * HD;
        Bh = g_kch + (size_t)z * SEQ * HD; Bl = g_kcl + (size_t)z * SEQ * HD;
    } else {
        Ah = g_ph  + (size_t)z * SEQ * SEQ; Al = g_pl  + (size_t)z * SEQ * SEQ;
        Bh = g_vth + (size_t)z * HD * SEQ;  Bl = g_vtl + (size_t)z * HD * SEQ;
    }

    // ---- cp.async loader state ----
    const int lrow = tid >> 2;
    const int lc   = tid & 3;
    const uint32_t swc = (uint32_t)((lc ^ ((lrow >> 1) & 3)) << 4);
    const uint32_t dA0 = (uint32_t)lrow * 64 + swc;
    const __half* pAh = Ah + (size_t)(mBase + lrow) * K + lc * 8;
    const __half* pAl = Al + (size_t)(mBase + lrow) * K + lc * 8;
    const __half* pBh = Bh + (size_t)(nBase + lrow) * K + lc * 8;
    const __half* pBl = Bl + (size_t)(nBase + lrow) * K + lc * 8;

    // ---- ldmatrix fragment addressing ----
    const int roff = (lane & 7) + ((lane >> 3) & 1) * 8;
    const int cq   = lane >> 4;
    const int xr   = (roff >> 1) & 3;
    const uint32_t abase = (uint32_t)(wm * 64 + roff) * 64;
    const uint32_t bbase = (uint32_t)(wn * 64 + roff) * 64;
    uint32_t kc[2];
    kc[0] = (uint32_t)((cq ^ xr) << 4);
    kc[1] = (uint32_t)(((2 + cq) ^ xr) << 4);

    float acc[4][8][4] = {};

#pragma unroll
    for (int s = 0; s < NSTAGE - 1; s++) {
        const uint32_t sb = sbase + s * STAGE_SZ;
#pragma unroll
        for (int i = 0; i < 4; i++) {
            cpa16(sb + ST_AH + dA0 + i * 4096, pAh + (size_t)i * 64 * K);
            cpa16(sb + ST_AL + dA0 + i * 4096, pAl + (size_t)i * 64 * K);
        }
#pragma unroll
        for (int i = 0; i < 2; i++) {
            cpa16(sb + ST_BH + dA0 + i * 4096, pBh + (size_t)i * 64 * K);
            cpa16(sb + ST_BL + dA0 + i * 4096, pBl + (size_t)i * 64 * K);
        }
        pAh += 32; pAl += 32; pBh += 32; pBl += 32;
        CP_COMMIT();
    }

    for (int kt = 0; kt < NT; kt++) {
        CP_WAIT(NSTAGE - 2);
        __syncthreads();

        if (kt + NSTAGE - 1 < NT) {
            const uint32_t sb = sbase + ((kt + NSTAGE - 1) % NSTAGE) * STAGE_SZ;
#pragma unroll
            for (int i = 0; i < 4; i++) {
                cpa16(sb + ST_AH + dA0 + i * 4096, pAh + (size_t)i * 64 * K);
                cpa16(sb + ST_AL + dA0 + i * 4096, pAl + (size_t)i * 64 * K);
            }
#pragma unroll
            for (int i = 0; i < 2; i++) {
                cpa16(sb + ST_BH + dA0 + i * 4096, pBh + (size_t)i * 64 * K);
                cpa16(sb + ST_BL + dA0 + i * 4096, pBl + (size_t)i * 64 * K);
            }
            pAh += 32; pAl += 32; pBh += 32; pBl += 32;
        }
        CP_COMMIT();

        const uint32_t stb = sbase + (kt % NSTAGE) * STAGE_SZ;
#pragma unroll
        for (int ks = 0; ks < 2; ks++) {
            uint32_t ah[4][4], al[4][4], bh[4][4], bl[4][4];
#pragma unroll
            for (int mt = 0; mt < 4; mt++) {
                ldm4(ah[mt], stb + ST_AH + abase + mt * 1024 + kc[ks]);
                ldm4(al[mt], stb + ST_AL + abase + mt * 1024 + kc[ks]);
            }
#pragma unroll
            for (int ng = 0; ng < 4; ng++) {
                ldm4(bh[ng], stb + ST_BH + bbase + ng * 1024 + kc[ks]);
                ldm4(bl[ng], stb + ST_BL + bbase + ng * 1024 + kc[ks]);
            }
#pragma unroll
            for (int mt = 0; mt < 4; mt++) {
#pragma unroll
                for (int ng = 0; ng < 4; ng++) {
#pragma unroll
                    for (int nb = 0; nb < 2; nb++) {
                        float* cc = acc[mt][ng * 2 + nb];
                        mma16816(cc, ah[mt], bh[ng][nb], bh[ng][nb + 2]);
                        mma16816(cc, ah[mt], bl[ng][nb], bl[ng][nb + 2]);
                        mma16816(cc, al[mt], bh[ng][nb], bh[ng][nb + 2]);
                    }
                }
            }
        }
    }

    // ---------------- epilogue ----------------
    const int rl = lane >> 2;
    const int cl = 2 * (lane & 3);
#pragma unroll
    for (int mt = 0; mt < 4; mt++) {
#pragma unroll
        for (int nt = 0; nt < 8; nt++) {
            const int r0 = mBase + wm * 64 + mt * 16 + rl;
            const int c0 = nBase + wn * 64 + nt * 8 + cl;
            float* cc = acc[mt][nt];
            if constexpr (MODE == 0) {
                const int seg = c0 >> 10;             // 0=q 1=k 2=v
                const int lcc = c0 & 1023;
                const float b0 = bias[c0], b1 = bias[c0 + 1];
                if (seg == 2) {
                    *(float2*)(g_v + (size_t)r0 * HD + lcc)       = make_float2(cc[0] + b0, cc[1] + b1);
                    *(float2*)(g_v + (size_t)(r0 + 8) * HD + lcc) = make_float2(cc[2] + b0, cc[3] + b1);
                } else if (seg == 0) {
#pragma unroll
                    for (int rr = 0; rr < 2; rr++) {
                        float w0 = (cc[2 * rr + 0] + b0) * 32.0f;
                        float w1 = (cc[2 * rr + 1] + b1) * 32.0f;
                        __half h0 = __float2half_rn(w0), h1 = __float2half_rn(w1);
                        __half l0 = __float2half_rn(w0 - __half2float(h0));
                        __half l1 = __float2half_rn(w1 - __half2float(h1));
                        size_t idx = (size_t)(r0 + 8 * rr) * HD + lcc;
                        *(__half2*)(g_qh + idx) = __halves2half2(h0, h1);
                        *(__half2*)(g_ql + idx) = __halves2half2(l0, l1);
                    }
                } else { // k: write compacted row (drop masked)
#pragma unroll
                    for (int rr = 0; rr < 2; rr++) {
                        const int rg = r0 + 8 * rr;
                        const int dst = g_dstidx[rg];
                        if (dst < 0) continue;
                        float w0 = cc[2 * rr + 0] + b0;
                        float w1 = cc[2 * rr + 1] + b1;
                        __half h0 = __float2half_rn(w0), h1 = __float2half_rn(w1);
                        __half l0 = __float2half_rn(w0 - __half2float(h0));
                        __half l1 = __float2half_rn(w1 - __half2float(h1));
                        size_t idx = (((size_t)(rg >> 11) << 11) + dst) * HD + lcc;
                        *(__half2*)(g_kch + idx) = __halves2half2(h0, h1);
                        *(__half2*)(g_kcl + idx) = __halves2half2(l0, l1);
                    }
                }
            } else if constexpr (MODE == 1) {
                float* Cb = g_p + (size_t)z * SEQ * SEQ;
                *(float2*)(Cb + (size_t)r0 * SEQ + c0)       = make_float2(cc[0], cc[1]);
                *(float2*)(Cb + (size_t)(r0 + 8) * SEQ + c0) = make_float2(cc[2], cc[3]);
            } else {
                float* Cb = Cout + (size_t)z * SEQ * HD;
                *(float2*)(Cb + (size_t)r0 * HD + c0)        = make_float2(cc[0], cc[1]);
                *(float2*)(Cb + (size_t)(r0 + 8) * HD + c0)  = make_float2(cc[2], cc[3]);
            }
        }
    }
}

// ---------------- softmax over compact scores: g_p -> g_ph/g_pl ------------
__global__ __launch_bounds__(256)
void softmax_kernel()
{
    const int row = blockIdx.x;          // 0..8191
    const int b   = row >> 11;
    const int nk  = g_nk[b];
    const int nkp = g_nkpad[b];
    float* p = g_p + (size_t)row * SEQ;
    __half* ph = g_ph + (size_t)row * SEQ;
    __half* pl = g_pl + (size_t)row * SEQ;
    const int tid = threadIdx.x;
    __shared__ float red[256];

    float mx = -CUDART_INF_F;
#pragma unroll
    for (int t = 0; t < 8; t++) {
        int j = tid + t * 256;
        if (j < nk) mx = fmaxf(mx, p[j]);
    }
    red[tid] = mx;
    __syncthreads();
    for (int s = 128; s > 0; s >>= 1) {
        if (tid < s) red[tid] = fmaxf(red[tid], red[tid + s]);
        __syncthreads();
    }
    mx = red[0];
    __syncthreads();

    float vals[8];
    float sm = 0.0f;
#pragma unroll
    for (int t = 0; t < 8; t++) {
        int j = tid + t * 256;
        float e = (j < nk) ? __expf(p[j] - mx) : 0.0f;
        vals[t] = e;
        sm += e;
    }
    red[tid] = sm;
    __syncthreads();
    for (int s = 128; s > 0; s >>= 1) {
        if (tid < s) red[tid] += red[tid + s];
        __syncthreads();
    }
    const float inv = 1.0f / red[0];
#pragma unroll
    for (int t = 0; t < 8; t++) {
        int j = tid + t * 256;
        if (j < nkp) {
            float w = vals[t] * inv;     // 0 for j in [nk, nkp)
            __half h = __float2half_rn(w);
            ph[j] = h;
            pl[j] = __float2half_rn(w - __half2float(h));
        }
    }
}

// ---------------- launch ----------------
extern "C" void kernel_launch(void* const* d_in, const int* in_sizes, int n_in,
                              void* d_out, int out_size)
{
    const float* qkv  = (const float*)d_in[0];
    const void*  mask = d_in[1];
    const float* W    = (const float*)d_in[2];
    const float* bqkv = (const float*)d_in[3];
    float* out = (float*)d_out;

    cudaFuncSetAttribute(hmma_gemm<0>, cudaFuncAttributeMaxDynamicSharedMemorySize, SMEM_TOT);
    cudaFuncSetAttribute(hmma_gemm<1>, cudaFuncAttributeMaxDynamicSharedMemorySize, SMEM_TOT);
    cudaFuncSetAttribute(hmma_gemm<2>, cudaFuncAttributeMaxDynamicSharedMemorySize, SMEM_TOT);

    detect_mask_kernel<<<1, 256>>>(mask);
    normalize_mask_kernel<<<(BATCH * SEQ + 255) / 256, 256>>>(mask);
    scan_mask_kernel<<<BATCH, 256>>>();

    // split qkv input: fp32 -> fp16 hi/lo
    {
        __half *qh, *ql;
        cudaGetSymbolAddress((void**)&qh, g_qkvh);
        cudaGetSymbolAddress((void**)&ql, g_qkvl);
        int n4 = BATCH * SEQ * DIN / 4;
        split_kernel<<<(n4 + 255) / 256, 256>>>(qkv, qh, ql, n4);
    }
    // transpose + split W: [1024,3072] -> [3072,1024]
    {
        __half *wh, *wl;
        cudaGetSymbolAddress((void**)&wh, g_wth);
        cudaGetSymbolAddress((void**)&wl, g_wtl);
        dim3 grid(N3 / 32, DIN / 32, 1);
        transpose_split_kernel<<<grid, dim3(32, 8)>>>(W, wh, wl, DIN, N3);
    }
    // GEMM1: QKV projection (M=8192, N=3072, K=1024)
    {
        dim3 grid(N3 / 128, (BATCH * SEQ) / 256, 1);
        hmma_gemm<0><<<grid, 256, SMEM_TOT>>>(bqkv, nullptr);
    }
    zero_kc_pad_kernel<<<dim3(128, 1, BATCH), 256>>>();
    // transpose + split + gather V -> compacted V^T
    {
        dim3 grid(DIN / 32, SEQ / 32, BATCH);
        transpose_split_gather_kernel<<<grid, dim3(32, 8)>>>();
    }
    // GEMM2: scores = q @ kc^T (N limited to nkpad via early exit)
    {
        dim3 grid(SEQ / 128, SEQ / 256, BATCH);
        hmma_gemm<1><<<grid, 256, SMEM_TOT>>>(nullptr, nullptr);
    }
    softmax_kernel<<<BATCH * SEQ, 256>>>();
    // GEMM3: out = P_c @ V_c (K = nkpad dynamic)
    {
        dim3 grid(HD / 128, SEQ / 256, BATCH);
        hmma_gemm<2><<<grid, 256, SMEM_TOT>>>(nullptr, out);
    }
}

// round 6
// speedup vs baseline: 3.9142x; 1.2153x over previous
#include <cuda_runtime.h>
#include <cuda_fp16.h>
#include <math_constants.h>
#include <cstdint>

// Problem constants
#define BATCH 4
#define SEQ   2048
#define DIN   1024
#define HD    1024
#define N3    3072   // 3*HD

// ---------------- device scratch (no allocations allowed) ----------------
__device__ __align__(16) __half g_qkvh[BATCH * SEQ * DIN];
__device__ __align__(16) __half g_qkvl[BATCH * SEQ * DIN];
__device__ __align__(16) __half g_wth[N3 * DIN];
__device__ __align__(16) __half g_wtl[N3 * DIN];
__device__ __align__(16) __half g_qh[BATCH * SEQ * HD];
__device__ __align__(16) __half g_ql[BATCH * SEQ * HD];
__device__ __align__(16) __half g_kch[BATCH * SEQ * HD];   // compacted keys (split)
__device__ __align__(16) __half g_kcl[BATCH * SEQ * HD];
__device__ __align__(16) float  g_v[BATCH * SEQ * HD];     // compacted V (fp32 rows)
__device__ __align__(16) __half g_vth[BATCH * HD * SEQ];   // compacted V^T (split)
__device__ __align__(16) __half g_vtl[BATCH * HD * SEQ];
__device__ __align__(16) float  g_p[(size_t)BATCH * SEQ * SEQ];
__device__ __align__(16) __half g_ph[(size_t)BATCH * SEQ * SEQ];
__device__ __align__(16) __half g_pl[(size_t)BATCH * SEQ * SEQ];
__device__ int g_mask[BATCH * SEQ];
__device__ int g_mask_flag;
__device__ int g_srcidx[BATCH * SEQ];   // compact j -> original position (0 for j >= nk)
__device__ int g_nk[BATCH];
__device__ int g_nkpad[BATCH];          // ceil128(nk)

// ---------------- helpers ----------------
__device__ __forceinline__ uint32_t smem_u32(const void* p) {
    uint32_t a;
    asm("{ .reg .u64 t; cvta.to.shared.u64 t, %1; cvt.u32.u64 %0, t; }" : "=r"(a) : "l"(p));
    return a;
}
__device__ __forceinline__ void ldm4(uint32_t* r, uint32_t addr) {
    asm volatile("ldmatrix.sync.aligned.m8n8.x4.shared.b16 {%0,%1,%2,%3}, [%4];"
                 : "=r"(r[0]), "=r"(r[1]), "=r"(r[2]), "=r"(r[3]) : "r"(addr));
}
__device__ __forceinline__ void mma16816(float* c, const uint32_t* a,
                                         uint32_t b0, uint32_t b1) {
    asm volatile(
        "mma.sync.aligned.m16n8k16.row.col.f32.f16.f16.f32 "
        "{%0,%1,%2,%3}, {%4,%5,%6,%7}, {%8,%9}, {%0,%1,%2,%3};"
        : "+f"(c[0]), "+f"(c[1]), "+f"(c[2]), "+f"(c[3])
        : "r"(a[0]), "r"(a[1]), "r"(a[2]), "r"(a[3]), "r"(b0), "r"(b1));
}
__device__ __forceinline__ void cpa16(uint32_t dst, const void* src) {
    asm volatile("cp.async.cg.shared.global [%0], [%1], 16;" :: "r"(dst), "l"(src));
}
#define CP_COMMIT() asm volatile("cp.async.commit_group;" ::: "memory")
#define CP_WAIT(n)  asm volatile("cp.async.wait_group %0;" :: "n"(n) : "memory")

// ---------------- mask dtype detection + normalization ----------------
__global__ void detect_mask_kernel(const void* mptr) {
    const unsigned int* w = (const unsigned int*)mptr;
    __shared__ int okInt, okFloat;
    if (threadIdx.x == 0) { okInt = 1; okFloat = 1; }
    __syncthreads();
    for (int i = threadIdx.x; i < 2048; i += blockDim.x) {
        unsigned int x = w[i];
        if (!(x == 0u || x == 1u))          okInt = 0;
        if (!(x == 0u || x == 0x3F800000u)) okFloat = 0;
    }
    __syncthreads();
    if (threadIdx.x == 0) g_mask_flag = okInt ? 0 : (okFloat ? 1 : 2);
}
__global__ void normalize_mask_kernel(const void* mptr) {
    int i = blockIdx.x * blockDim.x + threadIdx.x;
    if (i >= BATCH * SEQ) return;
    int f = g_mask_flag, v;
    if (f == 0)      v = (((const int*)mptr)[i] != 0);
    else if (f == 1) v = (((const float*)mptr)[i] != 0.0f);
    else             v = (((const unsigned char*)mptr)[i] != 0);
    g_mask[i] = v;
}

// ---------------- per-batch stable compaction scan ----------------
__global__ __launch_bounds__(256)
void scan_mask_kernel()
{
    const int b   = blockIdx.x;
    const int tid = threadIdx.x;
    __shared__ int sums[256];
    // phase 0: zero-fill srcidx (safe gather addresses for pad rows)
#pragma unroll
    for (int i = 0; i < 8; i++) g_srcidx[b * SEQ + tid * 8 + i] = 0;

    int keep[8], loc[8];
    int s = 0;
    const int base = b * SEQ + tid * 8;
#pragma unroll
    for (int i = 0; i < 8; i++) {
        keep[i] = !g_mask[base + i];
        loc[i]  = s;
        s += keep[i];
    }
    sums[tid] = s;
    __syncthreads();   // also orders the zero-fill before the scatter below
    // Hillis-Steele inclusive scan
    for (int d = 1; d < 256; d <<= 1) {
        int v = (tid >= d) ? sums[tid - d] : 0;
        __syncthreads();
        sums[tid] += v;
        __syncthreads();
    }
    const int offs = sums[tid] - s;   // exclusive
#pragma unroll
    for (int i = 0; i < 8; i++) {
        if (keep[i]) g_srcidx[b * SEQ + offs + loc[i]] = tid * 8 + i;
    }
    if (tid == 255) {
        const int total = sums[255];
        g_nk[b]    = total;
        g_nkpad[b] = (total + 127) & ~127;
    }
}

// zero the pad rows [nk, nkpad) of compacted K
__global__ __launch_bounds__(256)
void zero_kc_pad_kernel()
{
    const int b   = blockIdx.z;
    const int row = g_nk[b] + blockIdx.x;
    if (row >= g_nkpad[b]) return;
    const size_t idx = ((size_t)b * SEQ + row) * HD + threadIdx.x * 4;
    *(uint2*)(g_kch + idx) = make_uint2(0, 0);
    *(uint2*)(g_kcl + idx) = make_uint2(0, 0);
}

// ---------------- elementwise split: fp32 -> (hi, lo) fp16 ----------------
__global__ __launch_bounds__(256)
void split_kernel(const float* __restrict__ in, __half* __restrict__ oh,
                  __half* __restrict__ ol, int n4)
{
    int i = blockIdx.x * blockDim.x + threadIdx.x;
    if (i >= n4) return;
    float4 v = ((const float4*)in)[i];
    __half h0 = __float2half_rn(v.x), h1 = __float2half_rn(v.y);
    __half h2 = __float2half_rn(v.z), h3 = __float2half_rn(v.w);
    __half l0 = __float2half_rn(v.x - __half2float(h0));
    __half l1 = __float2half_rn(v.y - __half2float(h1));
    __half l2 = __float2half_rn(v.z - __half2float(h2));
    __half l3 = __float2half_rn(v.w - __half2float(h3));
    ((__half2*)oh)[2 * i]     = __halves2half2(h0, h1);
    ((__half2*)oh)[2 * i + 1] = __halves2half2(h2, h3);
    ((__half2*)ol)[2 * i]     = __halves2half2(l0, l1);
    ((__half2*)ol)[2 * i + 1] = __halves2half2(l2, l3);
}

// ---------------- transpose + split W ----------------
__global__ void transpose_split_kernel(const float* __restrict__ in,
                                       __half* __restrict__ oh, __half* __restrict__ ol,
                                       int R, int C)
{
    __shared__ float t[32][33];
    int bx = blockIdx.x * 32, by = blockIdx.y * 32;
    int x = threadIdx.x, y = threadIdx.y;
#pragma unroll
    for (int i = y; i < 32; i += 8) t[i][x] = in[(size_t)(by + i) * C + bx + x];
    __syncthreads();
#pragma unroll
    for (int i = y; i < 32; i += 8) {
        float w = t[x][i];
        __half h = __float2half_rn(w);
        size_t idx = (size_t)(bx + i) * R + by + x;
        oh[idx] = h;
        ol[idx] = __float2half_rn(w - __half2float(h));
    }
}

// ---- transpose + split compacted V: vt[h][j] = split(g_v[j][h]) for j<nk, else 0
__global__ void transpose_split_v_kernel()
{
    const int b = blockIdx.z;
    const float* in = g_v + (size_t)b * SEQ * HD;
    __half* oh = g_vth + (size_t)b * HD * SEQ;
    __half* ol = g_vtl + (size_t)b * HD * SEQ;
    const int nk = g_nk[b];

    __shared__ float t[32][33];
    int bx = blockIdx.x * 32;   // head dim
    int by = blockIdx.y * 32;   // compact key dim
    int x = threadIdx.x, y = threadIdx.y;
#pragma unroll
    for (int i = y; i < 32; i += 8) {
        const int j = by + i;
        t[i][x] = (j < nk) ? in[(size_t)j * HD + bx + x] : 0.0f;
    }
    __syncthreads();
#pragma unroll
    for (int i = y; i < 32; i += 8) {
        float w = t[x][i];
        __half h = __float2half_rn(w);
        size_t idx = (size_t)(bx + i) * SEQ + by + x;
        oh[idx] = h;
        ol[idx] = __float2half_rn(w - __half2float(h));
    }
}

// ---------------- fp16x3 split GEMM, CTA 256x128x32, warp 64x64, cp.async ----
// MODE 0: q-proj:  qkv_split[8192,1024] @ wt_split[0:1024] + b -> q split (*32)
// MODE 3: kv-proj: gathered qkv rows (nk per batch) @ wt_split[1024:3072] + b
//                  -> compacted K split / compacted V fp32
// MODE 1: q_split @ kc_split -> g_p (N limited to nkpad, per batch z)
// MODE 2: p_split @ vtc_split -> out (K = nkpad dynamic, per batch z)
#define NSTAGE   3
#define ST_AH    0
#define ST_AL    16384
#define ST_BH    32768
#define ST_BL    40960
#define STAGE_SZ 49152
#define SMEM_TOT (NSTAGE * STAGE_SZ)   // 147456

template <int MODE>
__global__ __launch_bounds__(256, 1)
void hmma_gemm(const float* __restrict__ bias, float* __restrict__ Cout)
{
    constexpr int K = (MODE == 2) ? 2048 : 1024;   // k-extent == row stride (all modes)
    const int z = blockIdx.z;
    int NT;
    if constexpr (MODE == 2) NT = g_nkpad[z] >> 5;
    else NT = 1024 / 32;

    const int nBase = blockIdx.x * 128;
    const int mBase = blockIdx.y * 256;
    if constexpr (MODE == 1) { if (nBase >= g_nkpad[z]) return; }
    if constexpr (MODE == 3) { if (mBase >= g_nk[z])    return; }

    extern __shared__ char smem[];
    const uint32_t sbase = smem_u32(smem);
    const int tid  = threadIdx.x;
    const int wid  = tid >> 5;
    const int lane = tid & 31;
    const int wm   = wid >> 1;
    const int wn   = wid & 1;

    const __half *Ah, *Al, *Bh, *Bl;
    if constexpr (MODE == 0) {
        Ah = g_qkvh; Al = g_qkvl; Bh = g_wth; Bl = g_wtl;
    } else if constexpr (MODE == 3) {
        Ah = g_qkvh + (size_t)z * SEQ * DIN; Al = g_qkvl + (size_t)z * SEQ * DIN;
        Bh = g_wth + (size_t)1024 * DIN;     Bl = g_wtl + (size_t)1024 * DIN;
    } else if constexpr (MODE == 1) {
        Ah = g_qh  + (size_t)z * SEQ * HD; Al = g_ql  + (size_t)z * SEQ * HD;
        Bh = g_kch + (size_t)z * SEQ * HD; Bl = g_kcl + (size_t)z * SEQ * HD;
    } else {
        Ah = g_ph  + (size_t)z * SEQ * SEQ; Al = g_pl  + (size_t)z * SEQ * SEQ;
        Bh = g_vth + (size_t)z * HD * SEQ;  Bl = g_vtl + (size_t)z * HD * SEQ;
    }

    // ---- cp.async loader state ----
    const int lrow = tid >> 2;
    const int lc   = tid & 3;
    const uint32_t swc = (uint32_t)((lc ^ ((lrow >> 1) & 3)) << 4);
    const uint32_t dA0 = (uint32_t)lrow * 64 + swc;
    const __half *pAh[4], *pAl[4], *pBh[2], *pBl[2];
#pragma unroll
    for (int i = 0; i < 4; i++) {
        int ar = mBase + lrow + i * 64;
        if constexpr (MODE == 3) ar = g_srcidx[z * SEQ + ar];
        pAh[i] = Ah + (size_t)ar * K + lc * 8;
        pAl[i] = Al + (size_t)ar * K + lc * 8;
    }
#pragma unroll
    for (int i = 0; i < 2; i++) {
        pBh[i] = Bh + (size_t)(nBase + lrow + i * 64) * K + lc * 8;
        pBl[i] = Bl + (size_t)(nBase + lrow + i * 64) * K + lc * 8;
    }

    // ---- ldmatrix fragment addressing ----
    const int roff = (lane & 7) + ((lane >> 3) & 1) * 8;
    const int cq   = lane >> 4;
    const int xr   = (roff >> 1) & 3;
    const uint32_t abase = (uint32_t)(wm * 64 + roff) * 64;
    const uint32_t bbase = (uint32_t)(wn * 64 + roff) * 64;
    uint32_t kcofs[2];
    kcofs[0] = (uint32_t)((cq ^ xr) << 4);
    kcofs[1] = (uint32_t)(((2 + cq) ^ xr) << 4);

    float acc[4][8][4] = {};

#pragma unroll
    for (int s = 0; s < NSTAGE - 1; s++) {
        const uint32_t sb = sbase + s * STAGE_SZ;
#pragma unroll
        for (int i = 0; i < 4; i++) {
            cpa16(sb + ST_AH + dA0 + i * 4096, pAh[i]);
            cpa16(sb + ST_AL + dA0 + i * 4096, pAl[i]);
            pAh[i] += 32; pAl[i] += 32;
        }
#pragma unroll
        for (int i = 0; i < 2; i++) {
            cpa16(sb + ST_BH + dA0 + i * 4096, pBh[i]);
            cpa16(sb + ST_BL + dA0 + i * 4096, pBl[i]);
            pBh[i] += 32; pBl[i] += 32;
        }
        CP_COMMIT();
    }

    for (int kt = 0; kt < NT; kt++) {
        CP_WAIT(NSTAGE - 2);
        __syncthreads();

        if (kt + NSTAGE - 1 < NT) {
            const uint32_t sb = sbase + ((kt + NSTAGE - 1) % NSTAGE) * STAGE_SZ;
#pragma unroll
            for (int i = 0; i < 4; i++) {
                cpa16(sb + ST_AH + dA0 + i * 4096, pAh[i]);
                cpa16(sb + ST_AL + dA0 + i * 4096, pAl[i]);
                pAh[i] += 32; pAl[i] += 32;
            }
#pragma unroll
            for (int i = 0; i < 2; i++) {
                cpa16(sb + ST_BH + dA0 + i * 4096, pBh[i]);
                cpa16(sb + ST_BL + dA0 + i * 4096, pBl[i]);
                pBh[i] += 32; pBl[i] += 32;
            }
        }
        CP_COMMIT();

        const uint32_t stb = sbase + (kt % NSTAGE) * STAGE_SZ;
#pragma unroll
        for (int ks = 0; ks < 2; ks++) {
            uint32_t ah[4][4], al[4][4], bh[4][4], bl[4][4];
#pragma unroll
            for (int mt = 0; mt < 4; mt++) {
                ldm4(ah[mt], stb + ST_AH + abase + mt * 1024 + kcofs[ks]);
                ldm4(al[mt], stb + ST_AL + abase + mt * 1024 + kcofs[ks]);
            }
#pragma unroll
            for (int ng = 0; ng < 4; ng++) {
                ldm4(bh[ng], stb + ST_BH + bbase + ng * 1024 + kcofs[ks]);
                ldm4(bl[ng], stb + ST_BL + bbase + ng * 1024 + kcofs[ks]);
            }
#pragma unroll
            for (int mt = 0; mt < 4; mt++) {
#pragma unroll
                for (int ng = 0; ng < 4; ng++) {
#pragma unroll
                    for (int nb = 0; nb < 2; nb++) {
                        float* cc = acc[mt][ng * 2 + nb];
                        mma16816(cc, ah[mt], bh[ng][nb], bh[ng][nb + 2]);
                        mma16816(cc, ah[mt], bl[ng][nb], bl[ng][nb + 2]);
                        mma16816(cc, al[mt], bh[ng][nb], bh[ng][nb + 2]);
                    }
                }
            }
        }
    }

    // ---------------- epilogue ----------------
    const int rl = lane >> 2;
    const int cl = 2 * (lane & 3);
#pragma unroll
    for (int mt = 0; mt < 4; mt++) {
#pragma unroll
        for (int nt = 0; nt < 8; nt++) {
            const int r0 = mBase + wm * 64 + mt * 16 + rl;
            const int c0 = nBase + wn * 64 + nt * 8 + cl;
            float* cc = acc[mt][nt];
            if constexpr (MODE == 0) {
                const float b0 = bias[c0], b1 = bias[c0 + 1];
#pragma unroll
                for (int rr = 0; rr < 2; rr++) {
                    float w0 = (cc[2 * rr + 0] + b0) * 32.0f;
                    float w1 = (cc[2 * rr + 1] + b1) * 32.0f;
                    __half h0 = __float2half_rn(w0), h1 = __float2half_rn(w1);
                    __half l0 = __float2half_rn(w0 - __half2float(h0));
                    __half l1 = __float2half_rn(w1 - __half2float(h1));
                    size_t idx = (size_t)(r0 + 8 * rr) * HD + c0;
                    *(__half2*)(g_qh + idx) = __halves2half2(h0, h1);
                    *(__half2*)(g_ql + idx) = __halves2half2(l0, l1);
                }
            } else if constexpr (MODE == 3) {
                const int nk = g_nk[z];
                const float b0 = bias[1024 + c0], b1 = bias[1024 + c0 + 1];
#pragma unroll
                for (int rr = 0; rr < 2; rr++) {
                    const int j = r0 + 8 * rr;
                    if (j >= nk) continue;
                    float w0 = cc[2 * rr + 0] + b0;
                    float w1 = cc[2 * rr + 1] + b1;
                    if (c0 < 1024) {
                        __half h0 = __float2half_rn(w0), h1 = __float2half_rn(w1);
                        __half l0 = __float2half_rn(w0 - __half2float(h0));
                        __half l1 = __float2half_rn(w1 - __half2float(h1));
                        size_t idx = ((size_t)z * SEQ + j) * HD + c0;
                        *(__half2*)(g_kch + idx) = __halves2half2(h0, h1);
                        *(__half2*)(g_kcl + idx) = __halves2half2(l0, l1);
                    } else {
                        *(float2*)(g_v + ((size_t)z * SEQ + j) * HD + (c0 - 1024)) =
                            make_float2(w0, w1);
                    }
                }
            } else if constexpr (MODE == 1) {
                float* Cb = g_p + (size_t)z * SEQ * SEQ;
                *(float2*)(Cb + (size_t)r0 * SEQ + c0)       = make_float2(cc[0], cc[1]);
                *(float2*)(Cb + (size_t)(r0 + 8) * SEQ + c0) = make_float2(cc[2], cc[3]);
            } else {
                float* Cb = Cout + (size_t)z * SEQ * HD;
                *(float2*)(Cb + (size_t)r0 * HD + c0)        = make_float2(cc[0], cc[1]);
                *(float2*)(Cb + (size_t)(r0 + 8) * HD + c0)  = make_float2(cc[2], cc[3]);
            }
        }
    }
}

// ---------------- softmax over compact scores: g_p -> g_ph/g_pl ------------
__global__ __launch_bounds__(256)
void softmax_kernel()
{
    const int row = blockIdx.x;          // 0..8191
    const int b   = row >> 11;
    const int nk  = g_nk[b];
    const int nkp = g_nkpad[b];
    float* p = g_p + (size_t)row * SEQ;
    __half* ph = g_ph + (size_t)row * SEQ;
    __half* pl = g_pl + (size_t)row * SEQ;
    const int tid = threadIdx.x;
    __shared__ float red[256];

    float mx = -CUDART_INF_F;
#pragma unroll
    for (int t = 0; t < 8; t++) {
        int j = tid + t * 256;
        if (j < nk) mx = fmaxf(mx, p[j]);
    }
    red[tid] = mx;
    __syncthreads();
    for (int s = 128; s > 0; s >>= 1) {
        if (tid < s) red[tid] = fmaxf(red[tid], red[tid + s]);
        __syncthreads();
    }
    mx = red[0];
    __syncthreads();

    float vals[8];
    float sm = 0.0f;
#pragma unroll
    for (int t = 0; t < 8; t++) {
        int j = tid + t * 256;
        float e = (j < nk) ? __expf(p[j] - mx) : 0.0f;
        vals[t] = e;
        sm += e;
    }
    red[tid] = sm;
    __syncthreads();
    for (int s = 128; s > 0; s >>= 1) {
        if (tid < s) red[tid] += red[tid + s];
        __syncthreads();
    }
    const float inv = 1.0f / red[0];
#pragma unroll
    for (int t = 0; t < 8; t++) {
        int j = tid + t * 256;
        if (j < nkp) {
            float w = vals[t] * inv;     // 0 for j in [nk, nkp)
            __half h = __float2half_rn(w);
            ph[j] = h;
            pl[j] = __float2half_rn(w - __half2float(h));
        }
    }
}

// ---------------- launch ----------------
extern "C" void kernel_launch(void* const* d_in, const int* in_sizes, int n_in,
                              void* d_out, int out_size)
{
    const float* qkv  = (const float*)d_in[0];
    const void*  mask = d_in[1];
    const float* W    = (const float*)d_in[2];
    const float* bqkv = (const float*)d_in[3];
    float* out = (float*)d_out;

    cudaFuncSetAttribute(hmma_gemm<0>, cudaFuncAttributeMaxDynamicSharedMemorySize, SMEM_TOT);
    cudaFuncSetAttribute(hmma_gemm<1>, cudaFuncAttributeMaxDynamicSharedMemorySize, SMEM_TOT);
    cudaFuncSetAttribute(hmma_gemm<2>, cudaFuncAttributeMaxDynamicSharedMemorySize, SMEM_TOT);
    cudaFuncSetAttribute(hmma_gemm<3>, cudaFuncAttributeMaxDynamicSharedMemorySize, SMEM_TOT);

    detect_mask_kernel<<<1, 256>>>(mask);
    normalize_mask_kernel<<<(BATCH * SEQ + 255) / 256, 256>>>(mask);
    scan_mask_kernel<<<BATCH, 256>>>();

    // split qkv input: fp32 -> fp16 hi/lo
    {
        __half *qh, *ql;
        cudaGetSymbolAddress((void**)&qh, g_qkvh);
        cudaGetSymbolAddress((void**)&ql, g_qkvl);
        int n4 = BATCH * SEQ * DIN / 4;
        split_kernel<<<(n4 + 255) / 256, 256>>>(qkv, qh, ql, n4);
    }
    // transpose + split W: [1024,3072] -> [3072,1024]
    {
        __half *wh, *wl;
        cudaGetSymbolAddress((void**)&wh, g_wth);
        cudaGetSymbolAddress((void**)&wl, g_wtl);
        dim3 grid(N3 / 32, DIN / 32, 1);
        transpose_split_kernel<<<grid, dim3(32, 8)>>>(W, wh, wl, DIN, N3);
    }
    // GEMM1a: q projection (M=8192, N=1024)
    {
        dim3 grid(1024 / 128, (BATCH * SEQ) / 256, 1);
        hmma_gemm<0><<<grid, 256, SMEM_TOT>>>(bqkv, nullptr);
    }
    // GEMM1b: k+v projection on compacted rows (M=nk per batch, N=2048)
    {
        dim3 grid(2048 / 128, SEQ / 256, BATCH);
        hmma_gemm<3><<<grid, 256, SMEM_TOT>>>(bqkv, nullptr);
    }
    zero_kc_pad_kernel<<<dim3(128, 1, BATCH), 256>>>();
    // transpose + split compacted V -> V^T
    {
        dim3 grid(DIN / 32, SEQ / 32, BATCH);
        transpose_split_v_kernel<<<grid, dim3(32, 8)>>>();
    }
    // GEMM2: scores = q @ kc^T (N limited to nkpad via early exit)
    {
        dim3 grid(SEQ / 128, SEQ / 256, BATCH);
        hmma_gemm<1><<<grid, 256, SMEM_TOT>>>(nullptr, nullptr);
    }
    softmax_kernel<<<BATCH * SEQ, 256>>>();
    // GEMM3: out = P_c @ V_c (K = nkpad dynamic)
    {
        dim3 grid(HD / 128, SEQ / 256, BATCH);
        hmma_gemm<2><<<grid, 256, SMEM_TOT>>>(nullptr, out);
    }
}

// round 7
// speedup vs baseline: 4.2896x; 1.0959x over previous
#include <cuda_runtime.h>
#include <cuda_fp16.h>
#include <math_constants.h>
#include <cstdint>

// Problem constants
#define BATCH 4
#define SEQ   2048
#define DIN   1024
#define HD    1024
#define N3    3072   // 3*HD

// ---------------- device scratch (no allocations allowed) ----------------
__device__ __align__(16) __half g_qkvh[BATCH * SEQ * DIN];
__device__ __align__(16) __half g_qkvl[BATCH * SEQ * DIN];
__device__ __align__(16) __half g_wth[N3 * DIN];
__device__ __align__(16) __half g_wtl[N3 * DIN];
__device__ __align__(16) __half g_qh[BATCH * SEQ * HD];
__device__ __align__(16) __half g_ql[BATCH * SEQ * HD];
__device__ __align__(16) __half g_kch[BATCH * SEQ * HD];   // compacted keys (split)
__device__ __align__(16) __half g_kcl[BATCH * SEQ * HD];
__device__ __align__(16) float  g_v[BATCH * SEQ * HD];     // compacted V (fp32 rows)
__device__ __align__(16) __half g_vth[BATCH * HD * SEQ];   // compacted V^T (split)
__device__ __align__(16) __half g_vtl[BATCH * HD * SEQ];
__device__ __align__(16) float  g_p[(size_t)BATCH * SEQ * SEQ];
__device__ __align__(16) __half g_ph[(size_t)BATCH * SEQ * SEQ];  // P as fp16 (hi only)
__device__ int g_srcidx[BATCH * SEQ];   // compact j -> original position (0 for j >= nk)
__device__ int g_nk[BATCH];
__device__ int g_nkpad[BATCH];          // ceil128(nk)

// ---------------- helpers ----------------
__device__ __forceinline__ uint32_t smem_u32(const void* p) {
    uint32_t a;
    asm("{ .reg .u64 t; cvta.to.shared.u64 t, %1; cvt.u32.u64 %0, t; }" : "=r"(a) : "l"(p));
    return a;
}
__device__ __forceinline__ void ldm4(uint32_t* r, uint32_t addr) {
    asm volatile("ldmatrix.sync.aligned.m8n8.x4.shared.b16 {%0,%1,%2,%3}, [%4];"
                 : "=r"(r[0]), "=r"(r[1]), "=r"(r[2]), "=r"(r[3]) : "r"(addr));
}
__device__ __forceinline__ void mma16816(float* c, const uint32_t* a,
                                         uint32_t b0, uint32_t b1) {
    asm volatile(
        "mma.sync.aligned.m16n8k16.row.col.f32.f16.f16.f32 "
        "{%0,%1,%2,%3}, {%4,%5,%6,%7}, {%8,%9}, {%0,%1,%2,%3};"
        : "+f"(c[0]), "+f"(c[1]), "+f"(c[2]), "+f"(c[3])
        : "r"(a[0]), "r"(a[1]), "r"(a[2]), "r"(a[3]), "r"(b0), "r"(b1));
}
__device__ __forceinline__ void cpa16(uint32_t dst, const void* src) {
    asm volatile("cp.async.cg.shared.global [%0], [%1], 16;" :: "r"(dst), "l"(src));
}
#define CP_COMMIT() asm volatile("cp.async.commit_group;" ::: "memory")
#define CP_WAIT(n)  asm volatile("cp.async.wait_group %0;" :: "n"(n) : "memory")

// ---------------- mask detect + normalize + compaction scan (fused) --------
__global__ __launch_bounds__(256)
void scan_mask_kernel(const void* mptr)
{
    const int b   = blockIdx.x;
    const int tid = threadIdx.x;
    __shared__ int sums[256];
    __shared__ int okInt, okFloat;
    if (tid == 0) { okInt = 1; okFloat = 1; }
    __syncthreads();
    // dtype sniff over first 2048 32-bit words (same result in every block)
    const unsigned int* w = (const unsigned int*)mptr;
    for (int i = tid; i < 2048; i += 256) {
        unsigned int x = w[i];
        if (!(x == 0u || x == 1u))          okInt = 0;
        if (!(x == 0u || x == 0x3F800000u)) okFloat = 0;
    }
    // zero-fill srcidx (safe gather addresses for pad rows)
#pragma unroll
    for (int i = 0; i < 8; i++) g_srcidx[b * SEQ + tid * 8 + i] = 0;
    __syncthreads();
    const int flag = okInt ? 0 : (okFloat ? 1 : 2);

    int keep[8], loc[8];
    int s = 0;
#pragma unroll
    for (int i = 0; i < 8; i++) {
        const int gi = b * SEQ + tid * 8 + i;
        int m;
        if (flag == 0)      m = (((const int*)mptr)[gi] != 0);
        else if (flag == 1) m = (((const float*)mptr)[gi] != 0.0f);
        else                m = (((const unsigned char*)mptr)[gi] != 0);
        keep[i] = !m;
        loc[i]  = s;
        s += keep[i];
    }
    sums[tid] = s;
    __syncthreads();
    // Hillis-Steele inclusive scan
    for (int d = 1; d < 256; d <<= 1) {
        int v = (tid >= d) ? sums[tid - d] : 0;
        __syncthreads();
        sums[tid] += v;
        __syncthreads();
    }
    const int offs = sums[tid] - s;   // exclusive
#pragma unroll
    for (int i = 0; i < 8; i++) {
        if (keep[i]) g_srcidx[b * SEQ + offs + loc[i]] = tid * 8 + i;
    }
    if (tid == 255) {
        const int total = sums[255];
        g_nk[b]    = total;
        g_nkpad[b] = (total + 127) & ~127;
    }
}

// zero the pad rows [nk, nkpad) of compacted K
__global__ __launch_bounds__(256)
void zero_kc_pad_kernel()
{
    const int b   = blockIdx.z;
    const int row = g_nk[b] + blockIdx.x;
    if (row >= g_nkpad[b]) return;
    const size_t idx = ((size_t)b * SEQ + row) * HD + threadIdx.x * 4;
    *(uint2*)(g_kch + idx) = make_uint2(0, 0);
    *(uint2*)(g_kcl + idx) = make_uint2(0, 0);
}

// ---------------- elementwise split: fp32 -> (hi, lo) fp16 ----------------
__global__ __launch_bounds__(256)
void split_kernel(const float* __restrict__ in, __half* __restrict__ oh,
                  __half* __restrict__ ol, int n4)
{
    int i = blockIdx.x * blockDim.x + threadIdx.x;
    if (i >= n4) return;
    float4 v = ((const float4*)in)[i];
    __half h0 = __float2half_rn(v.x), h1 = __float2half_rn(v.y);
    __half h2 = __float2half_rn(v.z), h3 = __float2half_rn(v.w);
    __half l0 = __float2half_rn(v.x - __half2float(h0));
    __half l1 = __float2half_rn(v.y - __half2float(h1));
    __half l2 = __float2half_rn(v.z - __half2float(h2));
    __half l3 = __float2half_rn(v.w - __half2float(h3));
    ((__half2*)oh)[2 * i]     = __halves2half2(h0, h1);
    ((__half2*)oh)[2 * i + 1] = __halves2half2(h2, h3);
    ((__half2*)ol)[2 * i]     = __halves2half2(l0, l1);
    ((__half2*)ol)[2 * i + 1] = __halves2half2(l2, l3);
}

// ---------------- transpose + split W ----------------
__global__ void transpose_split_kernel(const float* __restrict__ in,
                                       __half* __restrict__ oh, __half* __restrict__ ol,
                                       int R, int C)
{
    __shared__ float t[32][33];
    int bx = blockIdx.x * 32, by = blockIdx.y * 32;
    int x = threadIdx.x, y = threadIdx.y;
#pragma unroll
    for (int i = y; i < 32; i += 8) t[i][x] = in[(size_t)(by + i) * C + bx + x];
    __syncthreads();
#pragma unroll
    for (int i = y; i < 32; i += 8) {
        float w = t[x][i];
        __half h = __float2half_rn(w);
        size_t idx = (size_t)(bx + i) * R + by + x;
        oh[idx] = h;
        ol[idx] = __float2half_rn(w - __half2float(h));
    }
}

// ---- transpose + split compacted V: vt[h][j] = split(g_v[j][h]) for j<nk, else 0
__global__ void transpose_split_v_kernel()
{
    const int b = blockIdx.z;
    const float* in = g_v + (size_t)b * SEQ * HD;
    __half* oh = g_vth + (size_t)b * HD * SEQ;
    __half* ol = g_vtl + (size_t)b * HD * SEQ;
    const int nk = g_nk[b];

    __shared__ float t[32][33];
    int bx = blockIdx.x * 32;   // head dim
    int by = blockIdx.y * 32;   // compact key dim
    int x = threadIdx.x, y = threadIdx.y;
#pragma unroll
    for (int i = y; i < 32; i += 8) {
        const int j = by + i;
        t[i][x] = (j < nk) ? in[(size_t)j * HD + bx + x] : 0.0f;
    }
    __syncthreads();
#pragma unroll
    for (int i = y; i < 32; i += 8) {
        float w = t[x][i];
        __half h = __float2half_rn(w);
        size_t idx = (size_t)(bx + i) * SEQ + by + x;
        oh[idx] = h;
        ol[idx] = __float2half_rn(w - __half2float(h));
    }
}

// ---------------- fp16 split GEMM, CTA 256x128x32, warp 64x64, cp.async ----
// MODE 0: q-proj:  qkv_split[8192,1024] @ wt_split[0:1024] + b -> q split (*32)   [3-pass]
// MODE 3: kv-proj: gathered qkv rows (nk per batch) @ wt_split[1024:3072] + b     [3-pass]
//                  -> compacted K split / compacted V fp32
// MODE 1: q_split @ kc_split -> g_p (N limited to nkpad, per batch z)             [3-pass]
// MODE 2: P fp16 @ vtc_split -> out (K = nkpad dynamic, per batch z)              [2-pass]
#define NSTAGE   3
#define ST_AH    0
#define ST_AL    16384
#define ST_BH    32768
#define ST_BL    40960
#define STAGE_SZ 49152
#define SMEM_TOT (NSTAGE * STAGE_SZ)   // 147456

template <int MODE>
__global__ __launch_bounds__(256, 1)
void hmma_gemm(const float* __restrict__ bias, float* __restrict__ Cout)
{
    constexpr int K = (MODE == 2) ? 2048 : 1024;   // k-extent == row stride (all modes)
    constexpr bool ALO = (MODE != 2);              // A-lo pass enabled
    const int z = blockIdx.z;
    int NT;
    if constexpr (MODE == 2) NT = g_nkpad[z] >> 5;
    else NT = 1024 / 32;

    const int nBase = blockIdx.x * 128;
    const int mBase = blockIdx.y * 256;
    if constexpr (MODE == 1) { if (nBase >= g_nkpad[z]) return; }
    if constexpr (MODE == 3) { if (mBase >= g_nk[z])    return; }

    extern __shared__ char smem[];
    const uint32_t sbase = smem_u32(smem);
    const int tid  = threadIdx.x;
    const int wid  = tid >> 5;
    const int lane = tid & 31;
    const int wm   = wid >> 1;
    const int wn   = wid & 1;

    const __half *Ah, *Al, *Bh, *Bl;
    if constexpr (MODE == 0) {
        Ah = g_qkvh; Al = g_qkvl; Bh = g_wth; Bl = g_wtl;
    } else if constexpr (MODE == 3) {
        Ah = g_qkvh + (size_t)z * SEQ * DIN; Al = g_qkvl + (size_t)z * SEQ * DIN;
        Bh = g_wth + (size_t)1024 * DIN;     Bl = g_wtl + (size_t)1024 * DIN;
    } else if constexpr (MODE == 1) {
        Ah = g_qh  + (size_t)z * SEQ * HD; Al = g_ql  + (size_t)z * SEQ * HD;
        Bh = g_kch + (size_t)z * SEQ * HD; Bl = g_kcl + (size_t)z * SEQ * HD;
    } else {
        Ah = g_ph  + (size_t)z * SEQ * SEQ; Al = Ah;   // no A-lo in MODE 2
        Bh = g_vth + (size_t)z * HD * SEQ;  Bl = g_vtl + (size_t)z * HD * SEQ;
    }

    // ---- cp.async loader state ----
    const int lrow = tid >> 2;
    const int lc   = tid & 3;
    const uint32_t swc = (uint32_t)((lc ^ ((lrow >> 1) & 3)) << 4);
    const uint32_t dA0 = (uint32_t)lrow * 64 + swc;
    const __half *pAh[4], *pAl[4], *pBh[2], *pBl[2];
#pragma unroll
    for (int i = 0; i < 4; i++) {
        int ar = mBase + lrow + i * 64;
        if constexpr (MODE == 3) ar = g_srcidx[z * SEQ + ar];
        pAh[i] = Ah + (size_t)ar * K + lc * 8;
        pAl[i] = Al + (size_t)ar * K + lc * 8;
    }
#pragma unroll
    for (int i = 0; i < 2; i++) {
        pBh[i] = Bh + (size_t)(nBase + lrow + i * 64) * K + lc * 8;
        pBl[i] = Bl + (size_t)(nBase + lrow + i * 64) * K + lc * 8;
    }

    // ---- ldmatrix fragment addressing ----
    const int roff = (lane & 7) + ((lane >> 3) & 1) * 8;
    const int cq   = lane >> 4;
    const int xr   = (roff >> 1) & 3;
    const uint32_t abase = (uint32_t)(wm * 64 + roff) * 64;
    const uint32_t bbase = (uint32_t)(wn * 64 + roff) * 64;
    uint32_t kcofs[2];
    kcofs[0] = (uint32_t)((cq ^ xr) << 4);
    kcofs[1] = (uint32_t)(((2 + cq) ^ xr) << 4);

    float acc[4][8][4] = {};

#pragma unroll
    for (int s = 0; s < NSTAGE - 1; s++) {
        const uint32_t sb = sbase + s * STAGE_SZ;
#pragma unroll
        for (int i = 0; i < 4; i++) {
            cpa16(sb + ST_AH + dA0 + i * 4096, pAh[i]);
            if constexpr (ALO) cpa16(sb + ST_AL + dA0 + i * 4096, pAl[i]);
            pAh[i] += 32; pAl[i] += 32;
        }
#pragma unroll
        for (int i = 0; i < 2; i++) {
            cpa16(sb + ST_BH + dA0 + i * 4096, pBh[i]);
            cpa16(sb + ST_BL + dA0 + i * 4096, pBl[i]);
            pBh[i] += 32; pBl[i] += 32;
        }
        CP_COMMIT();
    }

    for (int kt = 0; kt < NT; kt++) {
        CP_WAIT(NSTAGE - 2);
        __syncthreads();

        if (kt + NSTAGE - 1 < NT) {
            const uint32_t sb = sbase + ((kt + NSTAGE - 1) % NSTAGE) * STAGE_SZ;
#pragma unroll
            for (int i = 0; i < 4; i++) {
                cpa16(sb + ST_AH + dA0 + i * 4096, pAh[i]);
                if constexpr (ALO) cpa16(sb + ST_AL + dA0 + i * 4096, pAl[i]);
                pAh[i] += 32; pAl[i] += 32;
            }
#pragma unroll
            for (int i = 0; i < 2; i++) {
                cpa16(sb + ST_BH + dA0 + i * 4096, pBh[i]);
                cpa16(sb + ST_BL + dA0 + i * 4096, pBl[i]);
                pBh[i] += 32; pBl[i] += 32;
            }
        }
        CP_COMMIT();

        const uint32_t stb = sbase + (kt % NSTAGE) * STAGE_SZ;
#pragma unroll
        for (int ks = 0; ks < 2; ks++) {
            uint32_t ah[4][4], al[4][4], bh[4][4], bl[4][4];
#pragma unroll
            for (int mt = 0; mt < 4; mt++) {
                ldm4(ah[mt], stb + ST_AH + abase + mt * 1024 + kcofs[ks]);
                if constexpr (ALO)
                    ldm4(al[mt], stb + ST_AL + abase + mt * 1024 + kcofs[ks]);
            }
#pragma unroll
            for (int ng = 0; ng < 4; ng++) {
                ldm4(bh[ng], stb + ST_BH + bbase + ng * 1024 + kcofs[ks]);
                ldm4(bl[ng], stb + ST_BL + bbase + ng * 1024 + kcofs[ks]);
            }
#pragma unroll
            for (int mt = 0; mt < 4; mt++) {
#pragma unroll
                for (int ng = 0; ng < 4; ng++) {
#pragma unroll
                    for (int nb = 0; nb < 2; nb++) {
                        float* cc = acc[mt][ng * 2 + nb];
                        mma16816(cc, ah[mt], bh[ng][nb], bh[ng][nb + 2]);
                        mma16816(cc, ah[mt], bl[ng][nb], bl[ng][nb + 2]);
                        if constexpr (ALO)
                            mma16816(cc, al[mt], bh[ng][nb], bh[ng][nb + 2]);
                    }
                }
            }
        }
    }

    // ---------------- epilogue ----------------
    const int rl = lane >> 2;
    const int cl = 2 * (lane & 3);
#pragma unroll
    for (int mt = 0; mt < 4; mt++) {
#pragma unroll
        for (int nt = 0; nt < 8; nt++) {
            const int r0 = mBase + wm * 64 + mt * 16 + rl;
            const int c0 = nBase + wn * 64 + nt * 8 + cl;
            float* cc = acc[mt][nt];
            if constexpr (MODE == 0) {
                const float b0 = bias[c0], b1 = bias[c0 + 1];
#pragma unroll
                for (int rr = 0; rr < 2; rr++) {
                    float w0 = (cc[2 * rr + 0] + b0) * 32.0f;
                    float w1 = (cc[2 * rr + 1] + b1) * 32.0f;
                    __half h0 = __float2half_rn(w0), h1 = __float2half_rn(w1);
                    __half l0 = __float2half_rn(w0 - __half2float(h0));
                    __half l1 = __float2half_rn(w1 - __half2float(h1));
                    size_t idx = (size_t)(r0 + 8 * rr) * HD + c0;
                    *(__half2*)(g_qh + idx) = __halves2half2(h0, h1);
                    *(__half2*)(g_ql + idx) = __halves2half2(l0, l1);
                }
            } else if constexpr (MODE == 3) {
                const int nk = g_nk[z];
                const float b0 = bias[1024 + c0], b1 = bias[1024 + c0 + 1];
#pragma unroll
                for (int rr = 0; rr < 2; rr++) {
                    const int j = r0 + 8 * rr;
                    if (j >= nk) continue;
                    float w0 = cc[2 * rr + 0] + b0;
                    float w1 = cc[2 * rr + 1] + b1;
                    if (c0 < 1024) {
                        __half h0 = __float2half_rn(w0), h1 = __float2half_rn(w1);
                        __half l0 = __float2half_rn(w0 - __half2float(h0));
                        __half l1 = __float2half_rn(w1 - __half2float(h1));
                        size_t idx = ((size_t)z * SEQ + j) * HD + c0;
                        *(__half2*)(g_kch + idx) = __halves2half2(h0, h1);
                        *(__half2*)(g_kcl + idx) = __halves2half2(l0, l1);
                    } else {
                        *(float2*)(g_v + ((size_t)z * SEQ + j) * HD + (c0 - 1024)) =
                            make_float2(w0, w1);
                    }
                }
            } else if constexpr (MODE == 1) {
                float* Cb = g_p + (size_t)z * SEQ * SEQ;
                *(float2*)(Cb + (size_t)r0 * SEQ + c0)       = make_float2(cc[0], cc[1]);
                *(float2*)(Cb + (size_t)(r0 + 8) * SEQ + c0) = make_float2(cc[2], cc[3]);
            } else {
                float* Cb = Cout + (size_t)z * SEQ * HD;
                *(float2*)(Cb + (size_t)r0 * HD + c0)        = make_float2(cc[0], cc[1]);
                *(float2*)(Cb + (size_t)(r0 + 8) * HD + c0)  = make_float2(cc[2], cc[3]);
            }
        }
    }
}

// ---------------- softmax over compact scores: g_p -> g_ph (fp16) ----------
__global__ __launch_bounds__(256)
void softmax_kernel()
{
    const int row = blockIdx.x;          // 0..8191
    const int b   = row >> 11;
    const int nk  = g_nk[b];
    const int nkp = g_nkpad[b];
    float* p = g_p + (size_t)row * SEQ;
    __half* ph = g_ph + (size_t)row * SEQ;
    const int tid = threadIdx.x;
    __shared__ float red[256];

    float mx = -CUDART_INF_F;
#pragma unroll
    for (int t = 0; t < 8; t++) {
        int j = tid + t * 256;
        if (j < nk) mx = fmaxf(mx, p[j]);
    }
    red[tid] = mx;
    __syncthreads();
    for (int s = 128; s > 0; s >>= 1) {
        if (tid < s) red[tid] = fmaxf(red[tid], red[tid + s]);
        __syncthreads();
    }
    mx = red[0];
    __syncthreads();

    float vals[8];
    float sm = 0.0f;
#pragma unroll
    for (int t = 0; t < 8; t++) {
        int j = tid + t * 256;
        float e = (j < nk) ? __expf(p[j] - mx) : 0.0f;
        vals[t] = e;
        sm += e;
    }
    red[tid] = sm;
    __syncthreads();
    for (int s = 128; s > 0; s >>= 1) {
        if (tid < s) red[tid] += red[tid + s];
        __syncthreads();
    }
    const float inv = 1.0f / red[0];
#pragma unroll
    for (int t = 0; t < 8; t++) {
        int j = tid + t * 256;
        if (j < nkp) ph[j] = __float2half_rn(vals[t] * inv);  // 0 in pad region
    }
}

// ---------------- launch ----------------
extern "C" void kernel_launch(void* const* d_in, const int* in_sizes, int n_in,
                              void* d_out, int out_size)
{
    const float* qkv  = (const float*)d_in[0];
    const void*  mask = d_in[1];
    const float* W    = (const float*)d_in[2];
    const float* bqkv = (const float*)d_in[3];
    float* out = (float*)d_out;

    cudaFuncSetAttribute(hmma_gemm<0>, cudaFuncAttributeMaxDynamicSharedMemorySize, SMEM_TOT);
    cudaFuncSetAttribute(hmma_gemm<1>, cudaFuncAttributeMaxDynamicSharedMemorySize, SMEM_TOT);
    cudaFuncSetAttribute(hmma_gemm<2>, cudaFuncAttributeMaxDynamicSharedMemorySize, SMEM_TOT);
    cudaFuncSetAttribute(hmma_gemm<3>, cudaFuncAttributeMaxDynamicSharedMemorySize, SMEM_TOT);

    scan_mask_kernel<<<BATCH, 256>>>(mask);

    // split qkv input: fp32 -> fp16 hi/lo
    {
        __half *qh, *ql;
        cudaGetSymbolAddress((void**)&qh, g_qkvh);
        cudaGetSymbolAddress((void**)&ql, g_qkvl);
        int n4 = BATCH * SEQ * DIN / 4;
        split_kernel<<<(n4 + 255) / 256, 256>>>(qkv, qh, ql, n4);
    }
    // transpose + split W: [1024,3072] -> [3072,1024]
    {
        __half *wh, *wl;
        cudaGetSymbolAddress((void**)&wh, g_wth);
        cudaGetSymbolAddress((void**)&wl, g_wtl);
        dim3 grid(N3 / 32, DIN / 32, 1);
        transpose_split_kernel<<<grid, dim3(32, 8)>>>(W, wh, wl, DIN, N3);
    }
    // GEMM1a: q projection (M=8192, N=1024)
    {
        dim3 grid(1024 / 128, (BATCH * SEQ) / 256, 1);
        hmma_gemm<0><<<grid, 256, SMEM_TOT>>>(bqkv, nullptr);
    }
    // GEMM1b: k+v projection on compacted rows (M=nk per batch, N=2048)
    {
        dim3 grid(2048 / 128, SEQ / 256, BATCH);
        hmma_gemm<3><<<grid, 256, SMEM_TOT>>>(bqkv, nullptr);
    }
    zero_kc_pad_kernel<<<dim3(128, 1, BATCH), 256>>>();
    // transpose + split compacted V -> V^T
    {
        dim3 grid(DIN / 32, SEQ / 32, BATCH);
        transpose_split_v_kernel<<<grid, dim3(32, 8)>>>();
    }
    // GEMM2: scores = q @ kc^T (N limited to nkpad via early exit)
    {
        dim3 grid(SEQ / 128, SEQ / 256, BATCH);
        hmma_gemm<1><<<grid, 256, SMEM_TOT>>>(nullptr, nullptr);
    }
    softmax_kernel<<<BATCH * SEQ, 256>>>();
    // GEMM3: out = P_fp16 @ V_c split (K = nkpad dynamic, 2-pass)
    {
        dim3 grid(HD / 128, SEQ / 256, BATCH);
        hmma_gemm<2><<<grid, 256, SMEM_TOT>>>(nullptr, out);
    }
}

// round 8
// speedup vs baseline: 4.5347x; 1.0571x over previous
#include <cuda_runtime.h>
#include <cuda_fp16.h>
#include <math_constants.h>
#include <cstdint>

// Problem constants
#define BATCH 4
#define SEQ   2048
#define DIN   1024
#define HD    1024
#define N3    3072   // 3*HD

// ---------------- device scratch (no allocations allowed) ----------------
__device__ __align__(16) __half g_qkvh[BATCH * SEQ * DIN];
__device__ __align__(16) __half g_qkvl[BATCH * SEQ * DIN];
__device__ __align__(16) __half g_wth[N3 * DIN];
__device__ __align__(16) __half g_wtl[N3 * DIN];
__device__ __align__(16) __half g_qh[BATCH * SEQ * HD];
__device__ __align__(16) __half g_ql[BATCH * SEQ * HD];
__device__ __align__(16) __half g_kch[BATCH * SEQ * HD];   // compacted keys (split)
__device__ __align__(16) __half g_kcl[BATCH * SEQ * HD];
__device__ __align__(16) float  g_v[BATCH * SEQ * HD];     // compacted V (fp32 rows)
__device__ __align__(16) __half g_vth[BATCH * HD * SEQ];   // compacted V^T (split)
__device__ __align__(16) __half g_vtl[BATCH * HD * SEQ];
__device__ __align__(16) float  g_p[(size_t)BATCH * SEQ * SEQ];
__device__ __align__(16) __half g_ph[(size_t)BATCH * SEQ * SEQ];  // P as fp16 (hi only)
__device__ int g_srcidx[BATCH * SEQ];   // compact j -> original position (0 for j >= nk)
__device__ int g_nk[BATCH];
__device__ int g_nkpad[BATCH];          // ceil128(nk)

// ---------------- helpers ----------------
__device__ __forceinline__ uint32_t smem_u32(const void* p) {
    uint32_t a;
    asm("{ .reg .u64 t; cvta.to.shared.u64 t, %1; cvt.u32.u64 %0, t; }" : "=r"(a) : "l"(p));
    return a;
}
__device__ __forceinline__ void ldm4(uint32_t* r, uint32_t addr) {
    asm volatile("ldmatrix.sync.aligned.m8n8.x4.shared.b16 {%0,%1,%2,%3}, [%4];"
                 : "=r"(r[0]), "=r"(r[1]), "=r"(r[2]), "=r"(r[3]) : "r"(addr));
}
__device__ __forceinline__ void mma16816(float* c, const uint32_t* a,
                                         uint32_t b0, uint32_t b1) {
    asm volatile(
        "mma.sync.aligned.m16n8k16.row.col.f32.f16.f16.f32 "
        "{%0,%1,%2,%3}, {%4,%5,%6,%7}, {%8,%9}, {%0,%1,%2,%3};"
        : "+f"(c[0]), "+f"(c[1]), "+f"(c[2]), "+f"(c[3])
        : "r"(a[0]), "r"(a[1]), "r"(a[2]), "r"(a[3]), "r"(b0), "r"(b1));
}
__device__ __forceinline__ void cpa16(uint32_t dst, const void* src) {
    asm volatile("cp.async.cg.shared.global [%0], [%1], 16;" :: "r"(dst), "l"(src));
}
#define CP_COMMIT() asm volatile("cp.async.commit_group;" ::: "memory")
#define CP_WAIT(n)  asm volatile("cp.async.wait_group %0;" :: "n"(n) : "memory")

// ---------------- mask detect + normalize + compaction scan (fused) --------
__global__ __launch_bounds__(256)
void scan_mask_kernel(const void* mptr)
{
    const int b   = blockIdx.x;
    const int tid = threadIdx.x;
    __shared__ int sums[256];
    __shared__ int okInt, okFloat;
    if (tid == 0) { okInt = 1; okFloat = 1; }
    __syncthreads();
    // dtype sniff over first 2048 32-bit words (same result in every block)
    const unsigned int* w = (const unsigned int*)mptr;
    for (int i = tid; i < 2048; i += 256) {
        unsigned int x = w[i];
        if (!(x == 0u || x == 1u))          okInt = 0;
        if (!(x == 0u || x == 0x3F800000u)) okFloat = 0;
    }
    // zero-fill srcidx (safe gather addresses for pad rows)
#pragma unroll
    for (int i = 0; i < 8; i++) g_srcidx[b * SEQ + tid * 8 + i] = 0;
    __syncthreads();
    const int flag = okInt ? 0 : (okFloat ? 1 : 2);

    int keep[8], loc[8];
    int s = 0;
#pragma unroll
    for (int i = 0; i < 8; i++) {
        const int gi = b * SEQ + tid * 8 + i;
        int m;
        if (flag == 0)      m = (((const int*)mptr)[gi] != 0);
        else if (flag == 1) m = (((const float*)mptr)[gi] != 0.0f);
        else                m = (((const unsigned char*)mptr)[gi] != 0);
        keep[i] = !m;
        loc[i]  = s;
        s += keep[i];
    }
    sums[tid] = s;
    __syncthreads();
    // Hillis-Steele inclusive scan
    for (int d = 1; d < 256; d <<= 1) {
        int v = (tid >= d) ? sums[tid - d] : 0;
        __syncthreads();
        sums[tid] += v;
        __syncthreads();
    }
    const int offs = sums[tid] - s;   // exclusive
#pragma unroll
    for (int i = 0; i < 8; i++) {
        if (keep[i]) g_srcidx[b * SEQ + offs + loc[i]] = tid * 8 + i;
    }
    if (tid == 255) {
        const int total = sums[255];
        g_nk[b]    = total;
        g_nkpad[b] = (total + 127) & ~127;
    }
}

// zero the pad rows [nk, nkpad) of compacted K
__global__ __launch_bounds__(256)
void zero_kc_pad_kernel()
{
    const int b   = blockIdx.z;
    const int row = g_nk[b] + blockIdx.x;
    if (row >= g_nkpad[b]) return;
    const size_t idx = ((size_t)b * SEQ + row) * HD + threadIdx.x * 4;
    *(uint2*)(g_kch + idx) = make_uint2(0, 0);
    *(uint2*)(g_kcl + idx) = make_uint2(0, 0);
}

// ---------------- elementwise split: fp32 -> (hi, lo) fp16 ----------------
__global__ __launch_bounds__(256)
void split_kernel(const float* __restrict__ in, __half* __restrict__ oh,
                  __half* __restrict__ ol, int n4)
{
    int i = blockIdx.x * blockDim.x + threadIdx.x;
    if (i >= n4) return;
    float4 v = ((const float4*)in)[i];
    __half h0 = __float2half_rn(v.x), h1 = __float2half_rn(v.y);
    __half h2 = __float2half_rn(v.z), h3 = __float2half_rn(v.w);
    __half l0 = __float2half_rn(v.x - __half2float(h0));
    __half l1 = __float2half_rn(v.y - __half2float(h1));
    __half l2 = __float2half_rn(v.z - __half2float(h2));
    __half l3 = __float2half_rn(v.w - __half2float(h3));
    ((__half2*)oh)[2 * i]     = __halves2half2(h0, h1);
    ((__half2*)oh)[2 * i + 1] = __halves2half2(h2, h3);
    ((__half2*)ol)[2 * i]     = __halves2half2(l0, l1);
    ((__half2*)ol)[2 * i + 1] = __halves2half2(l2, l3);
}

// ---------------- transpose + split W ----------------
__global__ void transpose_split_kernel(const float* __restrict__ in,
                                       __half* __restrict__ oh, __half* __restrict__ ol,
                                       int R, int C)
{
    __shared__ float t[32][33];
    int bx = blockIdx.x * 32, by = blockIdx.y * 32;
    int x = threadIdx.x, y = threadIdx.y;
#pragma unroll
    for (int i = y; i < 32; i += 8) t[i][x] = in[(size_t)(by + i) * C + bx + x];
    __syncthreads();
#pragma unroll
    for (int i = y; i < 32; i += 8) {
        float w = t[x][i];
        __half h = __float2half_rn(w);
        size_t idx = (size_t)(bx + i) * R + by + x;
        oh[idx] = h;
        ol[idx] = __float2half_rn(w - __half2float(h));
    }
}

// ---- transpose + split compacted V: vt[h][j] = split(g_v[j][h]) for j<nk, else 0
__global__ void transpose_split_v_kernel()
{
    const int b = blockIdx.z;
    const float* in = g_v + (size_t)b * SEQ * HD;
    __half* oh = g_vth + (size_t)b * HD * SEQ;
    __half* ol = g_vtl + (size_t)b * HD * SEQ;
    const int nk = g_nk[b];

    __shared__ float t[32][33];
    int bx = blockIdx.x * 32;   // head dim
    int by = blockIdx.y * 32;   // compact key dim
    int x = threadIdx.x, y = threadIdx.y;
#pragma unroll
    for (int i = y; i < 32; i += 8) {
        const int j = by + i;
        t[i][x] = (j < nk) ? in[(size_t)j * HD + bx + x] : 0.0f;
    }
    __syncthreads();
#pragma unroll
    for (int i = y; i < 32; i += 8) {
        float w = t[x][i];
        __half h = __float2half_rn(w);
        size_t idx = (size_t)(bx + i) * SEQ + by + x;
        oh[idx] = h;
        ol[idx] = __float2half_rn(w - __half2float(h));
    }
}

// ---------------- fp16 split GEMM, CTA 128x128x32, warp 64x64, 2 CTA/SM ----
// MODE 0: q-proj:  qkv_split[8192,1024] @ wt_split[0:1024] + b -> q split (*32)   [3-pass]
// MODE 3: kv-proj: gathered qkv rows (nk per batch) @ wt_split[1024:3072] + b     [3-pass]
//                  -> compacted K split / compacted V fp32
// MODE 1: q_split @ kc_split -> g_p (N limited to nkpad, per batch z)             [3-pass]
// MODE 2: P fp16 @ vtc_split -> out (K = nkpad dynamic, per batch z)              [2-pass]
#define NSTAGE   3
#define ST_AH    0
#define ST_AL    8192
#define ST_BH    16384
#define ST_BL    24576
#define STAGE_SZ 32768
#define SMEM_TOT (NSTAGE * STAGE_SZ)   // 98304

template <int MODE>
__global__ __launch_bounds__(128, 2)
void hmma_gemm(const float* __restrict__ bias, float* __restrict__ Cout)
{
    constexpr int K = (MODE == 2) ? 2048 : 1024;   // k-extent == row stride (all modes)
    constexpr bool ALO = (MODE != 2);              // A-lo pass enabled
    const int z = blockIdx.z;
    int NT;
    if constexpr (MODE == 2) NT = g_nkpad[z] >> 5;
    else NT = 1024 / 32;

    const int nBase = blockIdx.x * 128;
    const int mBase = blockIdx.y * 128;
    if constexpr (MODE == 1) { if (nBase >= g_nkpad[z]) return; }
    if constexpr (MODE == 3) { if (mBase >= g_nk[z])    return; }

    extern __shared__ char smem[];
    const uint32_t sbase = smem_u32(smem);
    const int tid  = threadIdx.x;
    const int wid  = tid >> 5;       // 0..3
    const int lane = tid & 31;
    const int wm   = wid >> 1;       // 0..1
    const int wn   = wid & 1;        // 0..1

    const __half *Ah, *Al, *Bh, *Bl;
    if constexpr (MODE == 0) {
        Ah = g_qkvh; Al = g_qkvl; Bh = g_wth; Bl = g_wtl;
    } else if constexpr (MODE == 3) {
        Ah = g_qkvh + (size_t)z * SEQ * DIN; Al = g_qkvl + (size_t)z * SEQ * DIN;
        Bh = g_wth + (size_t)1024 * DIN;     Bl = g_wtl + (size_t)1024 * DIN;
    } else if constexpr (MODE == 1) {
        Ah = g_qh  + (size_t)z * SEQ * HD; Al = g_ql  + (size_t)z * SEQ * HD;
        Bh = g_kch + (size_t)z * SEQ * HD; Bl = g_kcl + (size_t)z * SEQ * HD;
    } else {
        Ah = g_ph  + (size_t)z * SEQ * SEQ; Al = Ah;   // no A-lo in MODE 2
        Bh = g_vth + (size_t)z * HD * SEQ;  Bl = g_vtl + (size_t)z * HD * SEQ;
    }

    // ---- cp.async loader state: 128 threads, 32 rows/pass, 4 passes/tile ----
    const int lrow = tid >> 2;                       // 0..31
    const int lc   = tid & 3;                        // 16B chunk in 64B row
    const uint32_t swc = (uint32_t)((lc ^ ((lrow >> 1) & 3)) << 4);
    const uint32_t dA0 = (uint32_t)lrow * 64 + swc;  // pass i adds i*2048 (32 rows)
    const __half *pAh[4], *pAl[4], *pBh[4], *pBl[4];
#pragma unroll
    for (int i = 0; i < 4; i++) {
        int ar = mBase + lrow + i * 32;
        if constexpr (MODE == 3) ar = g_srcidx[z * SEQ + ar];
        pAh[i] = Ah + (size_t)ar * K + lc * 8;
        pAl[i] = Al + (size_t)ar * K + lc * 8;
        pBh[i] = Bh + (size_t)(nBase + lrow + i * 32) * K + lc * 8;
        pBl[i] = Bl + (size_t)(nBase + lrow + i * 32) * K + lc * 8;
    }

    // ---- ldmatrix fragment addressing ----
    const int roff = (lane & 7) + ((lane >> 3) & 1) * 8;
    const int cq   = lane >> 4;
    const int xr   = (roff >> 1) & 3;
    const uint32_t abase = (uint32_t)(wm * 64 + roff) * 64;
    const uint32_t bbase = (uint32_t)(wn * 64 + roff) * 64;
    uint32_t kcofs[2];
    kcofs[0] = (uint32_t)((cq ^ xr) << 4);
    kcofs[1] = (uint32_t)(((2 + cq) ^ xr) << 4);

    float acc[4][8][4] = {};

#pragma unroll
    for (int s = 0; s < NSTAGE - 1; s++) {
        const uint32_t sb = sbase + s * STAGE_SZ;
#pragma unroll
        for (int i = 0; i < 4; i++) {
            cpa16(sb + ST_AH + dA0 + i * 2048, pAh[i]);
            if constexpr (ALO) cpa16(sb + ST_AL + dA0 + i * 2048, pAl[i]);
            cpa16(sb + ST_BH + dA0 + i * 2048, pBh[i]);
            cpa16(sb + ST_BL + dA0 + i * 2048, pBl[i]);
            pAh[i] += 32; pAl[i] += 32; pBh[i] += 32; pBl[i] += 32;
        }
        CP_COMMIT();
    }

    for (int kt = 0; kt < NT; kt++) {
        CP_WAIT(NSTAGE - 2);
        __syncthreads();

        if (kt + NSTAGE - 1 < NT) {
            const uint32_t sb = sbase + ((kt + NSTAGE - 1) % NSTAGE) * STAGE_SZ;
#pragma unroll
            for (int i = 0; i < 4; i++) {
                cpa16(sb + ST_AH + dA0 + i * 2048, pAh[i]);
                if constexpr (ALO) cpa16(sb + ST_AL + dA0 + i * 2048, pAl[i]);
                cpa16(sb + ST_BH + dA0 + i * 2048, pBh[i]);
                cpa16(sb + ST_BL + dA0 + i * 2048, pBl[i]);
                pAh[i] += 32; pAl[i] += 32; pBh[i] += 32; pBl[i] += 32;
            }
        }
        CP_COMMIT();

        const uint32_t stb = sbase + (kt % NSTAGE) * STAGE_SZ;
#pragma unroll
        for (int ks = 0; ks < 2; ks++) {
            uint32_t ah[4][4], al[4][4], bh[4][4], bl[4][4];
#pragma unroll
            for (int mt = 0; mt < 4; mt++) {
                ldm4(ah[mt], stb + ST_AH + abase + mt * 1024 + kcofs[ks]);
                if constexpr (ALO)
                    ldm4(al[mt], stb + ST_AL + abase + mt * 1024 + kcofs[ks]);
            }
#pragma unroll
            for (int ng = 0; ng < 4; ng++) {
                ldm4(bh[ng], stb + ST_BH + bbase + ng * 1024 + kcofs[ks]);
                ldm4(bl[ng], stb + ST_BL + bbase + ng * 1024 + kcofs[ks]);
            }
#pragma unroll
            for (int mt = 0; mt < 4; mt++) {
#pragma unroll
                for (int ng = 0; ng < 4; ng++) {
#pragma unroll
                    for (int nb = 0; nb < 2; nb++) {
                        float* cc = acc[mt][ng * 2 + nb];
                        mma16816(cc, ah[mt], bh[ng][nb], bh[ng][nb + 2]);
                        mma16816(cc, ah[mt], bl[ng][nb], bl[ng][nb + 2]);
                        if constexpr (ALO)
                            mma16816(cc, al[mt], bh[ng][nb], bh[ng][nb + 2]);
                    }
                }
            }
        }
    }

    // ---------------- epilogue ----------------
    const int rl = lane >> 2;
    const int cl = 2 * (lane & 3);
#pragma unroll
    for (int mt = 0; mt < 4; mt++) {
#pragma unroll
        for (int nt = 0; nt < 8; nt++) {
            const int r0 = mBase + wm * 64 + mt * 16 + rl;
            const int c0 = nBase + wn * 64 + nt * 8 + cl;
            float* cc = acc[mt][nt];
            if constexpr (MODE == 0) {
                const float b0 = bias[c0], b1 = bias[c0 + 1];
#pragma unroll
                for (int rr = 0; rr < 2; rr++) {
                    float w0 = (cc[2 * rr + 0] + b0) * 32.0f;
                    float w1 = (cc[2 * rr + 1] + b1) * 32.0f;
                    __half h0 = __float2half_rn(w0), h1 = __float2half_rn(w1);
                    __half l0 = __float2half_rn(w0 - __half2float(h0));
                    __half l1 = __float2half_rn(w1 - __half2float(h1));
                    size_t idx = (size_t)(r0 + 8 * rr) * HD + c0;
                    *(__half2*)(g_qh + idx) = __halves2half2(h0, h1);
                    *(__half2*)(g_ql + idx) = __halves2half2(l0, l1);
                }
            } else if constexpr (MODE == 3) {
                const int nk = g_nk[z];
                const float b0 = bias[1024 + c0], b1 = bias[1024 + c0 + 1];
#pragma unroll
                for (int rr = 0; rr < 2; rr++) {
                    const int j = r0 + 8 * rr;
                    if (j >= nk) continue;
                    float w0 = cc[2 * rr + 0] + b0;
                    float w1 = cc[2 * rr + 1] + b1;
                    if (c0 < 1024) {
                        __half h0 = __float2half_rn(w0), h1 = __float2half_rn(w1);
                        __half l0 = __float2half_rn(w0 - __half2float(h0));
                        __half l1 = __float2half_rn(w1 - __half2float(h1));
                        size_t idx = ((size_t)z * SEQ + j) * HD + c0;
                        *(__half2*)(g_kch + idx) = __halves2half2(h0, h1);
                        *(__half2*)(g_kcl + idx) = __halves2half2(l0, l1);
                    } else {
                        *(float2*)(g_v + ((size_t)z * SEQ + j) * HD + (c0 - 1024)) =
                            make_float2(w0, w1);
                    }
                }
            } else if constexpr (MODE == 1) {
                float* Cb = g_p + (size_t)z * SEQ * SEQ;
                *(float2*)(Cb + (size_t)r0 * SEQ + c0)       = make_float2(cc[0], cc[1]);
                *(float2*)(Cb + (size_t)(r0 + 8) * SEQ + c0) = make_float2(cc[2], cc[3]);
            } else {
                float* Cb = Cout + (size_t)z * SEQ * HD;
                *(float2*)(Cb + (size_t)r0 * HD + c0)        = make_float2(cc[0], cc[1]);
                *(float2*)(Cb + (size_t)(r0 + 8) * HD + c0)  = make_float2(cc[2], cc[3]);
            }
        }
    }
}

// ---------------- softmax over compact scores: g_p -> g_ph (fp16) ----------
__global__ __launch_bounds__(256)
void softmax_kernel()
{
    const int row = blockIdx.x;          // 0..8191
    const int b   = row >> 11;
    const int nk  = g_nk[b];
    const int nkp = g_nkpad[b];
    float* p = g_p + (size_t)row * SEQ;
    __half* ph = g_ph + (size_t)row * SEQ;
    const int tid = threadIdx.x;
    __shared__ float red[256];

    float mx = -CUDART_INF_F;
#pragma unroll
    for (int t = 0; t < 8; t++) {
        int j = tid + t * 256;
        if (j < nk) mx = fmaxf(mx, p[j]);
    }
    red[tid] = mx;
    __syncthreads();
    for (int s = 128; s > 0; s >>= 1) {
        if (tid < s) red[tid] = fmaxf(red[tid], red[tid + s]);
        __syncthreads();
    }
    mx = red[0];
    __syncthreads();

    float vals[8];
    float sm = 0.0f;
#pragma unroll
    for (int t = 0; t < 8; t++) {
        int j = tid + t * 256;
        float e = (j < nk) ? __expf(p[j] - mx) : 0.0f;
        vals[t] = e;
        sm += e;
    }
    red[tid] = sm;
    __syncthreads();
    for (int s = 128; s > 0; s >>= 1) {
        if (tid < s) red[tid] += red[tid + s];
        __syncthreads();
    }
    const float inv = 1.0f / red[0];
#pragma unroll
    for (int t = 0; t < 8; t++) {
        int j = tid + t * 256;
        if (j < nkp) ph[j] = __float2half_rn(vals[t] * inv);  // 0 in pad region
    }
}

// ---------------- launch ----------------
extern "C" void kernel_launch(void* const* d_in, const int* in_sizes, int n_in,
                              void* d_out, int out_size)
{
    const float* qkv  = (const float*)d_in[0];
    const void*  mask = d_in[1];
    const float* W    = (const float*)d_in[2];
    const float* bqkv = (const float*)d_in[3];
    float* out = (float*)d_out;

    cudaFuncSetAttribute(hmma_gemm<0>, cudaFuncAttributeMaxDynamicSharedMemorySize, SMEM_TOT);
    cudaFuncSetAttribute(hmma_gemm<1>, cudaFuncAttributeMaxDynamicSharedMemorySize, SMEM_TOT);
    cudaFuncSetAttribute(hmma_gemm<2>, cudaFuncAttributeMaxDynamicSharedMemorySize, SMEM_TOT);
    cudaFuncSetAttribute(hmma_gemm<3>, cudaFuncAttributeMaxDynamicSharedMemorySize, SMEM_TOT);

    scan_mask_kernel<<<BATCH, 256>>>(mask);

    // split qkv input: fp32 -> fp16 hi/lo
    {
        __half *qh, *ql;
        cudaGetSymbolAddress((void**)&qh, g_qkvh);
        cudaGetSymbolAddress((void**)&ql, g_qkvl);
        int n4 = BATCH * SEQ * DIN / 4;
        split_kernel<<<(n4 + 255) / 256, 256>>>(qkv, qh, ql, n4);
    }
    // transpose + split W: [1024,3072] -> [3072,1024]
    {
        __half *wh, *wl;
        cudaGetSymbolAddress((void**)&wh, g_wth);
        cudaGetSymbolAddress((void**)&wl, g_wtl);
        dim3 grid(N3 / 32, DIN / 32, 1);
        transpose_split_kernel<<<grid, dim3(32, 8)>>>(W, wh, wl, DIN, N3);
    }
    // GEMM1a: q projection (M=8192, N=1024)
    {
        dim3 grid(1024 / 128, (BATCH * SEQ) / 128, 1);
        hmma_gemm<0><<<grid, 128, SMEM_TOT>>>(bqkv, nullptr);
    }
    // GEMM1b: k+v projection on compacted rows (M=nk per batch, N=2048)
    {
        dim3 grid(2048 / 128, SEQ / 128, BATCH);
        hmma_gemm<3><<<grid, 128, SMEM_TOT>>>(bqkv, nullptr);
    }
    zero_kc_pad_kernel<<<dim3(128, 1, BATCH), 256>>>();
    // transpose + split compacted V -> V^T
    {
        dim3 grid(DIN / 32, SEQ / 32, BATCH);
        transpose_split_v_kernel<<<grid, dim3(32, 8)>>>();
    }
    // GEMM2: scores = q @ kc^T (N limited to nkpad via early exit)
    {
        dim3 grid(SEQ / 128, SEQ / 128, BATCH);
        hmma_gemm<1><<<grid, 128, SMEM_TOT>>>(nullptr, nullptr);
    }
    softmax_kernel<<<BATCH * SEQ, 256>>>();
    // GEMM3: out = P_fp16 @ V_c split (K = nkpad dynamic, 2-pass)
    {
        dim3 grid(HD / 128, SEQ / 128, BATCH);
        hmma_gemm<2><<<grid, 128, SMEM_TOT>>>(nullptr, out);
    }
}

// round 9
// speedup vs baseline: 4.5464x; 1.0026x over previous
#include <cuda_runtime.h>
#include <cuda_fp16.h>
#include <math_constants.h>
#include <cstdint>

// Problem constants
#define BATCH 4
#define SEQ   2048
#define DIN   1024
#define HD    1024
#define N3    3072   // 3*HD

// ---------------- device scratch (no allocations allowed) ----------------
__device__ __align__(16) __half g_qkvh[BATCH * SEQ * DIN];
__device__ __align__(16) __half g_qkvl[BATCH * SEQ * DIN];
__device__ __align__(16) __half g_wth[N3 * DIN];
__device__ __align__(16) __half g_wtl[N3 * DIN];
__device__ __align__(16) __half g_qh[BATCH * SEQ * HD];
__device__ __align__(16) __half g_ql[BATCH * SEQ * HD];
__device__ __align__(16) __half g_kch[BATCH * SEQ * HD];   // compacted keys (split)
__device__ __align__(16) __half g_kcl[BATCH * SEQ * HD];
__device__ __align__(16) float  g_v[BATCH * SEQ * HD];     // compacted V (fp32 rows)
__device__ __align__(16) __half g_vth[BATCH * HD * SEQ];   // compacted V^T (split)
__device__ __align__(16) __half g_vtl[BATCH * HD * SEQ];
__device__ __align__(16) float  g_p[(size_t)BATCH * SEQ * SEQ];
__device__ __align__(16) __half g_ph[(size_t)BATCH * SEQ * SEQ];  // P as fp16 (hi only)
__device__ int g_srcidx[BATCH * SEQ];   // compact j -> original position (0 for j >= nk)
__device__ int g_nk[BATCH];
__device__ int g_nkpad[BATCH];          // ceil128(nk)

// ---------------- helpers ----------------
__device__ __forceinline__ uint32_t smem_u32(const void* p) {
    uint32_t a;
    asm("{ .reg .u64 t; cvta.to.shared.u64 t, %1; cvt.u32.u64 %0, t; }" : "=r"(a) : "l"(p));
    return a;
}
__device__ __forceinline__ void ldm4(uint32_t* r, uint32_t addr) {
    asm volatile("ldmatrix.sync.aligned.m8n8.x4.shared.b16 {%0,%1,%2,%3}, [%4];"
                 : "=r"(r[0]), "=r"(r[1]), "=r"(r[2]), "=r"(r[3]) : "r"(addr));
}
__device__ __forceinline__ void mma16816(float* c, const uint32_t* a,
                                         uint32_t b0, uint32_t b1) {
    asm volatile(
        "mma.sync.aligned.m16n8k16.row.col.f32.f16.f16.f32 "
        "{%0,%1,%2,%3}, {%4,%5,%6,%7}, {%8,%9}, {%0,%1,%2,%3};"
        : "+f"(c[0]), "+f"(c[1]), "+f"(c[2]), "+f"(c[3])
        : "r"(a[0]), "r"(a[1]), "r"(a[2]), "r"(a[3]), "r"(b0), "r"(b1));
}
__device__ __forceinline__ void cpa16(uint32_t dst, const void* src) {
    asm volatile("cp.async.cg.shared.global [%0], [%1], 16;" :: "r"(dst), "l"(src));
}
#define CP_COMMIT() asm volatile("cp.async.commit_group;" ::: "memory")
#define CP_WAIT(n)  asm volatile("cp.async.wait_group %0;" :: "n"(n) : "memory")

// ---------------- mask detect + normalize + compaction scan (fused) --------
__global__ __launch_bounds__(256)
void scan_mask_kernel(const void* mptr)
{
    const int b   = blockIdx.x;
    const int tid = threadIdx.x;
    __shared__ int sums[256];
    __shared__ int okInt, okFloat;
    if (tid == 0) { okInt = 1; okFloat = 1; }
    __syncthreads();
    // dtype sniff over first 2048 32-bit words (same result in every block)
    const unsigned int* w = (const unsigned int*)mptr;
    for (int i = tid; i < 2048; i += 256) {
        unsigned int x = w[i];
        if (!(x == 0u || x == 1u))          okInt = 0;
        if (!(x == 0u || x == 0x3F800000u)) okFloat = 0;
    }
    // zero-fill srcidx (safe gather addresses for pad rows)
#pragma unroll
    for (int i = 0; i < 8; i++) g_srcidx[b * SEQ + tid * 8 + i] = 0;
    __syncthreads();
    const int flag = okInt ? 0 : (okFloat ? 1 : 2);

    int keep[8], loc[8];
    int s = 0;
#pragma unroll
    for (int i = 0; i < 8; i++) {
        const int gi = b * SEQ + tid * 8 + i;
        int m;
        if (flag == 0)      m = (((const int*)mptr)[gi] != 0);
        else if (flag == 1) m = (((const float*)mptr)[gi] != 0.0f);
        else                m = (((const unsigned char*)mptr)[gi] != 0);
        keep[i] = !m;
        loc[i]  = s;
        s += keep[i];
    }
    sums[tid] = s;
    __syncthreads();
    // Hillis-Steele inclusive scan
    for (int d = 1; d < 256; d <<= 1) {
        int v = (tid >= d) ? sums[tid - d] : 0;
        __syncthreads();
        sums[tid] += v;
        __syncthreads();
    }
    const int offs = sums[tid] - s;   // exclusive
#pragma unroll
    for (int i = 0; i < 8; i++) {
        if (keep[i]) g_srcidx[b * SEQ + offs + loc[i]] = tid * 8 + i;
    }
    if (tid == 255) {
        const int total = sums[255];
        g_nk[b]    = total;
        g_nkpad[b] = (total + 127) & ~127;
    }
}

// zero the pad rows [nk, nkpad) of compacted K
__global__ __launch_bounds__(256)
void zero_kc_pad_kernel()
{
    const int b   = blockIdx.z;
    const int row = g_nk[b] + blockIdx.x;
    if (row >= g_nkpad[b]) return;
    const size_t idx = ((size_t)b * SEQ + row) * HD + threadIdx.x * 4;
    *(uint2*)(g_kch + idx) = make_uint2(0, 0);
    *(uint2*)(g_kcl + idx) = make_uint2(0, 0);
}

// ---------------- elementwise split: fp32 -> (hi, lo) fp16 ----------------
__global__ __launch_bounds__(256)
void split_kernel(const float* __restrict__ in, __half* __restrict__ oh,
                  __half* __restrict__ ol, int n4)
{
    int i = blockIdx.x * blockDim.x + threadIdx.x;
    if (i >= n4) return;
    float4 v = ((const float4*)in)[i];
    __half h0 = __float2half_rn(v.x), h1 = __float2half_rn(v.y);
    __half h2 = __float2half_rn(v.z), h3 = __float2half_rn(v.w);
    __half l0 = __float2half_rn(v.x - __half2float(h0));
    __half l1 = __float2half_rn(v.y - __half2float(h1));
    __half l2 = __float2half_rn(v.z - __half2float(h2));
    __half l3 = __float2half_rn(v.w - __half2float(h3));
    ((__half2*)oh)[2 * i]     = __halves2half2(h0, h1);
    ((__half2*)oh)[2 * i + 1] = __halves2half2(h2, h3);
    ((__half2*)ol)[2 * i]     = __halves2half2(l0, l1);
    ((__half2*)ol)[2 * i + 1] = __halves2half2(l2, l3);
}

// ---------------- transpose + split W ----------------
__global__ void transpose_split_kernel(const float* __restrict__ in,
                                       __half* __restrict__ oh, __half* __restrict__ ol,
                                       int R, int C)
{
    __shared__ float t[32][33];
    int bx = blockIdx.x * 32, by = blockIdx.y * 32;
    int x = threadIdx.x, y = threadIdx.y;
#pragma unroll
    for (int i = y; i < 32; i += 8) t[i][x] = in[(size_t)(by + i) * C + bx + x];
    __syncthreads();
#pragma unroll
    for (int i = y; i < 32; i += 8) {
        float w = t[x][i];
        __half h = __float2half_rn(w);
        size_t idx = (size_t)(bx + i) * R + by + x;
        oh[idx] = h;
        ol[idx] = __float2half_rn(w - __half2float(h));
    }
}

// ---- transpose + split compacted V: vt[h][j] = split(g_v[j][h]) for j<nk, else 0
__global__ void transpose_split_v_kernel()
{
    const int b = blockIdx.z;
    const float* in = g_v + (size_t)b * SEQ * HD;
    __half* oh = g_vth + (size_t)b * HD * SEQ;
    __half* ol = g_vtl + (size_t)b * HD * SEQ;
    const int nk = g_nk[b];

    __shared__ float t[32][33];
    int bx = blockIdx.x * 32;   // head dim
    int by = blockIdx.y * 32;   // compact key dim
    int x = threadIdx.x, y = threadIdx.y;
#pragma unroll
    for (int i = y; i < 32; i += 8) {
        const int j = by + i;
        t[i][x] = (j < nk) ? in[(size_t)j * HD + bx + x] : 0.0f;
    }
    __syncthreads();
#pragma unroll
    for (int i = y; i < 32; i += 8) {
        float w = t[x][i];
        __half h = __float2half_rn(w);
        size_t idx = (size_t)(bx + i) * SEQ + by + x;
        oh[idx] = h;
        ol[idx] = __float2half_rn(w - __half2float(h));
    }
}

// ---------------- fp16 split GEMM, CTA 128x128x32, warp 64x64, 2 CTA/SM ----
// MODE 0: q-proj:  qkv_split[8192,1024] @ wt_split[0:1024] + b -> q split (*32)   [3-pass]
// MODE 3: kv-proj: gathered qkv rows (nk per batch) @ wt_split[1024:3072] + b     [3-pass]
//                  -> compacted K split / compacted V fp32
// MODE 1: q_split @ kc_split -> g_p (N limited to nkpad, per batch z)             [3-pass]
// MODE 2: P fp16 @ vtc_split -> out (K = nkpad dynamic, per batch z)              [2-pass]
#define NSTAGE   3
#define ST_AH    0
#define ST_AL    8192
#define ST_BH    16384
#define ST_BL    24576
#define STAGE_SZ 32768
#define SMEM_TOT (NSTAGE * STAGE_SZ)   // 98304

template <int MODE>
__global__ __launch_bounds__(128, 2)
void hmma_gemm(const float* __restrict__ bias, float* __restrict__ Cout)
{
    constexpr int K = (MODE == 2) ? 2048 : 1024;   // k-extent == row stride (all modes)
    constexpr bool ALO = (MODE != 2);              // A-lo pass enabled
    const int z = blockIdx.z;
    int NT;
    if constexpr (MODE == 2) NT = g_nkpad[z] >> 5;
    else NT = 1024 / 32;

    const int nBase = blockIdx.x * 128;
    const int mBase = blockIdx.y * 128;
    if constexpr (MODE == 1) { if (nBase >= g_nkpad[z]) return; }
    if constexpr (MODE == 3) { if (mBase >= g_nk[z])    return; }

    extern __shared__ char smem[];
    const uint32_t sbase = smem_u32(smem);
    const int tid  = threadIdx.x;
    const int wid  = tid >> 5;       // 0..3
    const int lane = tid & 31;
    const int wm   = wid >> 1;       // 0..1
    const int wn   = wid & 1;        // 0..1

    const __half *Ah, *Al, *Bh, *Bl;
    if constexpr (MODE == 0) {
        Ah = g_qkvh; Al = g_qkvl; Bh = g_wth; Bl = g_wtl;
    } else if constexpr (MODE == 3) {
        Ah = g_qkvh + (size_t)z * SEQ * DIN; Al = g_qkvl + (size_t)z * SEQ * DIN;
        Bh = g_wth + (size_t)1024 * DIN;     Bl = g_wtl + (size_t)1024 * DIN;
    } else if constexpr (MODE == 1) {
        Ah = g_qh  + (size_t)z * SEQ * HD; Al = g_ql  + (size_t)z * SEQ * HD;
        Bh = g_kch + (size_t)z * SEQ * HD; Bl = g_kcl + (size_t)z * SEQ * HD;
    } else {
        Ah = g_ph  + (size_t)z * SEQ * SEQ; Al = Ah;   // no A-lo in MODE 2
        Bh = g_vth + (size_t)z * HD * SEQ;  Bl = g_vtl + (size_t)z * HD * SEQ;
    }

    // ---- cp.async loader state: 128 threads, 32 rows/pass, 4 passes/tile ----
    const int lrow = tid >> 2;                       // 0..31
    const int lc   = tid & 3;                        // 16B chunk in 64B row
    const uint32_t swc = (uint32_t)((lc ^ ((lrow >> 1) & 3)) << 4);
    const uint32_t dA0 = (uint32_t)lrow * 64 + swc;  // pass i adds i*2048 (32 rows)
    const __half *pAh[4], *pAl[4], *pBh[4], *pBl[4];
#pragma unroll
    for (int i = 0; i < 4; i++) {
        int ar = mBase + lrow + i * 32;
        if constexpr (MODE == 3) ar = g_srcidx[z * SEQ + ar];
        pAh[i] = Ah + (size_t)ar * K + lc * 8;
        pAl[i] = Al + (size_t)ar * K + lc * 8;
        pBh[i] = Bh + (size_t)(nBase + lrow + i * 32) * K + lc * 8;
        pBl[i] = Bl + (size_t)(nBase + lrow + i * 32) * K + lc * 8;
    }

    // ---- ldmatrix fragment addressing ----
    const int roff = (lane & 7) + ((lane >> 3) & 1) * 8;
    const int cq   = lane >> 4;
    const int xr   = (roff >> 1) & 3;
    const uint32_t abase = (uint32_t)(wm * 64 + roff) * 64;
    const uint32_t bbase = (uint32_t)(wn * 64 + roff) * 64;
    uint32_t kcofs[2];
    kcofs[0] = (uint32_t)((cq ^ xr) << 4);
    kcofs[1] = (uint32_t)(((2 + cq) ^ xr) << 4);

    float acc[4][8][4] = {};

#pragma unroll
    for (int s = 0; s < NSTAGE - 1; s++) {
        const uint32_t sb = sbase + s * STAGE_SZ;
#pragma unroll
        for (int i = 0; i < 4; i++) {
            cpa16(sb + ST_AH + dA0 + i * 2048, pAh[i]);
            if constexpr (ALO) cpa16(sb + ST_AL + dA0 + i * 2048, pAl[i]);
            cpa16(sb + ST_BH + dA0 + i * 2048, pBh[i]);
            cpa16(sb + ST_BL + dA0 + i * 2048, pBl[i]);
            pAh[i] += 32; pAl[i] += 32; pBh[i] += 32; pBl[i] += 32;
        }
        CP_COMMIT();
    }

    for (int kt = 0; kt < NT; kt++) {
        CP_WAIT(NSTAGE - 2);
        __syncthreads();

        if (kt + NSTAGE - 1 < NT) {
            const uint32_t sb = sbase + ((kt + NSTAGE - 1) % NSTAGE) * STAGE_SZ;
#pragma unroll
            for (int i = 0; i < 4; i++) {
                cpa16(sb + ST_AH + dA0 + i * 2048, pAh[i]);
                if constexpr (ALO) cpa16(sb + ST_AL + dA0 + i * 2048, pAl[i]);
                cpa16(sb + ST_BH + dA0 + i * 2048, pBh[i]);
                cpa16(sb + ST_BL + dA0 + i * 2048, pBl[i]);
                pAh[i] += 32; pAl[i] += 32; pBh[i] += 32; pBl[i] += 32;
            }
        }
        CP_COMMIT();

        const uint32_t stb = sbase + (kt % NSTAGE) * STAGE_SZ;
#pragma unroll
        for (int ks = 0; ks < 2; ks++) {
            uint32_t ah[4][4], al[4][4], bh[4][4], bl[4][4];
#pragma unroll
            for (int mt = 0; mt < 4; mt++) {
                ldm4(ah[mt], stb + ST_AH + abase + mt * 1024 + kcofs[ks]);
                if constexpr (ALO)
                    ldm4(al[mt], stb + ST_AL + abase + mt * 1024 + kcofs[ks]);
            }
#pragma unroll
            for (int ng = 0; ng < 4; ng++) {
                ldm4(bh[ng], stb + ST_BH + bbase + ng * 1024 + kcofs[ks]);
                ldm4(bl[ng], stb + ST_BL + bbase + ng * 1024 + kcofs[ks]);
            }
            // ---- pass-major sweeps: no back-to-back mma on the same acc ----
#pragma unroll
            for (int mt = 0; mt < 4; mt++)
#pragma unroll
                for (int ng = 0; ng < 4; ng++)
#pragma unroll
                    for (int nb = 0; nb < 2; nb++)
                        mma16816(acc[mt][ng * 2 + nb], ah[mt], bh[ng][nb], bh[ng][nb + 2]);
#pragma unroll
            for (int mt = 0; mt < 4; mt++)
#pragma unroll
                for (int ng = 0; ng < 4; ng++)
#pragma unroll
                    for (int nb = 0; nb < 2; nb++)
                        mma16816(acc[mt][ng * 2 + nb], ah[mt], bl[ng][nb], bl[ng][nb + 2]);
            if constexpr (ALO) {
#pragma unroll
                for (int mt = 0; mt < 4; mt++)
#pragma unroll
                    for (int ng = 0; ng < 4; ng++)
#pragma unroll
                        for (int nb = 0; nb < 2; nb++)
                            mma16816(acc[mt][ng * 2 + nb], al[mt], bh[ng][nb], bh[ng][nb + 2]);
            }
        }
    }

    // ---------------- epilogue ----------------
    const int rl = lane >> 2;
    const int cl = 2 * (lane & 3);
#pragma unroll
    for (int mt = 0; mt < 4; mt++) {
#pragma unroll
        for (int nt = 0; nt < 8; nt++) {
            const int r0 = mBase + wm * 64 + mt * 16 + rl;
            const int c0 = nBase + wn * 64 + nt * 8 + cl;
            float* cc = acc[mt][nt];
            if constexpr (MODE == 0) {
                const float b0 = bias[c0], b1 = bias[c0 + 1];
#pragma unroll
                for (int rr = 0; rr < 2; rr++) {
                    float w0 = (cc[2 * rr + 0] + b0) * 32.0f;
                    float w1 = (cc[2 * rr + 1] + b1) * 32.0f;
                    __half h0 = __float2half_rn(w0), h1 = __float2half_rn(w1);
                    __half l0 = __float2half_rn(w0 - __half2float(h0));
                    __half l1 = __float2half_rn(w1 - __half2float(h1));
                    size_t idx = (size_t)(r0 + 8 * rr) * HD + c0;
                    *(__half2*)(g_qh + idx) = __halves2half2(h0, h1);
                    *(__half2*)(g_ql + idx) = __halves2half2(l0, l1);
                }
            } else if constexpr (MODE == 3) {
                const int nk = g_nk[z];
                const float b0 = bias[1024 + c0], b1 = bias[1024 + c0 + 1];
#pragma unroll
                for (int rr = 0; rr < 2; rr++) {
                    const int j = r0 + 8 * rr;
                    if (j >= nk) continue;
                    float w0 = cc[2 * rr + 0] + b0;
                    float w1 = cc[2 * rr + 1] + b1;
                    if (c0 < 1024) {
                        __half h0 = __float2half_rn(w0), h1 = __float2half_rn(w1);
                        __half l0 = __float2half_rn(w0 - __half2float(h0));
                        __half l1 = __float2half_rn(w1 - __half2float(h1));
                        size_t idx = ((size_t)z * SEQ + j) * HD + c0;
                        *(__half2*)(g_kch + idx) = __halves2half2(h0, h1);
                        *(__half2*)(g_kcl + idx) = __halves2half2(l0, l1);
                    } else {
                        *(float2*)(g_v + ((size_t)z * SEQ + j) * HD + (c0 - 1024)) =
                            make_float2(w0, w1);
                    }
                }
            } else if constexpr (MODE == 1) {
                float* Cb = g_p + (size_t)z * SEQ * SEQ;
                *(float2*)(Cb + (size_t)r0 * SEQ + c0)       = make_float2(cc[0], cc[1]);
                *(float2*)(Cb + (size_t)(r0 + 8) * SEQ + c0) = make_float2(cc[2], cc[3]);
            } else {
                float* Cb = Cout + (size_t)z * SEQ * HD;
                *(float2*)(Cb + (size_t)r0 * HD + c0)        = make_float2(cc[0], cc[1]);
                *(float2*)(Cb + (size_t)(r0 + 8) * HD + c0)  = make_float2(cc[2], cc[3]);
            }
        }
    }
}

// ---------------- softmax over compact scores: g_p -> g_ph (fp16) ----------
__global__ __launch_bounds__(256)
void softmax_kernel()
{
    const int row = blockIdx.x;          // 0..8191
    const int b   = row >> 11;
    const int nk  = g_nk[b];
    const int nkp = g_nkpad[b];
    float* p = g_p + (size_t)row * SEQ;
    __half* ph = g_ph + (size_t)row * SEQ;
    const int tid = threadIdx.x;
    __shared__ float red[256];

    float mx = -CUDART_INF_F;
#pragma unroll
    for (int t = 0; t < 8; t++) {
        int j = tid + t * 256;
        if (j < nk) mx = fmaxf(mx, p[j]);
    }
    red[tid] = mx;
    __syncthreads();
    for (int s = 128; s > 0; s >>= 1) {
        if (tid < s) red[tid] = fmaxf(red[tid], red[tid + s]);
        __syncthreads();
    }
    mx = red[0];
    __syncthreads();

    float vals[8];
    float sm = 0.0f;
#pragma unroll
    for (int t = 0; t < 8; t++) {
        int j = tid + t * 256;
        float e = (j < nk) ? __expf(p[j] - mx) : 0.0f;
        vals[t] = e;
        sm += e;
    }
    red[tid] = sm;
    __syncthreads();
    for (int s = 128; s > 0; s >>= 1) {
        if (tid < s) red[tid] += red[tid + s];
        __syncthreads();
    }
    const float inv = 1.0f / red[0];
#pragma unroll
    for (int t = 0; t < 8; t++) {
        int j = tid + t * 256;
        if (j < nkp) ph[j] = __float2half_rn(vals[t] * inv);  // 0 in pad region
    }
}

// ---------------- launch ----------------
extern "C" void kernel_launch(void* const* d_in, const int* in_sizes, int n_in,
                              void* d_out, int out_size)
{
    const float* qkv  = (const float*)d_in[0];
    const void*  mask = d_in[1];
    const float* W    = (const float*)d_in[2];
    const float* bqkv = (const float*)d_in[3];
    float* out = (float*)d_out;

    cudaFuncSetAttribute(hmma_gemm<0>, cudaFuncAttributeMaxDynamicSharedMemorySize, SMEM_TOT);
    cudaFuncSetAttribute(hmma_gemm<1>, cudaFuncAttributeMaxDynamicSharedMemorySize, SMEM_TOT);
    cudaFuncSetAttribute(hmma_gemm<2>, cudaFuncAttributeMaxDynamicSharedMemorySize, SMEM_TOT);
    cudaFuncSetAttribute(hmma_gemm<3>, cudaFuncAttributeMaxDynamicSharedMemorySize, SMEM_TOT);

    scan_mask_kernel<<<BATCH, 256>>>(mask);

    // split qkv input: fp32 -> fp16 hi/lo
    {
        __half *qh, *ql;
        cudaGetSymbolAddress((void**)&qh, g_qkvh);
        cudaGetSymbolAddress((void**)&ql, g_qkvl);
        int n4 = BATCH * SEQ * DIN / 4;
        split_kernel<<<(n4 + 255) / 256, 256>>>(qkv, qh, ql, n4);
    }
    // transpose + split W: [1024,3072] -> [3072,1024]
    {
        __half *wh, *wl;
        cudaGetSymbolAddress((void**)&wh, g_wth);
        cudaGetSymbolAddress((void**)&wl, g_wtl);
        dim3 grid(N3 / 32, DIN / 32, 1);
        transpose_split_kernel<<<grid, dim3(32, 8)>>>(W, wh, wl, DIN, N3);
    }
    // GEMM1a: q projection (M=8192, N=1024)
    {
        dim3 grid(1024 / 128, (BATCH * SEQ) / 128, 1);
        hmma_gemm<0><<<grid, 128, SMEM_TOT>>>(bqkv, nullptr);
    }
    // GEMM1b: k+v projection on compacted rows (M=nk per batch, N=2048)
    {
        dim3 grid(2048 / 128, SEQ / 128, BATCH);
        hmma_gemm<3><<<grid, 128, SMEM_TOT>>>(bqkv, nullptr);
    }
    zero_kc_pad_kernel<<<dim3(128, 1, BATCH), 256>>>();
    // transpose + split compacted V -> V^T
    {
        dim3 grid(DIN / 32, SEQ / 32, BATCH);
        transpose_split_v_kernel<<<grid, dim3(32, 8)>>>();
    }
    // GEMM2: scores = q @ kc^T (N limited to nkpad via early exit)
    {
        dim3 grid(SEQ / 128, SEQ / 128, BATCH);
        hmma_gemm<1><<<grid, 128, SMEM_TOT>>>(nullptr, nullptr);
    }
    softmax_kernel<<<BATCH * SEQ, 256>>>();
    // GEMM3: out = P_fp16 @ V_c split (K = nkpad dynamic, 2-pass)
    {
        dim3 grid(HD / 128, SEQ / 128, BATCH);
        hmma_gemm<2><<<grid, 128, SMEM_TOT>>>(nullptr, out);
    }
}

// round 10
// speedup vs baseline: 4.8145x; 1.0590x over previous
#include <cuda_runtime.h>
#include <cuda_fp16.h>
#include <math_constants.h>
#include <cstdint>

// Problem constants
#define BATCH 4
#define SEQ   2048
#define DIN   1024
#define HD    1024
#define N3    3072   // 3*HD

// ---------------- device scratch (no allocations allowed) ----------------
__device__ __align__(16) __half g_qkvh[BATCH * SEQ * DIN];
__device__ __align__(16) __half g_qkvl[BATCH * SEQ * DIN];
__device__ __align__(16) __half g_wth[N3 * DIN];
__device__ __align__(16) __half g_wtl[N3 * DIN];
__device__ __align__(16) __half g_qh[BATCH * SEQ * HD];
__device__ __align__(16) __half g_ql[BATCH * SEQ * HD];
__device__ __align__(16) __half g_kch[BATCH * SEQ * HD];   // compacted keys (split)
__device__ __align__(16) __half g_kcl[BATCH * SEQ * HD];
__device__ __align__(16) float  g_v[BATCH * SEQ * HD];     // compacted V (fp32 rows)
__device__ __align__(16) __half g_vth[BATCH * HD * SEQ];   // compacted V^T (split)
__device__ __align__(16) __half g_vtl[BATCH * HD * SEQ];
__device__ __align__(16) float  g_p[(size_t)BATCH * SEQ * SEQ];
__device__ __align__(16) __half g_ph[(size_t)BATCH * SEQ * SEQ];  // P as fp16 (hi only)
__device__ int g_srcidx[BATCH * SEQ];   // compact j -> original position (0 for j >= nk)
__device__ int g_nk[BATCH];
__device__ int g_nkpad[BATCH];          // ceil128(nk)

// ---------------- helpers ----------------
__device__ __forceinline__ uint32_t smem_u32(const void* p) {
    uint32_t a;
    asm("{ .reg .u64 t; cvta.to.shared.u64 t, %1; cvt.u32.u64 %0, t; }" : "=r"(a) : "l"(p));
    return a;
}
__device__ __forceinline__ void ldm4(uint32_t* r, uint32_t addr) {
    asm volatile("ldmatrix.sync.aligned.m8n8.x4.shared.b16 {%0,%1,%2,%3}, [%4];"
                 : "=r"(r[0]), "=r"(r[1]), "=r"(r[2]), "=r"(r[3]) : "r"(addr));
}
__device__ __forceinline__ void mma16816(float* c, const uint32_t* a,
                                         uint32_t b0, uint32_t b1) {
    asm volatile(
        "mma.sync.aligned.m16n8k16.row.col.f32.f16.f16.f32 "
        "{%0,%1,%2,%3}, {%4,%5,%6,%7}, {%8,%9}, {%0,%1,%2,%3};"
        : "+f"(c[0]), "+f"(c[1]), "+f"(c[2]), "+f"(c[3])
        : "r"(a[0]), "r"(a[1]), "r"(a[2]), "r"(a[3]), "r"(b0), "r"(b1));
}
__device__ __forceinline__ void cpa16(uint32_t dst, const void* src) {
    asm volatile("cp.async.cg.shared.global [%0], [%1], 16;" :: "r"(dst), "l"(src));
}
#define CP_COMMIT() asm volatile("cp.async.commit_group;" ::: "memory")
#define CP_WAIT(n)  asm volatile("cp.async.wait_group %0;" :: "n"(n) : "memory")

// ---------------- mask detect + normalize + compaction scan (fused) --------
__global__ __launch_bounds__(256)
void scan_mask_kernel(const void* mptr)
{
    const int b   = blockIdx.x;
    const int tid = threadIdx.x;
    __shared__ int sums[256];
    __shared__ int okInt, okFloat;
    if (tid == 0) { okInt = 1; okFloat = 1; }
    __syncthreads();
    // dtype sniff over first 2048 32-bit words (same result in every block)
    const unsigned int* w = (const unsigned int*)mptr;
    for (int i = tid; i < 2048; i += 256) {
        unsigned int x = w[i];
        if (!(x == 0u || x == 1u))          okInt = 0;
        if (!(x == 0u || x == 0x3F800000u)) okFloat = 0;
    }
    // zero-fill srcidx (safe gather addresses for pad rows)
#pragma unroll
    for (int i = 0; i < 8; i++) g_srcidx[b * SEQ + tid * 8 + i] = 0;
    __syncthreads();
    const int flag = okInt ? 0 : (okFloat ? 1 : 2);

    int keep[8], loc[8];
    int s = 0;
#pragma unroll
    for (int i = 0; i < 8; i++) {
        const int gi = b * SEQ + tid * 8 + i;
        int m;
        if (flag == 0)      m = (((const int*)mptr)[gi] != 0);
        else if (flag == 1) m = (((const float*)mptr)[gi] != 0.0f);
        else                m = (((const unsigned char*)mptr)[gi] != 0);
        keep[i] = !m;
        loc[i]  = s;
        s += keep[i];
    }
    sums[tid] = s;
    __syncthreads();
    // Hillis-Steele inclusive scan
    for (int d = 1; d < 256; d <<= 1) {
        int v = (tid >= d) ? sums[tid - d] : 0;
        __syncthreads();
        sums[tid] += v;
        __syncthreads();
    }
    const int offs = sums[tid] - s;   // exclusive
#pragma unroll
    for (int i = 0; i < 8; i++) {
        if (keep[i]) g_srcidx[b * SEQ + offs + loc[i]] = tid * 8 + i;
    }
    if (tid == 255) {
        const int total = sums[255];
        g_nk[b]    = total;
        g_nkpad[b] = (total + 127) & ~127;
    }
}

// zero the pad rows [nk, nkpad) of compacted K
__global__ __launch_bounds__(256)
void zero_kc_pad_kernel()
{
    const int b   = blockIdx.z;
    const int row = g_nk[b] + blockIdx.x;
    if (row >= g_nkpad[b]) return;
    const size_t idx = ((size_t)b * SEQ + row) * HD + threadIdx.x * 4;
    *(uint2*)(g_kch + idx) = make_uint2(0, 0);
    *(uint2*)(g_kcl + idx) = make_uint2(0, 0);
}

// ---------------- elementwise split: fp32 -> (hi, lo) fp16 ----------------
__global__ __launch_bounds__(256)
void split_kernel(const float* __restrict__ in, __half* __restrict__ oh,
                  __half* __restrict__ ol, int n4)
{
    int i = blockIdx.x * blockDim.x + threadIdx.x;
    if (i >= n4) return;
    float4 v = ((const float4*)in)[i];
    __half h0 = __float2half_rn(v.x), h1 = __float2half_rn(v.y);
    __half h2 = __float2half_rn(v.z), h3 = __float2half_rn(v.w);
    __half l0 = __float2half_rn(v.x - __half2float(h0));
    __half l1 = __float2half_rn(v.y - __half2float(h1));
    __half l2 = __float2half_rn(v.z - __half2float(h2));
    __half l3 = __float2half_rn(v.w - __half2float(h3));
    ((__half2*)oh)[2 * i]     = __halves2half2(h0, h1);
    ((__half2*)oh)[2 * i + 1] = __halves2half2(h2, h3);
    ((__half2*)ol)[2 * i]     = __halves2half2(l0, l1);
    ((__half2*)ol)[2 * i + 1] = __halves2half2(l2, l3);
}

// ---------------- transpose + split W ----------------
__global__ void transpose_split_kernel(const float* __restrict__ in,
                                       __half* __restrict__ oh, __half* __restrict__ ol,
                                       int R, int C)
{
    __shared__ float t[32][33];
    int bx = blockIdx.x * 32, by = blockIdx.y * 32;
    int x = threadIdx.x, y = threadIdx.y;
#pragma unroll
    for (int i = y; i < 32; i += 8) t[i][x] = in[(size_t)(by + i) * C + bx + x];
    __syncthreads();
#pragma unroll
    for (int i = y; i < 32; i += 8) {
        float w = t[x][i];
        __half h = __float2half_rn(w);
        size_t idx = (size_t)(bx + i) * R + by + x;
        oh[idx] = h;
        ol[idx] = __float2half_rn(w - __half2float(h));
    }
}

// ---- transpose + split compacted V: vt[h][j] = split(g_v[j][h]) for j<nk, else 0
__global__ void transpose_split_v_kernel()
{
    const int b = blockIdx.z;
    const float* in = g_v + (size_t)b * SEQ * HD;
    __half* oh = g_vth + (size_t)b * HD * SEQ;
    __half* ol = g_vtl + (size_t)b * HD * SEQ;
    const int nk = g_nk[b];

    __shared__ float t[32][33];
    int bx = blockIdx.x * 32;   // head dim
    int by = blockIdx.y * 32;   // compact key dim
    int x = threadIdx.x, y = threadIdx.y;
#pragma unroll
    for (int i = y; i < 32; i += 8) {
        const int j = by + i;
        t[i][x] = (j < nk) ? in[(size_t)j * HD + bx + x] : 0.0f;
    }
    __syncthreads();
#pragma unroll
    for (int i = y; i < 32; i += 8) {
        float w = t[x][i];
        __half h = __float2half_rn(w);
        size_t idx = (size_t)(bx + i) * SEQ + by + x;
        oh[idx] = h;
        ol[idx] = __float2half_rn(w - __half2float(h));
    }
}

// ---------------- fp16 split GEMM, CTA 128x128x32, warp 64x64, 2 CTA/SM ----
// MODE 4: MERGED projection launch (1536 linearized CTAs):
//   CTA [0,512):    q-proj  qkv_split @ wt_split[0:1024] + b -> q split (*32)  [3-pass]
//   CTA [512,1536): kv-proj gathered rows @ wt_split[1024:3072] + b            [3-pass]
//                   -> compacted K split / compacted V fp32
// MODE 1: q_split @ kc_split -> g_p (N limited to nkpad, per batch z)          [3-pass]
// MODE 2: P fp16 @ vtc_split -> out (K = nkpad dynamic, per batch z)           [2-pass]
#define NSTAGE   3
#define ST_AH    0
#define ST_AL    8192
#define ST_BH    16384
#define ST_BL    24576
#define STAGE_SZ 32768
#define SMEM_TOT (NSTAGE * STAGE_SZ)   // 98304

template <int MODE>
__global__ __launch_bounds__(128, 2)
void hmma_gemm(const float* __restrict__ bias, float* __restrict__ Cout)
{
    constexpr int K = (MODE == 2) ? 2048 : 1024;   // k-extent == row stride (all modes)
    constexpr bool ALO = (MODE != 2);              // A-lo pass enabled

    int z = blockIdx.z;
    int mBase, nBase;
    bool kv = false;
    if constexpr (MODE == 4) {
        const int bx = blockIdx.x;
        if (bx < 512) {                    // q-proj: N=1024 (8 tiles), M=8192 (64 tiles)
            nBase = (bx & 7) * 128;
            mBase = (bx >> 3) * 128;
            z = 0;
        } else {                           // kv-proj: N=2048 (16), M=2048 (16), B=4
            kv = true;
            const int b2 = bx - 512;
            nBase = (b2 & 15) * 128;
            const int rem = b2 >> 4;
            mBase = (rem & 15) * 128;
            z = rem >> 4;
            if (mBase >= g_nk[z]) return;
        }
    } else {
        nBase = blockIdx.x * 128;
        mBase = blockIdx.y * 128;
        if constexpr (MODE == 1) { if (nBase >= g_nkpad[z]) return; }
    }

    int NT;
    if constexpr (MODE == 2) NT = g_nkpad[z] >> 5;
    else NT = 1024 / 32;

    extern __shared__ char smem[];
    const uint32_t sbase = smem_u32(smem);
    const int tid  = threadIdx.x;
    const int wid  = tid >> 5;       // 0..3
    const int lane = tid & 31;
    const int wm   = wid >> 1;       // 0..1
    const int wn   = wid & 1;        // 0..1

    const __half *Ah, *Al, *Bh, *Bl;
    if constexpr (MODE == 4) {
        if (!kv) {
            Ah = g_qkvh; Al = g_qkvl; Bh = g_wth; Bl = g_wtl;
        } else {
            Ah = g_qkvh + (size_t)z * SEQ * DIN; Al = g_qkvl + (size_t)z * SEQ * DIN;
            Bh = g_wth + (size_t)1024 * DIN;     Bl = g_wtl + (size_t)1024 * DIN;
        }
    } else if constexpr (MODE == 1) {
        Ah = g_qh  + (size_t)z * SEQ * HD; Al = g_ql  + (size_t)z * SEQ * HD;
        Bh = g_kch + (size_t)z * SEQ * HD; Bl = g_kcl + (size_t)z * SEQ * HD;
    } else {
        Ah = g_ph  + (size_t)z * SEQ * SEQ; Al = Ah;   // no A-lo in MODE 2
        Bh = g_vth + (size_t)z * HD * SEQ;  Bl = g_vtl + (size_t)z * HD * SEQ;
    }

    // ---- cp.async loader state: 128 threads, 32 rows/pass, 4 passes/tile ----
    const int lrow = tid >> 2;                       // 0..31
    const int lc   = tid & 3;                        // 16B chunk in 64B row
    const uint32_t swc = (uint32_t)((lc ^ ((lrow >> 1) & 3)) << 4);
    const uint32_t dA0 = (uint32_t)lrow * 64 + swc;  // pass i adds i*2048 (32 rows)
    const __half *pAh[4], *pAl[4], *pBh[4], *pBl[4];
#pragma unroll
    for (int i = 0; i < 4; i++) {
        int ar = mBase + lrow + i * 32;
        if constexpr (MODE == 4) { if (kv) ar = g_srcidx[z * SEQ + ar]; }
        pAh[i] = Ah + (size_t)ar * K + lc * 8;
        pAl[i] = Al + (size_t)ar * K + lc * 8;
        pBh[i] = Bh + (size_t)(nBase + lrow + i * 32) * K + lc * 8;
        pBl[i] = Bl + (size_t)(nBase + lrow + i * 32) * K + lc * 8;
    }

    // ---- ldmatrix fragment addressing ----
    const int roff = (lane & 7) + ((lane >> 3) & 1) * 8;
    const int cq   = lane >> 4;
    const int xr   = (roff >> 1) & 3;
    const uint32_t abase = (uint32_t)(wm * 64 + roff) * 64;
    const uint32_t bbase = (uint32_t)(wn * 64 + roff) * 64;
    uint32_t kcofs[2];
    kcofs[0] = (uint32_t)((cq ^ xr) << 4);
    kcofs[1] = (uint32_t)(((2 + cq) ^ xr) << 4);

    float acc[4][8][4] = {};

#pragma unroll
    for (int s = 0; s < NSTAGE - 1; s++) {
        const uint32_t sb = sbase + s * STAGE_SZ;
#pragma unroll
        for (int i = 0; i < 4; i++) {
            cpa16(sb + ST_AH + dA0 + i * 2048, pAh[i]);
            if constexpr (ALO) cpa16(sb + ST_AL + dA0 + i * 2048, pAl[i]);
            cpa16(sb + ST_BH + dA0 + i * 2048, pBh[i]);
            cpa16(sb + ST_BL + dA0 + i * 2048, pBl[i]);
            pAh[i] += 32; pAl[i] += 32; pBh[i] += 32; pBl[i] += 32;
        }
        CP_COMMIT();
    }

    for (int kt = 0; kt < NT; kt++) {
        CP_WAIT(NSTAGE - 2);
        __syncthreads();

        if (kt + NSTAGE - 1 < NT) {
            const uint32_t sb = sbase + ((kt + NSTAGE - 1) % NSTAGE) * STAGE_SZ;
#pragma unroll
            for (int i = 0; i < 4; i++) {
                cpa16(sb + ST_AH + dA0 + i * 2048, pAh[i]);
                if constexpr (ALO) cpa16(sb + ST_AL + dA0 + i * 2048, pAl[i]);
                cpa16(sb + ST_BH + dA0 + i * 2048, pBh[i]);
                cpa16(sb + ST_BL + dA0 + i * 2048, pBl[i]);
                pAh[i] += 32; pAl[i] += 32; pBh[i] += 32; pBl[i] += 32;
            }
        }
        CP_COMMIT();

        const uint32_t stb = sbase + (kt % NSTAGE) * STAGE_SZ;
#pragma unroll
        for (int ks = 0; ks < 2; ks++) {
            uint32_t ah[4][4], al[4][4], bh[4][4], bl[4][4];
#pragma unroll
            for (int mt = 0; mt < 4; mt++) {
                ldm4(ah[mt], stb + ST_AH + abase + mt * 1024 + kcofs[ks]);
                if constexpr (ALO)
                    ldm4(al[mt], stb + ST_AL + abase + mt * 1024 + kcofs[ks]);
            }
#pragma unroll
            for (int ng = 0; ng < 4; ng++) {
                ldm4(bh[ng], stb + ST_BH + bbase + ng * 1024 + kcofs[ks]);
                ldm4(bl[ng], stb + ST_BL + bbase + ng * 1024 + kcofs[ks]);
            }
#pragma unroll
            for (int mt = 0; mt < 4; mt++) {
#pragma unroll
                for (int ng = 0; ng < 4; ng++) {
#pragma unroll
                    for (int nb = 0; nb < 2; nb++) {
                        float* cc = acc[mt][ng * 2 + nb];
                        mma16816(cc, ah[mt], bh[ng][nb], bh[ng][nb + 2]);
                        mma16816(cc, ah[mt], bl[ng][nb], bl[ng][nb + 2]);
                        if constexpr (ALO)
                            mma16816(cc, al[mt], bh[ng][nb], bh[ng][nb + 2]);
                    }
                }
            }
        }
    }

    // ---------------- epilogue ----------------
    const int rl = lane >> 2;
    const int cl = 2 * (lane & 3);
#pragma unroll
    for (int mt = 0; mt < 4; mt++) {
#pragma unroll
        for (int nt = 0; nt < 8; nt++) {
            const int r0 = mBase + wm * 64 + mt * 16 + rl;
            const int c0 = nBase + wn * 64 + nt * 8 + cl;
            float* cc = acc[mt][nt];
            if constexpr (MODE == 4) {
                if (!kv) {
                    const float b0 = bias[c0], b1 = bias[c0 + 1];
#pragma unroll
                    for (int rr = 0; rr < 2; rr++) {
                        float w0 = (cc[2 * rr + 0] + b0) * 32.0f;
                        float w1 = (cc[2 * rr + 1] + b1) * 32.0f;
                        __half h0 = __float2half_rn(w0), h1 = __float2half_rn(w1);
                        __half l0 = __float2half_rn(w0 - __half2float(h0));
                        __half l1 = __float2half_rn(w1 - __half2float(h1));
                        size_t idx = (size_t)(r0 + 8 * rr) * HD + c0;
                        *(__half2*)(g_qh + idx) = __halves2half2(h0, h1);
                        *(__half2*)(g_ql + idx) = __halves2half2(l0, l1);
                    }
                } else {
                    const int nk = g_nk[z];
                    const float b0 = bias[1024 + c0], b1 = bias[1024 + c0 + 1];
#pragma unroll
                    for (int rr = 0; rr < 2; rr++) {
                        const int j = r0 + 8 * rr;
                        if (j >= nk) continue;
                        float w0 = cc[2 * rr + 0] + b0;
                        float w1 = cc[2 * rr + 1] + b1;
                        if (c0 < 1024) {
                            __half h0 = __float2half_rn(w0), h1 = __float2half_rn(w1);
                            __half l0 = __float2half_rn(w0 - __half2float(h0));
                            __half l1 = __float2half_rn(w1 - __half2float(h1));
                            size_t idx = ((size_t)z * SEQ + j) * HD + c0;
                            *(__half2*)(g_kch + idx) = __halves2half2(h0, h1);
                            *(__half2*)(g_kcl + idx) = __halves2half2(l0, l1);
                        } else {
                            *(float2*)(g_v + ((size_t)z * SEQ + j) * HD + (c0 - 1024)) =
                                make_float2(w0, w1);
                        }
                    }
                }
            } else if constexpr (MODE == 1) {
                float* Cb = g_p + (size_t)z * SEQ * SEQ;
                *(float2*)(Cb + (size_t)r0 * SEQ + c0)       = make_float2(cc[0], cc[1]);
                *(float2*)(Cb + (size_t)(r0 + 8) * SEQ + c0) = make_float2(cc[2], cc[3]);
            } else {
                float* Cb = Cout + (size_t)z * SEQ * HD;
                *(float2*)(Cb + (size_t)r0 * HD + c0)        = make_float2(cc[0], cc[1]);
                *(float2*)(Cb + (size_t)(r0 + 8) * HD + c0)  = make_float2(cc[2], cc[3]);
            }
        }
    }
}

// ---------------- softmax over compact scores: g_p -> g_ph (fp16) ----------
__global__ __launch_bounds__(256)
void softmax_kernel()
{
    const int row = blockIdx.x;          // 0..8191
    const int b   = row >> 11;
    const int nk  = g_nk[b];
    const int nkp = g_nkpad[b];
    float* p = g_p + (size_t)row * SEQ;
    __half* ph = g_ph + (size_t)row * SEQ;
    const int tid = threadIdx.x;
    __shared__ float red[256];

    float mx = -CUDART_INF_F;
#pragma unroll
    for (int t = 0; t < 8; t++) {
        int j = tid + t * 256;
        if (j < nk) mx = fmaxf(mx, p[j]);
    }
    red[tid] = mx;
    __syncthreads();
    for (int s = 128; s > 0; s >>= 1) {
        if (tid < s) red[tid] = fmaxf(red[tid], red[tid + s]);
        __syncthreads();
    }
    mx = red[0];
    __syncthreads();

    float vals[8];
    float sm = 0.0f;
#pragma unroll
    for (int t = 0; t < 8; t++) {
        int j = tid + t * 256;
        float e = (j < nk) ? __expf(p[j] - mx) : 0.0f;
        vals[t] = e;
        sm += e;
    }
    red[tid] = sm;
    __syncthreads();
    for (int s = 128; s > 0; s >>= 1) {
        if (tid < s) red[tid] += red[tid + s];
        __syncthreads();
    }
    const float inv = 1.0f / red[0];
#pragma unroll
    for (int t = 0; t < 8; t++) {
        int j = tid + t * 256;
        if (j < nkp) ph[j] = __float2half_rn(vals[t] * inv);  // 0 in pad region
    }
}

// ---------------- launch ----------------
extern "C" void kernel_launch(void* const* d_in, const int* in_sizes, int n_in,
                              void* d_out, int out_size)
{
    const float* qkv  = (const float*)d_in[0];
    const void*  mask = d_in[1];
    const float* W    = (const float*)d_in[2];
    const float* bqkv = (const float*)d_in[3];
    float* out = (float*)d_out;

    cudaFuncSetAttribute(hmma_gemm<1>, cudaFuncAttributeMaxDynamicSharedMemorySize, SMEM_TOT);
    cudaFuncSetAttribute(hmma_gemm<2>, cudaFuncAttributeMaxDynamicSharedMemorySize, SMEM_TOT);
    cudaFuncSetAttribute(hmma_gemm<4>, cudaFuncAttributeMaxDynamicSharedMemorySize, SMEM_TOT);

    scan_mask_kernel<<<BATCH, 256>>>(mask);

    // split qkv input: fp32 -> fp16 hi/lo
    {
        __half *qh, *ql;
        cudaGetSymbolAddress((void**)&qh, g_qkvh);
        cudaGetSymbolAddress((void**)&ql, g_qkvl);
        int n4 = BATCH * SEQ * DIN / 4;
        split_kernel<<<(n4 + 255) / 256, 256>>>(qkv, qh, ql, n4);
    }
    // transpose + split W: [1024,3072] -> [3072,1024]
    {
        __half *wh, *wl;
        cudaGetSymbolAddress((void**)&wh, g_wth);
        cudaGetSymbolAddress((void**)&wl, g_wtl);
        dim3 grid(N3 / 32, DIN / 32, 1);
        transpose_split_kernel<<<grid, dim3(32, 8)>>>(W, wh, wl, DIN, N3);
    }
    // MERGED projections: q-proj (512 CTAs) + kv-proj (1024 CTAs), wave-packed
    hmma_gemm<4><<<1536, 128, SMEM_TOT>>>(bqkv, nullptr);

    zero_kc_pad_kernel<<<dim3(128, 1, BATCH), 256>>>();
    // transpose + split compacted V -> V^T
    {
        dim3 grid(DIN / 32, SEQ / 32, BATCH);
        transpose_split_v_kernel<<<grid, dim3(32, 8)>>>();
    }
    // GEMM2: scores = q @ kc^T (N limited to nkpad via early exit)
    {
        dim3 grid(SEQ / 128, SEQ / 128, BATCH);
        hmma_gemm<1><<<grid, 128, SMEM_TOT>>>(nullptr, nullptr);
    }
    softmax_kernel<<<BATCH * SEQ, 256>>>();
    // GEMM3: out = P_fp16 @ V_c split (K = nkpad dynamic, 2-pass)
    {
        dim3 grid(HD / 128, SEQ / 128, BATCH);
        hmma_gemm<2><<<grid, 128, SMEM_TOT>>>(nullptr, out);
    }
}

// round 11
// speedup vs baseline: 5.0145x; 1.0416x over previous
#include <cuda_runtime.h>
#include <cuda_fp16.h>
#include <math_constants.h>
#include <cstdint>

// Problem constants
#define BATCH 4
#define SEQ   2048
#define DIN   1024
#define HD    1024
#define N3    3072   // 3*HD

// ---------------- device scratch (no allocations allowed) ----------------
__device__ __align__(16) __half g_qkvh[BATCH * SEQ * DIN];
__device__ __align__(16) __half g_qkvl[BATCH * SEQ * DIN];
__device__ __align__(16) __half g_wth[N3 * DIN];
__device__ __align__(16) __half g_wtl[N3 * DIN];
__device__ __align__(16) __half g_qh[BATCH * SEQ * HD];
__device__ __align__(16) __half g_ql[BATCH * SEQ * HD];
__device__ __align__(16) __half g_kch[BATCH * SEQ * HD];   // compacted keys (split)
__device__ __align__(16) __half g_kcl[BATCH * SEQ * HD];
__device__ __align__(16) float  g_v[BATCH * SEQ * HD];     // compacted V (fp32 rows)
__device__ __align__(16) __half g_vth[BATCH * HD * SEQ];   // compacted V^T (fp16)
__device__ __align__(16) float  g_p[(size_t)BATCH * SEQ * SEQ];
__device__ __align__(16) __half g_ph[(size_t)BATCH * SEQ * SEQ];  // P as fp16
__device__ int g_srcidx[BATCH * SEQ];   // compact j -> original position (0 for j >= nk)
__device__ int g_nk[BATCH];
__device__ int g_nkpad[BATCH];          // ceil128(nk)

// ---------------- helpers ----------------
__device__ __forceinline__ uint32_t smem_u32(const void* p) {
    uint32_t a;
    asm("{ .reg .u64 t; cvta.to.shared.u64 t, %1; cvt.u32.u64 %0, t; }" : "=r"(a) : "l"(p));
    return a;
}
__device__ __forceinline__ void ldm4(uint32_t* r, uint32_t addr) {
    asm volatile("ldmatrix.sync.aligned.m8n8.x4.shared.b16 {%0,%1,%2,%3}, [%4];"
                 : "=r"(r[0]), "=r"(r[1]), "=r"(r[2]), "=r"(r[3]) : "r"(addr));
}
__device__ __forceinline__ void mma16816(float* c, const uint32_t* a,
                                         uint32_t b0, uint32_t b1) {
    asm volatile(
        "mma.sync.aligned.m16n8k16.row.col.f32.f16.f16.f32 "
        "{%0,%1,%2,%3}, {%4,%5,%6,%7}, {%8,%9}, {%0,%1,%2,%3};"
        : "+f"(c[0]), "+f"(c[1]), "+f"(c[2]), "+f"(c[3])
        : "r"(a[0]), "r"(a[1]), "r"(a[2]), "r"(a[3]), "r"(b0), "r"(b1));
}
__device__ __forceinline__ void cpa16(uint32_t dst, const void* src) {
    asm volatile("cp.async.cg.shared.global [%0], [%1], 16;" :: "r"(dst), "l"(src));
}
#define CP_COMMIT() asm volatile("cp.async.commit_group;" ::: "memory")
#define CP_WAIT(n)  asm volatile("cp.async.wait_group %0;" :: "n"(n) : "memory")

// ---------------- mask detect + normalize + compaction scan (fused) --------
__global__ __launch_bounds__(256)
void scan_mask_kernel(const void* mptr)
{
    const int b   = blockIdx.x;
    const int tid = threadIdx.x;
    __shared__ int sums[256];
    __shared__ int okInt, okFloat;
    if (tid == 0) { okInt = 1; okFloat = 1; }
    __syncthreads();
    const unsigned int* w = (const unsigned int*)mptr;
    for (int i = tid; i < 2048; i += 256) {
        unsigned int x = w[i];
        if (!(x == 0u || x == 1u))          okInt = 0;
        if (!(x == 0u || x == 0x3F800000u)) okFloat = 0;
    }
#pragma unroll
    for (int i = 0; i < 8; i++) g_srcidx[b * SEQ + tid * 8 + i] = 0;
    __syncthreads();
    const int flag = okInt ? 0 : (okFloat ? 1 : 2);

    int keep[8], loc[8];
    int s = 0;
#pragma unroll
    for (int i = 0; i < 8; i++) {
        const int gi = b * SEQ + tid * 8 + i;
        int m;
        if (flag == 0)      m = (((const int*)mptr)[gi] != 0);
        else if (flag == 1) m = (((const float*)mptr)[gi] != 0.0f);
        else                m = (((const unsigned char*)mptr)[gi] != 0);
        keep[i] = !m;
        loc[i]  = s;
        s += keep[i];
    }
    sums[tid] = s;
    __syncthreads();
    for (int d = 1; d < 256; d <<= 1) {
        int v = (tid >= d) ? sums[tid - d] : 0;
        __syncthreads();
        sums[tid] += v;
        __syncthreads();
    }
    const int offs = sums[tid] - s;
#pragma unroll
    for (int i = 0; i < 8; i++) {
        if (keep[i]) g_srcidx[b * SEQ + offs + loc[i]] = tid * 8 + i;
    }
    if (tid == 255) {
        const int total = sums[255];
        g_nk[b]    = total;
        g_nkpad[b] = (total + 127) & ~127;
    }
}

// zero the pad rows [nk, nkpad) of compacted K
__global__ __launch_bounds__(256)
void zero_kc_pad_kernel()
{
    const int b   = blockIdx.z;
    const int row = g_nk[b] + blockIdx.x;
    if (row >= g_nkpad[b]) return;
    const size_t idx = ((size_t)b * SEQ + row) * HD + threadIdx.x * 4;
    *(uint2*)(g_kch + idx) = make_uint2(0, 0);
    *(uint2*)(g_kcl + idx) = make_uint2(0, 0);
}

// ---------------- elementwise split: fp32 -> (hi, lo) fp16 ----------------
__global__ __launch_bounds__(256)
void split_kernel(const float* __restrict__ in, __half* __restrict__ oh,
                  __half* __restrict__ ol, int n4)
{
    int i = blockIdx.x * blockDim.x + threadIdx.x;
    if (i >= n4) return;
    float4 v = ((const float4*)in)[i];
    __half h0 = __float2half_rn(v.x), h1 = __float2half_rn(v.y);
    __half h2 = __float2half_rn(v.z), h3 = __float2half_rn(v.w);
    __half l0 = __float2half_rn(v.x - __half2float(h0));
    __half l1 = __float2half_rn(v.y - __half2float(h1));
    __half l2 = __float2half_rn(v.z - __half2float(h2));
    __half l3 = __float2half_rn(v.w - __half2float(h3));
    ((__half2*)oh)[2 * i]     = __halves2half2(h0, h1);
    ((__half2*)oh)[2 * i + 1] = __halves2half2(h2, h3);
    ((__half2*)ol)[2 * i]     = __halves2half2(l0, l1);
    ((__half2*)ol)[2 * i + 1] = __halves2half2(l2, l3);
}

// ---------------- transpose + split W ----------------
__global__ void transpose_split_kernel(const float* __restrict__ in,
                                       __half* __restrict__ oh, __half* __restrict__ ol,
                                       int R, int C)
{
    __shared__ float t[32][33];
    int bx = blockIdx.x * 32, by = blockIdx.y * 32;
    int x = threadIdx.x, y = threadIdx.y;
#pragma unroll
    for (int i = y; i < 32; i += 8) t[i][x] = in[(size_t)(by + i) * C + bx + x];
    __syncthreads();
#pragma unroll
    for (int i = y; i < 32; i += 8) {
        float w = t[x][i];
        __half h = __float2half_rn(w);
        size_t idx = (size_t)(bx + i) * R + by + x;
        oh[idx] = h;
        ol[idx] = __float2half_rn(w - __half2float(h));
    }
}

// ---- transpose compacted V to fp16: vt[h][j] = fp16(g_v[j][h]) for j<nk, else 0
__global__ void transpose_v_kernel()
{
    const int b = blockIdx.z;
    const float* in = g_v + (size_t)b * SEQ * HD;
    __half* oh = g_vth + (size_t)b * HD * SEQ;
    const int nk = g_nk[b];

    __shared__ float t[32][33];
    int bx = blockIdx.x * 32;   // head dim
    int by = blockIdx.y * 32;   // compact key dim
    int x = threadIdx.x, y = threadIdx.y;
#pragma unroll
    for (int i = y; i < 32; i += 8) {
        const int j = by + i;
        t[i][x] = (j < nk) ? in[(size_t)j * HD + bx + x] : 0.0f;
    }
    __syncthreads();
#pragma unroll
    for (int i = y; i < 32; i += 8)
        oh[(size_t)(bx + i) * SEQ + by + x] = __float2half_rn(t[x][i]);
}

// ---------------- fp16 split GEMM, CTA 128x128x32, warp 64x64, 2 CTA/SM ----
// MODE 4: MERGED projection launch (1536 linearized CTAs):
//   CTA [0,512):    q-proj  [3-pass]
//   CTA [512,1536): kv-proj; K-columns 3-pass, V-columns 2-pass (drop xl·Wh)
// MODE 1: q_split @ kc_split -> g_p                                  [3-pass]
// MODE 2: P fp16 @ vth fp16 -> out (K = nkpad dynamic)               [1-pass]
#define NSTAGE   3
#define ST_AH    0
#define ST_AL    8192
#define ST_BH    16384
#define ST_BL    24576
#define STAGE_SZ 32768
#define SMEM_TOT (NSTAGE * STAGE_SZ)   // 98304

template <int MODE>
__global__ __launch_bounds__(128, 2)
void hmma_gemm(const float* __restrict__ bias, float* __restrict__ Cout)
{
    constexpr int K = (MODE == 2) ? 2048 : 1024;   // k-extent == row stride
    constexpr bool BLO = (MODE != 2);              // B-lo pass (ah·bl)

    int z = blockIdx.z;
    int mBase, nBase;
    bool kv = false;
    if constexpr (MODE == 4) {
        const int bx = blockIdx.x;
        if (bx < 512) {                    // q-proj: N=1024 (8 tiles), M=8192 (64 tiles)
            nBase = (bx & 7) * 128;
            mBase = (bx >> 3) * 128;
            z = 0;
        } else {                           // kv-proj: N=2048 (16), M=2048 (16), B=4
            kv = true;
            const int b2 = bx - 512;
            nBase = (b2 & 15) * 128;
            const int rem = b2 >> 4;
            mBase = (rem & 15) * 128;
            z = rem >> 4;
            if (mBase >= g_nk[z]) return;
        }
    } else {
        nBase = blockIdx.x * 128;
        mBase = blockIdx.y * 128;
        if constexpr (MODE == 1) { if (nBase >= g_nkpad[z]) return; }
    }

    // A-lo pass (al·bh): MODE1 yes; MODE2 no; MODE4: q/K-cols yes, V-cols no.
    const bool alo = (MODE == 1) || (MODE == 4 && (!kv || nBase < 1024));

    int NT;
    if constexpr (MODE == 2) NT = g_nkpad[z] >> 5;
    else NT = 1024 / 32;

    extern __shared__ char smem[];
    const uint32_t sbase = smem_u32(smem);
    const int tid  = threadIdx.x;
    const int wid  = tid >> 5;       // 0..3
    const int lane = tid & 31;
    const int wm   = wid >> 1;       // 0..1
    const int wn   = wid & 1;        // 0..1

    const __half *Ah, *Al, *Bh, *Bl;
    if constexpr (MODE == 4) {
        if (!kv) {
            Ah = g_qkvh; Al = g_qkvl; Bh = g_wth; Bl = g_wtl;
        } else {
            Ah = g_qkvh + (size_t)z * SEQ * DIN; Al = g_qkvl + (size_t)z * SEQ * DIN;
            Bh = g_wth + (size_t)1024 * DIN;     Bl = g_wtl + (size_t)1024 * DIN;
        }
    } else if constexpr (MODE == 1) {
        Ah = g_qh  + (size_t)z * SEQ * HD; Al = g_ql  + (size_t)z * SEQ * HD;
        Bh = g_kch + (size_t)z * SEQ * HD; Bl = g_kcl + (size_t)z * SEQ * HD;
    } else {
        Ah = g_ph  + (size_t)z * SEQ * SEQ; Al = Ah;
        Bh = g_vth + (size_t)z * HD * SEQ;  Bl = Bh;   // unused in MODE 2
    }

    // ---- cp.async loader state: 128 threads, 32 rows/pass, 4 passes/tile ----
    const int lrow = tid >> 2;                       // 0..31
    const int lc   = tid & 3;                        // 16B chunk in 64B row
    const uint32_t swc = (uint32_t)((lc ^ ((lrow >> 1) & 3)) << 4);
    const uint32_t dA0 = (uint32_t)lrow * 64 + swc;  // pass i adds i*2048 (32 rows)
    const __half *pAh[4], *pAl[4], *pBh[4], *pBl[4];
#pragma unroll
    for (int i = 0; i < 4; i++) {
        int ar = mBase + lrow + i * 32;
        if constexpr (MODE == 4) { if (kv) ar = g_srcidx[z * SEQ + ar]; }
        pAh[i] = Ah + (size_t)ar * K + lc * 8;
        pAl[i] = Al + (size_t)ar * K + lc * 8;
        pBh[i] = Bh + (size_t)(nBase + lrow + i * 32) * K + lc * 8;
        pBl[i] = Bl + (size_t)(nBase + lrow + i * 32) * K + lc * 8;
    }

    // ---- ldmatrix fragment addressing ----
    const int roff = (lane & 7) + ((lane >> 3) & 1) * 8;
    const int cq   = lane >> 4;
    const int xr   = (roff >> 1) & 3;
    const uint32_t abase = (uint32_t)(wm * 64 + roff) * 64;
    const uint32_t bbase = (uint32_t)(wn * 64 + roff) * 64;
    uint32_t kcofs[2];
    kcofs[0] = (uint32_t)((cq ^ xr) << 4);
    kcofs[1] = (uint32_t)(((2 + cq) ^ xr) << 4);

    float acc[4][8][4] = {};

#pragma unroll
    for (int s = 0; s < NSTAGE - 1; s++) {
        const uint32_t sb = sbase + s * STAGE_SZ;
#pragma unroll
        for (int i = 0; i < 4; i++) {
            cpa16(sb + ST_AH + dA0 + i * 2048, pAh[i]);
            if (alo) cpa16(sb + ST_AL + dA0 + i * 2048, pAl[i]);
            cpa16(sb + ST_BH + dA0 + i * 2048, pBh[i]);
            if constexpr (BLO) cpa16(sb + ST_BL + dA0 + i * 2048, pBl[i]);
            pAh[i] += 32; pAl[i] += 32; pBh[i] += 32; pBl[i] += 32;
        }
        CP_COMMIT();
    }

    for (int kt = 0; kt < NT; kt++) {
        CP_WAIT(NSTAGE - 2);
        __syncthreads();

        if (kt + NSTAGE - 1 < NT) {
            const uint32_t sb = sbase + ((kt + NSTAGE - 1) % NSTAGE) * STAGE_SZ;
#pragma unroll
            for (int i = 0; i < 4; i++) {
                cpa16(sb + ST_AH + dA0 + i * 2048, pAh[i]);
                if (alo) cpa16(sb + ST_AL + dA0 + i * 2048, pAl[i]);
                cpa16(sb + ST_BH + dA0 + i * 2048, pBh[i]);
                if constexpr (BLO) cpa16(sb + ST_BL + dA0 + i * 2048, pBl[i]);
                pAh[i] += 32; pAl[i] += 32; pBh[i] += 32; pBl[i] += 32;
            }
        }
        CP_COMMIT();

        const uint32_t stb = sbase + (kt % NSTAGE) * STAGE_SZ;
#pragma unroll
        for (int ks = 0; ks < 2; ks++) {
            uint32_t ah[4][4], al[4][4], bh[4][4], bl[4][4];
#pragma unroll
            for (int mt = 0; mt < 4; mt++) {
                ldm4(ah[mt], stb + ST_AH + abase + mt * 1024 + kcofs[ks]);
                if (alo) ldm4(al[mt], stb + ST_AL + abase + mt * 1024 + kcofs[ks]);
            }
#pragma unroll
            for (int ng = 0; ng < 4; ng++) {
                ldm4(bh[ng], stb + ST_BH + bbase + ng * 1024 + kcofs[ks]);
                if constexpr (BLO) ldm4(bl[ng], stb + ST_BL + bbase + ng * 1024 + kcofs[ks]);
            }
#pragma unroll
            for (int mt = 0; mt < 4; mt++)
#pragma unroll
                for (int ng = 0; ng < 4; ng++)
#pragma unroll
                    for (int nb = 0; nb < 2; nb++)
                        mma16816(acc[mt][ng * 2 + nb], ah[mt], bh[ng][nb], bh[ng][nb + 2]);
            if constexpr (BLO) {
#pragma unroll
                for (int mt = 0; mt < 4; mt++)
#pragma unroll
                    for (int ng = 0; ng < 4; ng++)
#pragma unroll
                        for (int nb = 0; nb < 2; nb++)
                            mma16816(acc[mt][ng * 2 + nb], ah[mt], bl[ng][nb], bl[ng][nb + 2]);
            }
            if (alo) {
#pragma unroll
                for (int mt = 0; mt < 4; mt++)
#pragma unroll
                    for (int ng = 0; ng < 4; ng++)
#pragma unroll
                        for (int nb = 0; nb < 2; nb++)
                            mma16816(acc[mt][ng * 2 + nb], al[mt], bh[ng][nb], bh[ng][nb + 2]);
            }
        }
    }

    // ---------------- epilogue ----------------
    const int rl = lane >> 2;
    const int cl = 2 * (lane & 3);
#pragma unroll
    for (int mt = 0; mt < 4; mt++) {
#pragma unroll
        for (int nt = 0; nt < 8; nt++) {
            const int r0 = mBase + wm * 64 + mt * 16 + rl;
            const int c0 = nBase + wn * 64 + nt * 8 + cl;
            float* cc = acc[mt][nt];
            if constexpr (MODE == 4) {
                if (!kv) {
                    const float b0 = bias[c0], b1 = bias[c0 + 1];
#pragma unroll
                    for (int rr = 0; rr < 2; rr++) {
                        float w0 = (cc[2 * rr + 0] + b0) * 32.0f;
                        float w1 = (cc[2 * rr + 1] + b1) * 32.0f;
                        __half h0 = __float2half_rn(w0), h1 = __float2half_rn(w1);
                        __half l0 = __float2half_rn(w0 - __half2float(h0));
                        __half l1 = __float2half_rn(w1 - __half2float(h1));
                        size_t idx = (size_t)(r0 + 8 * rr) * HD + c0;
                        *(__half2*)(g_qh + idx) = __halves2half2(h0, h1);
                        *(__half2*)(g_ql + idx) = __halves2half2(l0, l1);
                    }
                } else {
                    const int nk = g_nk[z];
                    const float b0 = bias[1024 + c0], b1 = bias[1024 + c0 + 1];
#pragma unroll
                    for (int rr = 0; rr < 2; rr++) {
                        const int j = r0 + 8 * rr;
                        if (j >= nk) continue;
                        float w0 = cc[2 * rr + 0] + b0;
                        float w1 = cc[2 * rr + 1] + b1;
                        if (c0 < 1024) {
                            __half h0 = __float2half_rn(w0), h1 = __float2half_rn(w1);
                            __half l0 = __float2half_rn(w0 - __half2float(h0));
                            __half l1 = __float2half_rn(w1 - __half2float(h1));
                            size_t idx = ((size_t)z * SEQ + j) * HD + c0;
                            *(__half2*)(g_kch + idx) = __halves2half2(h0, h1);
                            *(__half2*)(g_kcl + idx) = __halves2half2(l0, l1);
                        } else {
                            *(float2*)(g_v + ((size_t)z * SEQ + j) * HD + (c0 - 1024)) =
                                make_float2(w0, w1);
                        }
                    }
                }
            } else if constexpr (MODE == 1) {
                float* Cb = g_p + (size_t)z * SEQ * SEQ;
                *(float2*)(Cb + (size_t)r0 * SEQ + c0)       = make_float2(cc[0], cc[1]);
                *(float2*)(Cb + (size_t)(r0 + 8) * SEQ + c0) = make_float2(cc[2], cc[3]);
            } else {
                float* Cb = Cout + (size_t)z * SEQ * HD;
                *(float2*)(Cb + (size_t)r0 * HD + c0)        = make_float2(cc[0], cc[1]);
                *(float2*)(Cb + (size_t)(r0 + 8) * HD + c0)  = make_float2(cc[2], cc[3]);
            }
        }
    }
}

// ---------------- softmax over compact scores: g_p -> g_ph (fp16) ----------
__global__ __launch_bounds__(256)
void softmax_kernel()
{
    const int row = blockIdx.x;          // 0..8191
    const int b   = row >> 11;
    const int nk  = g_nk[b];
    const int nkp = g_nkpad[b];
    float* p = g_p + (size_t)row * SEQ;
    __half* ph = g_ph + (size_t)row * SEQ;
    const int tid = threadIdx.x;
    __shared__ float red[256];

    float mx = -CUDART_INF_F;
#pragma unroll
    for (int t = 0; t < 8; t++) {
        int j = tid + t * 256;
        if (j < nk) mx = fmaxf(mx, p[j]);
    }
    red[tid] = mx;
    __syncthreads();
    for (int s = 128; s > 0; s >>= 1) {
        if (tid < s) red[tid] = fmaxf(red[tid], red[tid + s]);
        __syncthreads();
    }
    mx = red[0];
    __syncthreads();

    float vals[8];
    float sm = 0.0f;
#pragma unroll
    for (int t = 0; t < 8; t++) {
        int j = tid + t * 256;
        float e = (j < nk) ? __expf(p[j] - mx) : 0.0f;
        vals[t] = e;
        sm += e;
    }
    red[tid] = sm;
    __syncthreads();
    for (int s = 128; s > 0; s >>= 1) {
        if (tid < s) red[tid] += red[tid + s];
        __syncthreads();
    }
    const float inv = 1.0f / red[0];
#pragma unroll
    for (int t = 0; t < 8; t++) {
        int j = tid + t * 256;
        if (j < nkp) ph[j] = __float2half_rn(vals[t] * inv);  // 0 in pad region
    }
}

// ---------------- launch ----------------
extern "C" void kernel_launch(void* const* d_in, const int* in_sizes, int n_in,
                              void* d_out, int out_size)
{
    const float* qkv  = (const float*)d_in[0];
    const void*  mask = d_in[1];
    const float* W    = (const float*)d_in[2];
    const float* bqkv = (const float*)d_in[3];
    float* out = (float*)d_out;

    cudaFuncSetAttribute(hmma_gemm<1>, cudaFuncAttributeMaxDynamicSharedMemorySize, SMEM_TOT);
    cudaFuncSetAttribute(hmma_gemm<2>, cudaFuncAttributeMaxDynamicSharedMemorySize, SMEM_TOT);
    cudaFuncSetAttribute(hmma_gemm<4>, cudaFuncAttributeMaxDynamicSharedMemorySize, SMEM_TOT);

    scan_mask_kernel<<<BATCH, 256>>>(mask);

    // split qkv input: fp32 -> fp16 hi/lo
    {
        __half *qh, *ql;
        cudaGetSymbolAddress((void**)&qh, g_qkvh);
        cudaGetSymbolAddress((void**)&ql, g_qkvl);
        int n4 = BATCH * SEQ * DIN / 4;
        split_kernel<<<(n4 + 255) / 256, 256>>>(qkv, qh, ql, n4);
    }
    // transpose + split W: [1024,3072] -> [3072,1024]
    {
        __half *wh, *wl;
        cudaGetSymbolAddress((void**)&wh, g_wth);
        cudaGetSymbolAddress((void**)&wl, g_wtl);
        dim3 grid(N3 / 32, DIN / 32, 1);
        transpose_split_kernel<<<grid, dim3(32, 8)>>>(W, wh, wl, DIN, N3);
    }
    // MERGED projections: q-proj (512 CTAs) + kv-proj (1024 CTAs), wave-packed
    hmma_gemm<4><<<1536, 128, SMEM_TOT>>>(bqkv, nullptr);

    zero_kc_pad_kernel<<<dim3(128, 1, BATCH), 256>>>();
    // transpose compacted V -> V^T fp16
    {
        dim3 grid(DIN / 32, SEQ / 32, BATCH);
        transpose_v_kernel<<<grid, dim3(32, 8)>>>();
    }
    // GEMM2: scores = q @ kc^T (N limited to nkpad via early exit)
    {
        dim3 grid(SEQ / 128, SEQ / 128, BATCH);
        hmma_gemm<1><<<grid, 128, SMEM_TOT>>>(nullptr, nullptr);
    }
    softmax_kernel<<<BATCH * SEQ, 256>>>();
    // GEMM3: out = P_fp16 @ V^T fp16 (K = nkpad dynamic, 1-pass)
    {
        dim3 grid(HD / 128, SEQ / 128, BATCH);
        hmma_gemm<2><<<grid, 128, SMEM_TOT>>>(nullptr, out);
    }
}

// round 12
// speedup vs baseline: 5.0716x; 1.0114x over previous
#include <cuda_runtime.h>
#include <cuda_fp16.h>
#include <math_constants.h>
#include <cstdint>

// Problem constants
#define BATCH 4
#define SEQ   2048
#define DIN   1024
#define HD    1024
#define N3    3072   // 3*HD

// ---------------- device scratch (no allocations allowed) ----------------
__device__ __align__(16) __half g_qkvh[BATCH * SEQ * DIN];
__device__ __align__(16) __half g_qkvl[BATCH * SEQ * DIN];
__device__ __align__(16) __half g_wth[N3 * DIN];
__device__ __align__(16) __half g_wtl[N3 * DIN];
__device__ __align__(16) __half g_qh[BATCH * SEQ * HD];
__device__ __align__(16) __half g_ql[BATCH * SEQ * HD];
__device__ __align__(16) __half g_kch[BATCH * SEQ * HD];   // compacted keys (split)
__device__ __align__(16) __half g_kcl[BATCH * SEQ * HD];
__device__ __align__(16) float  g_v[BATCH * SEQ * HD];     // compacted V (fp32 rows)
__device__ __align__(16) __half g_vth[BATCH * HD * SEQ];   // compacted V^T (fp16)
__device__ __align__(16) float  g_p[(size_t)BATCH * SEQ * SEQ];
__device__ __align__(16) __half g_ph[(size_t)BATCH * SEQ * SEQ];  // P as fp16
__device__ int g_srcidx[BATCH * SEQ];   // compact j -> original position (0 for j >= nk)
__device__ int g_nk[BATCH];
__device__ int g_nkpad[BATCH];          // ceil128(nk)

// ---------------- helpers ----------------
__device__ __forceinline__ uint32_t smem_u32(const void* p) {
    uint32_t a;
    asm("{ .reg .u64 t; cvta.to.shared.u64 t, %1; cvt.u32.u64 %0, t; }" : "=r"(a) : "l"(p));
    return a;
}
__device__ __forceinline__ void ldm4(uint32_t* r, uint32_t addr) {
    asm volatile("ldmatrix.sync.aligned.m8n8.x4.shared.b16 {%0,%1,%2,%3}, [%4];"
                 : "=r"(r[0]), "=r"(r[1]), "=r"(r[2]), "=r"(r[3]) : "r"(addr));
}
__device__ __forceinline__ void mma16816(float* c, const uint32_t* a,
                                         uint32_t b0, uint32_t b1) {
    asm volatile(
        "mma.sync.aligned.m16n8k16.row.col.f32.f16.f16.f32 "
        "{%0,%1,%2,%3}, {%4,%5,%6,%7}, {%8,%9}, {%0,%1,%2,%3};"
        : "+f"(c[0]), "+f"(c[1]), "+f"(c[2]), "+f"(c[3])
        : "r"(a[0]), "r"(a[1]), "r"(a[2]), "r"(a[3]), "r"(b0), "r"(b1));
}
__device__ __forceinline__ void cpa16(uint32_t dst, const void* src) {
    asm volatile("cp.async.cg.shared.global [%0], [%1], 16;" :: "r"(dst), "l"(src));
}
#define CP_COMMIT() asm volatile("cp.async.commit_group;" ::: "memory")
#define CP_WAIT(n)  asm volatile("cp.async.wait_group %0;" :: "n"(n) : "memory")

// ---------------- mask detect + normalize + compaction scan (fused) --------
__global__ __launch_bounds__(256)
void scan_mask_kernel(const void* mptr)
{
    const int b   = blockIdx.x;
    const int tid = threadIdx.x;
    __shared__ int sums[256];
    __shared__ int okInt, okFloat;
    if (tid == 0) { okInt = 1; okFloat = 1; }
    __syncthreads();
    const unsigned int* w = (const unsigned int*)mptr;
    for (int i = tid; i < 2048; i += 256) {
        unsigned int x = w[i];
        if (!(x == 0u || x == 1u))          okInt = 0;
        if (!(x == 0u || x == 0x3F800000u)) okFloat = 0;
    }
#pragma unroll
    for (int i = 0; i < 8; i++) g_srcidx[b * SEQ + tid * 8 + i] = 0;
    __syncthreads();
    const int flag = okInt ? 0 : (okFloat ? 1 : 2);

    int keep[8], loc[8];
    int s = 0;
#pragma unroll
    for (int i = 0; i < 8; i++) {
        const int gi = b * SEQ + tid * 8 + i;
        int m;
        if (flag == 0)      m = (((const int*)mptr)[gi] != 0);
        else if (flag == 1) m = (((const float*)mptr)[gi] != 0.0f);
        else                m = (((const unsigned char*)mptr)[gi] != 0);
        keep[i] = !m;
        loc[i]  = s;
        s += keep[i];
    }
    sums[tid] = s;
    __syncthreads();
    for (int d = 1; d < 256; d <<= 1) {
        int v = (tid >= d) ? sums[tid - d] : 0;
        __syncthreads();
        sums[tid] += v;
        __syncthreads();
    }
    const int offs = sums[tid] - s;
#pragma unroll
    for (int i = 0; i < 8; i++) {
        if (keep[i]) g_srcidx[b * SEQ + offs + loc[i]] = tid * 8 + i;
    }
    if (tid == 255) {
        const int total = sums[255];
        g_nk[b]    = total;
        g_nkpad[b] = (total + 127) & ~127;
    }
}

// zero the pad rows [nk, nkpad) of compacted K
__global__ __launch_bounds__(256)
void zero_kc_pad_kernel()
{
    const int b   = blockIdx.z;
    const int row = g_nk[b] + blockIdx.x;
    if (row >= g_nkpad[b]) return;
    const size_t idx = ((size_t)b * SEQ + row) * HD + threadIdx.x * 4;
    *(uint2*)(g_kch + idx) = make_uint2(0, 0);
    *(uint2*)(g_kcl + idx) = make_uint2(0, 0);
}

// ---------------- elementwise split: fp32 -> (hi, lo) fp16 ----------------
__global__ __launch_bounds__(256)
void split_kernel(const float* __restrict__ in, __half* __restrict__ oh,
                  __half* __restrict__ ol, int n4)
{
    int i = blockIdx.x * blockDim.x + threadIdx.x;
    if (i >= n4) return;
    float4 v = ((const float4*)in)[i];
    __half h0 = __float2half_rn(v.x), h1 = __float2half_rn(v.y);
    __half h2 = __float2half_rn(v.z), h3 = __float2half_rn(v.w);
    __half l0 = __float2half_rn(v.x - __half2float(h0));
    __half l1 = __float2half_rn(v.y - __half2float(h1));
    __half l2 = __float2half_rn(v.z - __half2float(h2));
    __half l3 = __float2half_rn(v.w - __half2float(h3));
    ((__half2*)oh)[2 * i]     = __halves2half2(h0, h1);
    ((__half2*)oh)[2 * i + 1] = __halves2half2(h2, h3);
    ((__half2*)ol)[2 * i]     = __halves2half2(l0, l1);
    ((__half2*)ol)[2 * i + 1] = __halves2half2(l2, l3);
}

// ---------------- transpose + split W ----------------
__global__ void transpose_split_kernel(const float* __restrict__ in,
                                       __half* __restrict__ oh, __half* __restrict__ ol,
                                       int R, int C)
{
    __shared__ float t[32][33];
    int bx = blockIdx.x * 32, by = blockIdx.y * 32;
    int x = threadIdx.x, y = threadIdx.y;
#pragma unroll
    for (int i = y; i < 32; i += 8) t[i][x] = in[(size_t)(by + i) * C + bx + x];
    __syncthreads();
#pragma unroll
    for (int i = y; i < 32; i += 8) {
        float w = t[x][i];
        __half h = __float2half_rn(w);
        size_t idx = (size_t)(bx + i) * R + by + x;
        oh[idx] = h;
        ol[idx] = __float2half_rn(w - __half2float(h));
    }
}

// ---- transpose compacted V to fp16: vt[h][j] = fp16(g_v[j][h]) for j<nk, else 0
__global__ void transpose_v_kernel()
{
    const int b = blockIdx.z;
    const float* in = g_v + (size_t)b * SEQ * HD;
    __half* oh = g_vth + (size_t)b * HD * SEQ;
    const int nk = g_nk[b];

    __shared__ float t[32][33];
    int bx = blockIdx.x * 32;   // head dim
    int by = blockIdx.y * 32;   // compact key dim
    int x = threadIdx.x, y = threadIdx.y;
#pragma unroll
    for (int i = y; i < 32; i += 8) {
        const int j = by + i;
        t[i][x] = (j < nk) ? in[(size_t)j * HD + bx + x] : 0.0f;
    }
    __syncthreads();
#pragma unroll
    for (int i = y; i < 32; i += 8)
        oh[(size_t)(bx + i) * SEQ + by + x] = __float2half_rn(t[x][i]);
}

// ---------------- GEMM core: prologue + pipelined mainloop -----------------
#define NSTAGE   3
#define ST_AH    0
#define ST_AL    8192
#define ST_BH    16384
#define ST_BL    24576
#define STAGE_SZ 32768
#define SMEM_TOT (NSTAGE * STAGE_SZ)   // 98304

template <bool ALO, bool BLO>
__device__ __forceinline__ void gemm_core(
    float (&acc)[4][8][4], int NT,
    const __half* pAh0, const __half* pAl0,
    const __half* pBh0, const __half* pBl0,
    const int arow[4], int K,
    uint32_t sbase, uint32_t dA0, int lc,
    uint32_t abase, uint32_t bbase, const uint32_t kcofs[2])
{
    const __half *pAh[4], *pAl[4], *pBh[4], *pBl[4];
#pragma unroll
    for (int i = 0; i < 4; i++) {
        pAh[i] = pAh0 + (size_t)arow[i] * K + lc * 8;
        if (ALO) pAl[i] = pAl0 + (size_t)arow[i] * K + lc * 8;
        pBh[i] = pBh0 + (size_t)i * 32 * K;
        if (BLO) pBl[i] = pBl0 + (size_t)i * 32 * K;
    }

#pragma unroll
    for (int s = 0; s < NSTAGE - 1; s++) {
        const uint32_t sb = sbase + s * STAGE_SZ;
#pragma unroll
        for (int i = 0; i < 4; i++) {
            cpa16(sb + ST_AH + dA0 + i * 2048, pAh[i]);
            if (ALO) { cpa16(sb + ST_AL + dA0 + i * 2048, pAl[i]); pAl[i] += 32; }
            cpa16(sb + ST_BH + dA0 + i * 2048, pBh[i]);
            if (BLO) { cpa16(sb + ST_BL + dA0 + i * 2048, pBl[i]); pBl[i] += 32; }
            pAh[i] += 32; pBh[i] += 32;
        }
        CP_COMMIT();
    }

    for (int kt = 0; kt < NT; kt++) {
        CP_WAIT(NSTAGE - 2);
        __syncthreads();

        if (kt + NSTAGE - 1 < NT) {
            const uint32_t sb = sbase + ((kt + NSTAGE - 1) % NSTAGE) * STAGE_SZ;
#pragma unroll
            for (int i = 0; i < 4; i++) {
                cpa16(sb + ST_AH + dA0 + i * 2048, pAh[i]);
                if (ALO) { cpa16(sb + ST_AL + dA0 + i * 2048, pAl[i]); pAl[i] += 32; }
                cpa16(sb + ST_BH + dA0 + i * 2048, pBh[i]);
                if (BLO) { cpa16(sb + ST_BL + dA0 + i * 2048, pBl[i]); pBl[i] += 32; }
                pAh[i] += 32; pBh[i] += 32;
            }
        }
        CP_COMMIT();

        const uint32_t stb = sbase + (kt % NSTAGE) * STAGE_SZ;
#pragma unroll
        for (int ks = 0; ks < 2; ks++) {
            uint32_t ah[4][4], al[4][4], bh[4][4], bl[4][4];
#pragma unroll
            for (int mt = 0; mt < 4; mt++) {
                ldm4(ah[mt], stb + ST_AH + abase + mt * 1024 + kcofs[ks]);
                if (ALO) ldm4(al[mt], stb + ST_AL + abase + mt * 1024 + kcofs[ks]);
            }
#pragma unroll
            for (int ng = 0; ng < 4; ng++) {
                ldm4(bh[ng], stb + ST_BH + bbase + ng * 1024 + kcofs[ks]);
                if (BLO) ldm4(bl[ng], stb + ST_BL + bbase + ng * 1024 + kcofs[ks]);
            }
#pragma unroll
            for (int mt = 0; mt < 4; mt++)
#pragma unroll
                for (int ng = 0; ng < 4; ng++)
#pragma unroll
                    for (int nb = 0; nb < 2; nb++)
                        mma16816(acc[mt][ng * 2 + nb], ah[mt], bh[ng][nb], bh[ng][nb + 2]);
            if (BLO) {
#pragma unroll
                for (int mt = 0; mt < 4; mt++)
#pragma unroll
                    for (int ng = 0; ng < 4; ng++)
#pragma unroll
                        for (int nb = 0; nb < 2; nb++)
                            mma16816(acc[mt][ng * 2 + nb], ah[mt], bl[ng][nb], bl[ng][nb + 2]);
            }
            if (ALO) {
#pragma unroll
                for (int mt = 0; mt < 4; mt++)
#pragma unroll
                    for (int ng = 0; ng < 4; ng++)
#pragma unroll
                        for (int nb = 0; nb < 2; nb++)
                            mma16816(acc[mt][ng * 2 + nb], al[mt], bh[ng][nb], bh[ng][nb + 2]);
            }
        }
    }
}

// ---------------- fp16 split GEMM kernels, CTA 128x128x32, 2 CTA/SM --------
// MODE 4: MERGED projection launch (1536 linearized CTAs):
//   CTA [0,512):    q-proj  [3-pass]
//   CTA [512,1536): kv-proj; K-columns 3-pass, V-columns 2-pass (drop xl·Wh)
// MODE 1: q_split @ kc_split -> g_p                                  [3-pass]
// MODE 2: P fp16 @ vth fp16 -> out (K = nkpad dynamic)               [1-pass]
template <int MODE>
__global__ __launch_bounds__(128, 2)
void hmma_gemm(const float* __restrict__ bias, float* __restrict__ Cout)
{
    constexpr int K = (MODE == 2) ? 2048 : 1024;

    int z = blockIdx.z;
    int mBase, nBase;
    bool kv = false;
    if constexpr (MODE == 4) {
        const int bx = blockIdx.x;
        if (bx < 512) {                    // q-proj: N=1024 (8 tiles), M=8192 (64 tiles)
            nBase = (bx & 7) * 128;
            mBase = (bx >> 3) * 128;
            z = 0;
        } else {                           // kv-proj: N=2048 (16), M=2048 (16), B=4
            kv = true;
            const int b2 = bx - 512;
            nBase = (b2 & 15) * 128;
            const int rem = b2 >> 4;
            mBase = (rem & 15) * 128;
            z = rem >> 4;
            if (mBase >= g_nk[z]) return;
        }
    } else {
        nBase = blockIdx.x * 128;
        mBase = blockIdx.y * 128;
        if constexpr (MODE == 1) { if (nBase >= g_nkpad[z]) return; }
    }

    int NT;
    if constexpr (MODE == 2) NT = g_nkpad[z] >> 5;
    else NT = 1024 / 32;

    extern __shared__ char smem[];
    const uint32_t sbase = smem_u32(smem);
    const int tid  = threadIdx.x;
    const int wid  = tid >> 5;       // 0..3
    const int lane = tid & 31;
    const int wm   = wid >> 1;       // 0..1
    const int wn   = wid & 1;        // 0..1

    const __half *Ah, *Al, *Bh, *Bl;
    if constexpr (MODE == 4) {
        if (!kv) {
            Ah = g_qkvh; Al = g_qkvl; Bh = g_wth; Bl = g_wtl;
        } else {
            Ah = g_qkvh + (size_t)z * SEQ * DIN; Al = g_qkvl + (size_t)z * SEQ * DIN;
            Bh = g_wth + (size_t)1024 * DIN;     Bl = g_wtl + (size_t)1024 * DIN;
        }
    } else if constexpr (MODE == 1) {
        Ah = g_qh  + (size_t)z * SEQ * HD; Al = g_ql  + (size_t)z * SEQ * HD;
        Bh = g_kch + (size_t)z * SEQ * HD; Bl = g_kcl + (size_t)z * SEQ * HD;
    } else {
        Ah = g_ph  + (size_t)z * SEQ * SEQ; Al = Ah;
        Bh = g_vth + (size_t)z * HD * SEQ;  Bl = Bh;
    }

    // ---- loader / fragment state ----
    const int lrow = tid >> 2;                       // 0..31
    const int lc   = tid & 3;
    const uint32_t swc = (uint32_t)((lc ^ ((lrow >> 1) & 3)) << 4);
    const uint32_t dA0 = (uint32_t)lrow * 64 + swc;
    int arow[4];
#pragma unroll
    for (int i = 0; i < 4; i++) {
        int ar = mBase + lrow + i * 32;
        if constexpr (MODE == 4) { if (kv) ar = g_srcidx[z * SEQ + ar]; }
        arow[i] = ar;
    }
    const __half* pBh0 = Bh + (size_t)(nBase + lrow) * K + lc * 8;
    const __half* pBl0 = Bl + (size_t)(nBase + lrow) * K + lc * 8;

    const int roff = (lane & 7) + ((lane >> 3) & 1) * 8;
    const int cq   = lane >> 4;
    const int xr   = (roff >> 1) & 3;
    const uint32_t abase = (uint32_t)(wm * 64 + roff) * 64;
    const uint32_t bbase = (uint32_t)(wn * 64 + roff) * 64;
    uint32_t kcofs[2];
    kcofs[0] = (uint32_t)((cq ^ xr) << 4);
    kcofs[1] = (uint32_t)(((2 + cq) ^ xr) << 4);

    float acc[4][8][4] = {};

    if constexpr (MODE == 4) {
        const bool alo = (!kv || nBase < 1024);   // CTA-uniform
        if (alo)
            gemm_core<true, true>(acc, NT, Ah, Al, pBh0, pBl0, arow, K,
                                  sbase, dA0, lc, abase, bbase, kcofs);
        else
            gemm_core<false, true>(acc, NT, Ah, Al, pBh0, pBl0, arow, K,
                                   sbase, dA0, lc, abase, bbase, kcofs);
    } else if constexpr (MODE == 1) {
        gemm_core<true, true>(acc, NT, Ah, Al, pBh0, pBl0, arow, K,
                              sbase, dA0, lc, abase, bbase, kcofs);
    } else {
        gemm_core<false, false>(acc, NT, Ah, Al, pBh0, pBl0, arow, K,
                                sbase, dA0, lc, abase, bbase, kcofs);
    }

    // ---------------- epilogue ----------------
    const int rl = lane >> 2;
    const int cl = 2 * (lane & 3);
#pragma unroll
    for (int mt = 0; mt < 4; mt++) {
#pragma unroll
        for (int nt = 0; nt < 8; nt++) {
            const int r0 = mBase + wm * 64 + mt * 16 + rl;
            const int c0 = nBase + wn * 64 + nt * 8 + cl;
            float* cc = acc[mt][nt];
            if constexpr (MODE == 4) {
                if (!kv) {
                    const float b0 = bias[c0], b1 = bias[c0 + 1];
#pragma unroll
                    for (int rr = 0; rr < 2; rr++) {
                        float w0 = (cc[2 * rr + 0] + b0) * 32.0f;
                        float w1 = (cc[2 * rr + 1] + b1) * 32.0f;
                        __half h0 = __float2half_rn(w0), h1 = __float2half_rn(w1);
                        __half l0 = __float2half_rn(w0 - __half2float(h0));
                        __half l1 = __float2half_rn(w1 - __half2float(h1));
                        size_t idx = (size_t)(r0 + 8 * rr) * HD + c0;
                        *(__half2*)(g_qh + idx) = __halves2half2(h0, h1);
                        *(__half2*)(g_ql + idx) = __halves2half2(l0, l1);
                    }
                } else {
                    const int nk = g_nk[z];
                    const float b0 = bias[1024 + c0], b1 = bias[1024 + c0 + 1];
#pragma unroll
                    for (int rr = 0; rr < 2; rr++) {
                        const int j = r0 + 8 * rr;
                        if (j >= nk) continue;
                        float w0 = cc[2 * rr + 0] + b0;
                        float w1 = cc[2 * rr + 1] + b1;
                        if (c0 < 1024) {
                            __half h0 = __float2half_rn(w0), h1 = __float2half_rn(w1);
                            __half l0 = __float2half_rn(w0 - __half2float(h0));
                            __half l1 = __float2half_rn(w1 - __half2float(h1));
                            size_t idx = ((size_t)z * SEQ + j) * HD + c0;
                            *(__half2*)(g_kch + idx) = __halves2half2(h0, h1);
                            *(__half2*)(g_kcl + idx) = __halves2half2(l0, l1);
                        } else {
                            *(float2*)(g_v + ((size_t)z * SEQ + j) * HD + (c0 - 1024)) =
                                make_float2(w0, w1);
                        }
                    }
                }
            } else if constexpr (MODE == 1) {
                float* Cb = g_p + (size_t)z * SEQ * SEQ;
                *(float2*)(Cb + (size_t)r0 * SEQ + c0)       = make_float2(cc[0], cc[1]);
                *(float2*)(Cb + (size_t)(r0 + 8) * SEQ + c0) = make_float2(cc[2], cc[3]);
            } else {
                float* Cb = Cout + (size_t)z * SEQ * HD;
                *(float2*)(Cb + (size_t)r0 * HD + c0)        = make_float2(cc[0], cc[1]);
                *(float2*)(Cb + (size_t)(r0 + 8) * HD + c0)  = make_float2(cc[2], cc[3]);
            }
        }
    }
}

// ---------------- softmax over compact scores: g_p -> g_ph (fp16) ----------
__global__ __launch_bounds__(256)
void softmax_kernel()
{
    const int row = blockIdx.x;          // 0..8191
    const int b   = row >> 11;
    const int nk  = g_nk[b];
    const int nkp = g_nkpad[b];
    float* p = g_p + (size_t)row * SEQ;
    __half* ph = g_ph + (size_t)row * SEQ;
    const int tid = threadIdx.x;
    __shared__ float red[256];

    float mx = -CUDART_INF_F;
#pragma unroll
    for (int t = 0; t < 8; t++) {
        int j = tid + t * 256;
        if (j < nk) mx = fmaxf(mx, p[j]);
    }
    red[tid] = mx;
    __syncthreads();
    for (int s = 128; s > 0; s >>= 1) {
        if (tid < s) red[tid] = fmaxf(red[tid], red[tid + s]);
        __syncthreads();
    }
    mx = red[0];
    __syncthreads();

    float vals[8];
    float sm = 0.0f;
#pragma unroll
    for (int t = 0; t < 8; t++) {
        int j = tid + t * 256;
        float e = (j < nk) ? __expf(p[j] - mx) : 0.0f;
        vals[t] = e;
        sm += e;
    }
    red[tid] = sm;
    __syncthreads();
    for (int s = 128; s > 0; s >>= 1) {
        if (tid < s) red[tid] += red[tid + s];
        __syncthreads();
    }
    const float inv = 1.0f / red[0];
#pragma unroll
    for (int t = 0; t < 8; t++) {
        int j = tid + t * 256;
        if (j < nkp) ph[j] = __float2half_rn(vals[t] * inv);  // 0 in pad region
    }
}

// ---------------- launch ----------------
extern "C" void kernel_launch(void* const* d_in, const int* in_sizes, int n_in,
                              void* d_out, int out_size)
{
    const float* qkv  = (const float*)d_in[0];
    const void*  mask = d_in[1];
    const float* W    = (const float*)d_in[2];
    const float* bqkv = (const float*)d_in[3];
    float* out = (float*)d_out;

    cudaFuncSetAttribute(hmma_gemm<1>, cudaFuncAttributeMaxDynamicSharedMemorySize, SMEM_TOT);
    cudaFuncSetAttribute(hmma_gemm<2>, cudaFuncAttributeMaxDynamicSharedMemorySize, SMEM_TOT);
    cudaFuncSetAttribute(hmma_gemm<4>, cudaFuncAttributeMaxDynamicSharedMemorySize, SMEM_TOT);

    scan_mask_kernel<<<BATCH, 256>>>(mask);

    // split qkv input: fp32 -> fp16 hi/lo
    {
        __half *qh, *ql;
        cudaGetSymbolAddress((void**)&qh, g_qkvh);
        cudaGetSymbolAddress((void**)&ql, g_qkvl);
        int n4 = BATCH * SEQ * DIN / 4;
        split_kernel<<<(n4 + 255) / 256, 256>>>(qkv, qh, ql, n4);
    }
    // transpose + split W: [1024,3072] -> [3072,1024]
    {
        __half *wh, *wl;
        cudaGetSymbolAddress((void**)&wh, g_wth);
        cudaGetSymbolAddress((void**)&wl, g_wtl);
        dim3 grid(N3 / 32, DIN / 32, 1);
        transpose_split_kernel<<<grid, dim3(32, 8)>>>(W, wh, wl, DIN, N3);
    }
    // MERGED projections: q-proj (512 CTAs) + kv-proj (1024 CTAs), wave-packed
    hmma_gemm<4><<<1536, 128, SMEM_TOT>>>(bqkv, nullptr);

    zero_kc_pad_kernel<<<dim3(128, 1, BATCH), 256>>>();
    // transpose compacted V -> V^T fp16
    {
        dim3 grid(DIN / 32, SEQ / 32, BATCH);
        transpose_v_kernel<<<grid, dim3(32, 8)>>>();
    }
    // GEMM2: scores = q @ kc^T (N limited to nkpad via early exit)
    {
        dim3 grid(SEQ / 128, SEQ / 128, BATCH);
        hmma_gemm<1><<<grid, 128, SMEM_TOT>>>(nullptr, nullptr);
    }
    softmax_kernel<<<BATCH * SEQ, 256>>>();
    // GEMM3: out = P_fp16 @ V^T fp16 (K = nkpad dynamic, 1-pass)
    {
        dim3 grid(HD / 128, SEQ / 128, BATCH);
        hmma_gemm<2><<<grid, 128, SMEM_TOT>>>(nullptr, out);
    }
}

// round 13
// speedup vs baseline: 5.1447x; 1.0144x over previous
#include <cuda_runtime.h>
#include <cuda_fp16.h>
#include <math_constants.h>
#include <cstdint>

// Problem constants
#define BATCH 4
#define SEQ   2048
#define DIN   1024
#define HD    1024
#define N3    3072   // 3*HD

// ---------------- device scratch (no allocations allowed) ----------------
__device__ __align__(16) __half g_qkvh[BATCH * SEQ * DIN];
__device__ __align__(16) __half g_qkvl[BATCH * SEQ * DIN];
__device__ __align__(16) __half g_wth[N3 * DIN];
__device__ __align__(16) __half g_wtl[N3 * DIN];
__device__ __align__(16) __half g_qh[BATCH * SEQ * HD];
__device__ __align__(16) __half g_ql[BATCH * SEQ * HD];
__device__ __align__(16) __half g_kch[BATCH * SEQ * HD];   // compacted keys (split)
__device__ __align__(16) __half g_kcl[BATCH * SEQ * HD];
__device__ __align__(16) __half g_vh[BATCH * SEQ * HD];    // compacted V (fp16 rows)
__device__ __align__(16) __half g_vth[BATCH * HD * SEQ];   // compacted V^T (fp16)
__device__ __align__(16) float  g_p[(size_t)BATCH * SEQ * SEQ];
__device__ __align__(16) __half g_ph[(size_t)BATCH * SEQ * SEQ];  // P as fp16
__device__ int g_srcidx[BATCH * SEQ];   // compact j -> original position (0 for j >= nk)
__device__ int g_nk[BATCH];
__device__ int g_nkpad[BATCH];          // ceil128(nk)

// ---------------- helpers ----------------
__device__ __forceinline__ uint32_t smem_u32(const void* p) {
    uint32_t a;
    asm("{ .reg .u64 t; cvta.to.shared.u64 t, %1; cvt.u32.u64 %0, t; }" : "=r"(a) : "l"(p));
    return a;
}
__device__ __forceinline__ void ldm4(uint32_t* r, uint32_t addr) {
    asm volatile("ldmatrix.sync.aligned.m8n8.x4.shared.b16 {%0,%1,%2,%3}, [%4];"
                 : "=r"(r[0]), "=r"(r[1]), "=r"(r[2]), "=r"(r[3]) : "r"(addr));
}
__device__ __forceinline__ void mma16816(float* c, const uint32_t* a,
                                         uint32_t b0, uint32_t b1) {
    asm volatile(
        "mma.sync.aligned.m16n8k16.row.col.f32.f16.f16.f32 "
        "{%0,%1,%2,%3}, {%4,%5,%6,%7}, {%8,%9}, {%0,%1,%2,%3};"
        : "+f"(c[0]), "+f"(c[1]), "+f"(c[2]), "+f"(c[3])
        : "r"(a[0]), "r"(a[1]), "r"(a[2]), "r"(a[3]), "r"(b0), "r"(b1));
}
__device__ __forceinline__ void cpa16(uint32_t dst, const void* src) {
    asm volatile("cp.async.cg.shared.global [%0], [%1], 16;" :: "r"(dst), "l"(src));
}
#define CP_COMMIT() asm volatile("cp.async.commit_group;" ::: "memory")
#define CP_WAIT(n)  asm volatile("cp.async.wait_group %0;" :: "n"(n) : "memory")

// ---------------- mask detect + normalize + compaction scan (fused) --------
__global__ __launch_bounds__(256)
void scan_mask_kernel(const void* mptr)
{
    const int b   = blockIdx.x;
    const int tid = threadIdx.x;
    __shared__ int sums[256];
    __shared__ int okInt, okFloat;
    if (tid == 0) { okInt = 1; okFloat = 1; }
    __syncthreads();
    const unsigned int* w = (const unsigned int*)mptr;
    for (int i = tid; i < 2048; i += 256) {
        unsigned int x = w[i];
        if (!(x == 0u || x == 1u))          okInt = 0;
        if (!(x == 0u || x == 0x3F800000u)) okFloat = 0;
    }
#pragma unroll
    for (int i = 0; i < 8; i++) g_srcidx[b * SEQ + tid * 8 + i] = 0;
    __syncthreads();
    const int flag = okInt ? 0 : (okFloat ? 1 : 2);

    int keep[8], loc[8];
    int s = 0;
#pragma unroll
    for (int i = 0; i < 8; i++) {
        const int gi = b * SEQ + tid * 8 + i;
        int m;
        if (flag == 0)      m = (((const int*)mptr)[gi] != 0);
        else if (flag == 1) m = (((const float*)mptr)[gi] != 0.0f);
        else                m = (((const unsigned char*)mptr)[gi] != 0);
        keep[i] = !m;
        loc[i]  = s;
        s += keep[i];
    }
    sums[tid] = s;
    __syncthreads();
    for (int d = 1; d < 256; d <<= 1) {
        int v = (tid >= d) ? sums[tid - d] : 0;
        __syncthreads();
        sums[tid] += v;
        __syncthreads();
    }
    const int offs = sums[tid] - s;
#pragma unroll
    for (int i = 0; i < 8; i++) {
        if (keep[i]) g_srcidx[b * SEQ + offs + loc[i]] = tid * 8 + i;
    }
    if (tid == 255) {
        const int total = sums[255];
        g_nk[b]    = total;
        g_nkpad[b] = (total + 127) & ~127;
    }
}

// zero the pad rows [nk, nkpad) of compacted K
__global__ __launch_bounds__(256)
void zero_kc_pad_kernel()
{
    const int b   = blockIdx.z;
    const int row = g_nk[b] + blockIdx.x;
    if (row >= g_nkpad[b]) return;
    const size_t idx = ((size_t)b * SEQ + row) * HD + threadIdx.x * 4;
    *(uint2*)(g_kch + idx) = make_uint2(0, 0);
    *(uint2*)(g_kcl + idx) = make_uint2(0, 0);
}

// ---------------- elementwise split: fp32 -> (hi, lo) fp16 ----------------
__global__ __launch_bounds__(256)
void split_kernel(const float* __restrict__ in, __half* __restrict__ oh,
                  __half* __restrict__ ol, int n4)
{
    int i = blockIdx.x * blockDim.x + threadIdx.x;
    if (i >= n4) return;
    float4 v = ((const float4*)in)[i];
    __half h0 = __float2half_rn(v.x), h1 = __float2half_rn(v.y);
    __half h2 = __float2half_rn(v.z), h3 = __float2half_rn(v.w);
    __half l0 = __float2half_rn(v.x - __half2float(h0));
    __half l1 = __float2half_rn(v.y - __half2float(h1));
    __half l2 = __float2half_rn(v.z - __half2float(h2));
    __half l3 = __float2half_rn(v.w - __half2float(h3));
    ((__half2*)oh)[2 * i]     = __halves2half2(h0, h1);
    ((__half2*)oh)[2 * i + 1] = __halves2half2(h2, h3);
    ((__half2*)ol)[2 * i]     = __halves2half2(l0, l1);
    ((__half2*)ol)[2 * i + 1] = __halves2half2(l2, l3);
}

// ---------------- transpose + split W ----------------
__global__ void transpose_split_kernel(const float* __restrict__ in,
                                       __half* __restrict__ oh, __half* __restrict__ ol,
                                       int R, int C)
{
    __shared__ float t[32][33];
    int bx = blockIdx.x * 32, by = blockIdx.y * 32;
    int x = threadIdx.x, y = threadIdx.y;
#pragma unroll
    for (int i = y; i < 32; i += 8) t[i][x] = in[(size_t)(by + i) * C + bx + x];
    __syncthreads();
#pragma unroll
    for (int i = y; i < 32; i += 8) {
        float w = t[x][i];
        __half h = __float2half_rn(w);
        size_t idx = (size_t)(bx + i) * R + by + x;
        oh[idx] = h;
        ol[idx] = __float2half_rn(w - __half2float(h));
    }
}

// ---- transpose compacted V (fp16): vt[h][j] = g_vh[j][h] for j<nk, else 0
__global__ void transpose_v_kernel()
{
    const int b = blockIdx.z;
    const __half* in = g_vh + (size_t)b * SEQ * HD;
    __half* oh = g_vth + (size_t)b * HD * SEQ;
    const int nk = g_nk[b];

    __shared__ __half t[32][33];
    int bx = blockIdx.x * 32;   // head dim
    int by = blockIdx.y * 32;   // compact key dim
    int x = threadIdx.x, y = threadIdx.y;
#pragma unroll
    for (int i = y; i < 32; i += 8) {
        const int j = by + i;
        t[i][x] = (j < nk) ? in[(size_t)j * HD + bx + x] : __half(0.0f);
    }
    __syncthreads();
#pragma unroll
    for (int i = y; i < 32; i += 8)
        oh[(size_t)(bx + i) * SEQ + by + x] = t[x][i];
}

// ---------------- GEMM core: prologue + pipelined mainloop -----------------
#define NSTAGE   3
#define ST_AH    0
#define ST_AL    8192
#define ST_BH    16384
#define ST_BL    24576
#define STAGE_SZ 32768
#define SMEM_TOT (NSTAGE * STAGE_SZ)   // 98304

template <bool ALO, bool BLO>
__device__ __forceinline__ void gemm_core(
    float (&acc)[4][8][4], int NT,
    const __half* pAh0, const __half* pAl0,
    const __half* pBh0, const __half* pBl0,
    const int arow[4], int K,
    uint32_t sbase, uint32_t dA0, int lc,
    uint32_t abase, uint32_t bbase, const uint32_t kcofs[2])
{
    const __half *pAh[4], *pAl[4], *pBh[4], *pBl[4];
#pragma unroll
    for (int i = 0; i < 4; i++) {
        pAh[i] = pAh0 + (size_t)arow[i] * K + lc * 8;
        if (ALO) pAl[i] = pAl0 + (size_t)arow[i] * K + lc * 8;
        pBh[i] = pBh0 + (size_t)i * 32 * K;
        if (BLO) pBl[i] = pBl0 + (size_t)i * 32 * K;
    }

#pragma unroll
    for (int s = 0; s < NSTAGE - 1; s++) {
        const uint32_t sb = sbase + s * STAGE_SZ;
#pragma unroll
        for (int i = 0; i < 4; i++) {
            cpa16(sb + ST_AH + dA0 + i * 2048, pAh[i]);
            if (ALO) { cpa16(sb + ST_AL + dA0 + i * 2048, pAl[i]); pAl[i] += 32; }
            cpa16(sb + ST_BH + dA0 + i * 2048, pBh[i]);
            if (BLO) { cpa16(sb + ST_BL + dA0 + i * 2048, pBl[i]); pBl[i] += 32; }
            pAh[i] += 32; pBh[i] += 32;
        }
        CP_COMMIT();
    }

    for (int kt = 0; kt < NT; kt++) {
        CP_WAIT(NSTAGE - 2);
        __syncthreads();

        if (kt + NSTAGE - 1 < NT) {
            const uint32_t sb = sbase + ((kt + NSTAGE - 1) % NSTAGE) * STAGE_SZ;
#pragma unroll
            for (int i = 0; i < 4; i++) {
                cpa16(sb + ST_AH + dA0 + i * 2048, pAh[i]);
                if (ALO) { cpa16(sb + ST_AL + dA0 + i * 2048, pAl[i]); pAl[i] += 32; }
                cpa16(sb + ST_BH + dA0 + i * 2048, pBh[i]);
                if (BLO) { cpa16(sb + ST_BL + dA0 + i * 2048, pBl[i]); pBl[i] += 32; }
                pAh[i] += 32; pBh[i] += 32;
            }
        }
        CP_COMMIT();

        const uint32_t stb = sbase + (kt % NSTAGE) * STAGE_SZ;
#pragma unroll
        for (int ks = 0; ks < 2; ks++) {
            uint32_t ah[4][4], al[4][4], bh[4][4], bl[4][4];
#pragma unroll
            for (int mt = 0; mt < 4; mt++) {
                ldm4(ah[mt], stb + ST_AH + abase + mt * 1024 + kcofs[ks]);
                if (ALO) ldm4(al[mt], stb + ST_AL + abase + mt * 1024 + kcofs[ks]);
            }
#pragma unroll
            for (int ng = 0; ng < 4; ng++) {
                ldm4(bh[ng], stb + ST_BH + bbase + ng * 1024 + kcofs[ks]);
                if (BLO) ldm4(bl[ng], stb + ST_BL + bbase + ng * 1024 + kcofs[ks]);
            }
#pragma unroll
            for (int mt = 0; mt < 4; mt++)
#pragma unroll
                for (int ng = 0; ng < 4; ng++)
#pragma unroll
                    for (int nb = 0; nb < 2; nb++)
                        mma16816(acc[mt][ng * 2 + nb], ah[mt], bh[ng][nb], bh[ng][nb + 2]);
            if (BLO) {
#pragma unroll
                for (int mt = 0; mt < 4; mt++)
#pragma unroll
                    for (int ng = 0; ng < 4; ng++)
#pragma unroll
                        for (int nb = 0; nb < 2; nb++)
                            mma16816(acc[mt][ng * 2 + nb], ah[mt], bl[ng][nb], bl[ng][nb + 2]);
            }
            if (ALO) {
#pragma unroll
                for (int mt = 0; mt < 4; mt++)
#pragma unroll
                    for (int ng = 0; ng < 4; ng++)
#pragma unroll
                        for (int nb = 0; nb < 2; nb++)
                            mma16816(acc[mt][ng * 2 + nb], al[mt], bh[ng][nb], bh[ng][nb + 2]);
            }
        }
    }
}

// ---------------- fp16 split GEMM kernels, CTA 128x128x32, 2 CTA/SM --------
// MODE 4: MERGED projection launch (1536 linearized CTAs), uniform 3-pass:
//   CTA [0,512):    q-proj
//   CTA [512,1536): kv-proj (gathered rows) -> K split / V fp16
// MODE 1: q_split @ kc_split -> g_p                                  [3-pass]
// MODE 2: P fp16 @ vth fp16 -> out (K = nkpad dynamic)               [1-pass]
template <int MODE>
__global__ __launch_bounds__(128, 2)
void hmma_gemm(const float* __restrict__ bias, float* __restrict__ Cout)
{
    constexpr int K = (MODE == 2) ? 2048 : 1024;

    int z = blockIdx.z;
    int mBase, nBase;
    bool kv = false;
    if constexpr (MODE == 4) {
        const int bx = blockIdx.x;
        if (bx < 512) {                    // q-proj: N=1024 (8 tiles), M=8192 (64 tiles)
            nBase = (bx & 7) * 128;
            mBase = (bx >> 3) * 128;
            z = 0;
        } else {                           // kv-proj: N=2048 (16), M=2048 (16), B=4
            kv = true;
            const int b2 = bx - 512;
            nBase = (b2 & 15) * 128;
            const int rem = b2 >> 4;
            mBase = (rem & 15) * 128;
            z = rem >> 4;
            if (mBase >= g_nk[z]) return;
        }
    } else {
        nBase = blockIdx.x * 128;
        mBase = blockIdx.y * 128;
        if constexpr (MODE == 1) { if (nBase >= g_nkpad[z]) return; }
    }

    int NT;
    if constexpr (MODE == 2) NT = g_nkpad[z] >> 5;
    else NT = 1024 / 32;

    extern __shared__ char smem[];
    const uint32_t sbase = smem_u32(smem);
    const int tid  = threadIdx.x;
    const int wid  = tid >> 5;       // 0..3
    const int lane = tid & 31;
    const int wm   = wid >> 1;       // 0..1
    const int wn   = wid & 1;        // 0..1

    const __half *Ah, *Al, *Bh, *Bl;
    if constexpr (MODE == 4) {
        if (!kv) {
            Ah = g_qkvh; Al = g_qkvl; Bh = g_wth; Bl = g_wtl;
        } else {
            Ah = g_qkvh + (size_t)z * SEQ * DIN; Al = g_qkvl + (size_t)z * SEQ * DIN;
            Bh = g_wth + (size_t)1024 * DIN;     Bl = g_wtl + (size_t)1024 * DIN;
        }
    } else if constexpr (MODE == 1) {
        Ah = g_qh  + (size_t)z * SEQ * HD; Al = g_ql  + (size_t)z * SEQ * HD;
        Bh = g_kch + (size_t)z * SEQ * HD; Bl = g_kcl + (size_t)z * SEQ * HD;
    } else {
        Ah = g_ph  + (size_t)z * SEQ * SEQ; Al = Ah;
        Bh = g_vth + (size_t)z * HD * SEQ;  Bl = Bh;
    }

    // ---- loader / fragment state ----
    const int lrow = tid >> 2;                       // 0..31
    const int lc   = tid & 3;
    const uint32_t swc = (uint32_t)((lc ^ ((lrow >> 1) & 3)) << 4);
    const uint32_t dA0 = (uint32_t)lrow * 64 + swc;
    int arow[4];
#pragma unroll
    for (int i = 0; i < 4; i++) {
        int ar = mBase + lrow + i * 32;
        if constexpr (MODE == 4) { if (kv) ar = g_srcidx[z * SEQ + ar]; }
        arow[i] = ar;
    }
    const __half* pBh0 = Bh + (size_t)(nBase + lrow) * K + lc * 8;
    const __half* pBl0 = Bl + (size_t)(nBase + lrow) * K + lc * 8;

    const int roff = (lane & 7) + ((lane >> 3) & 1) * 8;
    const int cq   = lane >> 4;
    const int xr   = (roff >> 1) & 3;
    const uint32_t abase = (uint32_t)(wm * 64 + roff) * 64;
    const uint32_t bbase = (uint32_t)(wn * 64 + roff) * 64;
    uint32_t kcofs[2];
    kcofs[0] = (uint32_t)((cq ^ xr) << 4);
    kcofs[1] = (uint32_t)(((2 + cq) ^ xr) << 4);

    float acc[4][8][4] = {};

    if constexpr (MODE == 2)
        gemm_core<false, false>(acc, NT, Ah, Al, pBh0, pBl0, arow, K,
                                sbase, dA0, lc, abase, bbase, kcofs);
    else
        gemm_core<true, true>(acc, NT, Ah, Al, pBh0, pBl0, arow, K,
                              sbase, dA0, lc, abase, bbase, kcofs);

    // ---------------- epilogue ----------------
    const int rl = lane >> 2;
    const int cl = 2 * (lane & 3);
#pragma unroll
    for (int mt = 0; mt < 4; mt++) {
#pragma unroll
        for (int nt = 0; nt < 8; nt++) {
            const int r0 = mBase + wm * 64 + mt * 16 + rl;
            const int c0 = nBase + wn * 64 + nt * 8 + cl;
            float* cc = acc[mt][nt];
            if constexpr (MODE == 4) {
                if (!kv) {
                    const float b0 = bias[c0], b1 = bias[c0 + 1];
#pragma unroll
                    for (int rr = 0; rr < 2; rr++) {
                        float w0 = (cc[2 * rr + 0] + b0) * 32.0f;
                        float w1 = (cc[2 * rr + 1] + b1) * 32.0f;
                        __half h0 = __float2half_rn(w0), h1 = __float2half_rn(w1);
                        __half l0 = __float2half_rn(w0 - __half2float(h0));
                        __half l1 = __float2half_rn(w1 - __half2float(h1));
                        size_t idx = (size_t)(r0 + 8 * rr) * HD + c0;
                        *(__half2*)(g_qh + idx) = __halves2half2(h0, h1);
                        *(__half2*)(g_ql + idx) = __halves2half2(l0, l1);
                    }
                } else {
                    const int nk = g_nk[z];
                    const float b0 = bias[1024 + c0], b1 = bias[1024 + c0 + 1];
#pragma unroll
                    for (int rr = 0; rr < 2; rr++) {
                        const int j = r0 + 8 * rr;
                        if (j >= nk) continue;
                        float w0 = cc[2 * rr + 0] + b0;
                        float w1 = cc[2 * rr + 1] + b1;
                        if (c0 < 1024) {
                            __half h0 = __float2half_rn(w0), h1 = __float2half_rn(w1);
                            __half l0 = __float2half_rn(w0 - __half2float(h0));
                            __half l1 = __float2half_rn(w1 - __half2float(h1));
                            size_t idx = ((size_t)z * SEQ + j) * HD + c0;
                            *(__half2*)(g_kch + idx) = __halves2half2(h0, h1);
                            *(__half2*)(g_kcl + idx) = __halves2half2(l0, l1);
                        } else {
                            size_t idx = ((size_t)z * SEQ + j) * HD + (c0 - 1024);
                            *(__half2*)(g_vh + idx) =
                                __halves2half2(__float2half_rn(w0), __float2half_rn(w1));
                        }
                    }
                }
            } else if constexpr (MODE == 1) {
                float* Cb = g_p + (size_t)z * SEQ * SEQ;
                *(float2*)(Cb + (size_t)r0 * SEQ + c0)       = make_float2(cc[0], cc[1]);
                *(float2*)(Cb + (size_t)(r0 + 8) * SEQ + c0) = make_float2(cc[2], cc[3]);
            } else {
                float* Cb = Cout + (size_t)z * SEQ * HD;
                *(float2*)(Cb + (size_t)r0 * HD + c0)        = make_float2(cc[0], cc[1]);
                *(float2*)(Cb + (size_t)(r0 + 8) * HD + c0)  = make_float2(cc[2], cc[3]);
            }
        }
    }
}

// ---------------- softmax over compact scores: g_p -> g_ph (fp16) ----------
__global__ __launch_bounds__(256)
void softmax_kernel()
{
    const int row = blockIdx.x;          // 0..8191
    const int b   = row >> 11;
    const int nk  = g_nk[b];
    const int nkp = g_nkpad[b];
    float* p = g_p + (size_t)row * SEQ;
    __half* ph = g_ph + (size_t)row * SEQ;
    const int tid = threadIdx.x;
    __shared__ float red[256];

    float mx = -CUDART_INF_F;
#pragma unroll
    for (int t = 0; t < 8; t++) {
        int j = tid + t * 256;
        if (j < nk) mx = fmaxf(mx, p[j]);
    }
    red[tid] = mx;
    __syncthreads();
    for (int s = 128; s > 0; s >>= 1) {
        if (tid < s) red[tid] = fmaxf(red[tid], red[tid + s]);
        __syncthreads();
    }
    mx = red[0];
    __syncthreads();

    float vals[8];
    float sm = 0.0f;
#pragma unroll
    for (int t = 0; t < 8; t++) {
        int j = tid + t * 256;
        float e = (j < nk) ? __expf(p[j] - mx) : 0.0f;
        vals[t] = e;
        sm += e;
    }
    red[tid] = sm;
    __syncthreads();
    for (int s = 128; s > 0; s >>= 1) {
        if (tid < s) red[tid] += red[tid + s];
        __syncthreads();
    }
    const float inv = 1.0f / red[0];
#pragma unroll
    for (int t = 0; t < 8; t++) {
        int j = tid + t * 256;
        if (j < nkp) ph[j] = __float2half_rn(vals[t] * inv);  // 0 in pad region
    }
}

// ---------------- launch ----------------
extern "C" void kernel_launch(void* const* d_in, const int* in_sizes, int n_in,
                              void* d_out, int out_size)
{
    const float* qkv  = (const float*)d_in[0];
    const void*  mask = d_in[1];
    const float* W    = (const float*)d_in[2];
    const float* bqkv = (const float*)d_in[3];
    float* out = (float*)d_out;

    cudaFuncSetAttribute(hmma_gemm<1>, cudaFuncAttributeMaxDynamicSharedMemorySize, SMEM_TOT);
    cudaFuncSetAttribute(hmma_gemm<2>, cudaFuncAttributeMaxDynamicSharedMemorySize, SMEM_TOT);
    cudaFuncSetAttribute(hmma_gemm<4>, cudaFuncAttributeMaxDynamicSharedMemorySize, SMEM_TOT);

    scan_mask_kernel<<<BATCH, 256>>>(mask);

    // split qkv input: fp32 -> fp16 hi/lo
    {
        __half *qh, *ql;
        cudaGetSymbolAddress((void**)&qh, g_qkvh);
        cudaGetSymbolAddress((void**)&ql, g_qkvl);
        int n4 = BATCH * SEQ * DIN / 4;
        split_kernel<<<(n4 + 255) / 256, 256>>>(qkv, qh, ql, n4);
    }
    // transpose + split W: [1024,3072] -> [3072,1024]
    {
        __half *wh, *wl;
        cudaGetSymbolAddress((void**)&wh, g_wth);
        cudaGetSymbolAddress((void**)&wl, g_wtl);
        dim3 grid(N3 / 32, DIN / 32, 1);
        transpose_split_kernel<<<grid, dim3(32, 8)>>>(W, wh, wl, DIN, N3);
    }
    // MERGED projections: q-proj (512 CTAs) + kv-proj (1024 CTAs), wave-packed
    hmma_gemm<4><<<1536, 128, SMEM_TOT>>>(bqkv, nullptr);

    zero_kc_pad_kernel<<<dim3(128, 1, BATCH), 256>>>();
    // transpose compacted V (fp16) -> V^T fp16
    {
        dim3 grid(DIN / 32, SEQ / 32, BATCH);
        transpose_v_kernel<<<grid, dim3(32, 8)>>>();
    }
    // GEMM2: scores = q @ kc^T (N limited to nkpad via early exit)
    {
        dim3 grid(SEQ / 128, SEQ / 128, BATCH);
        hmma_gemm<1><<<grid, 128, SMEM_TOT>>>(nullptr, nullptr);
    }
    softmax_kernel<<<BATCH * SEQ, 256>>>();
    // GEMM3: out = P_fp16 @ V^T fp16 (K = nkpad dynamic, 1-pass)
    {
        dim3 grid(HD / 128, SEQ / 128, BATCH);
        hmma_gemm<2><<<grid, 128, SMEM_TOT>>>(nullptr, out);
    }
}

// round 14
// speedup vs baseline: 5.2484x; 1.0202x over previous
#include <cuda_runtime.h>
#include <cuda_fp16.h>
#include <math_constants.h>
#include <cstdint>

// Problem constants
#define BATCH 4
#define SEQ   2048
#define DIN   1024
#define HD    1024
#define N3    3072   // 3*HD

// ---------------- device scratch (no allocations allowed) ----------------
__device__ __align__(16) __half g_qkvh[BATCH * SEQ * DIN];
__device__ __align__(16) __half g_qkvl[BATCH * SEQ * DIN];
__device__ __align__(16) __half g_wth[N3 * DIN];
__device__ __align__(16) __half g_wtl[N3 * DIN];
__device__ __align__(16) __half g_qh[BATCH * SEQ * HD];
__device__ __align__(16) __half g_ql[BATCH * SEQ * HD];
__device__ __align__(16) __half g_kch[BATCH * SEQ * HD];   // compacted keys (split)
__device__ __align__(16) __half g_kcl[BATCH * SEQ * HD];
__device__ __align__(16) __half g_vh[BATCH * SEQ * HD];    // compacted V (fp16 rows)
__device__ __align__(16) __half g_vth[BATCH * HD * SEQ];   // compacted V^T (fp16)
__device__ __align__(16) float  g_p[(size_t)BATCH * SEQ * SEQ];
__device__ __align__(16) __half g_ph[(size_t)BATCH * SEQ * SEQ];  // P as fp16
__device__ int g_srcidx[BATCH * SEQ];   // compact j -> original position (0 for j >= nk)
__device__ int g_nk[BATCH];
__device__ int g_nkpad[BATCH];          // ceil128(nk)

// ---------------- helpers ----------------
__device__ __forceinline__ uint32_t smem_u32(const void* p) {
    uint32_t a;
    asm("{ .reg .u64 t; cvta.to.shared.u64 t, %1; cvt.u32.u64 %0, t; }" : "=r"(a) : "l"(p));
    return a;
}
__device__ __forceinline__ void ldm4(uint32_t* r, uint32_t addr) {
    asm volatile("ldmatrix.sync.aligned.m8n8.x4.shared.b16 {%0,%1,%2,%3}, [%4];"
                 : "=r"(r[0]), "=r"(r[1]), "=r"(r[2]), "=r"(r[3]) : "r"(addr));
}
__device__ __forceinline__ void mma16816(float* c, const uint32_t* a,
                                         uint32_t b0, uint32_t b1) {
    asm volatile(
        "mma.sync.aligned.m16n8k16.row.col.f32.f16.f16.f32 "
        "{%0,%1,%2,%3}, {%4,%5,%6,%7}, {%8,%9}, {%0,%1,%2,%3};"
        : "+f"(c[0]), "+f"(c[1]), "+f"(c[2]), "+f"(c[3])
        : "r"(a[0]), "r"(a[1]), "r"(a[2]), "r"(a[3]), "r"(b0), "r"(b1));
}
__device__ __forceinline__ void cpa16(uint32_t dst, const void* src) {
    asm volatile("cp.async.cg.shared.global [%0], [%1], 16;" :: "r"(dst), "l"(src));
}
#define CP_COMMIT() asm volatile("cp.async.commit_group;" ::: "memory")
#define CP_WAIT(n)  asm volatile("cp.async.wait_group %0;" :: "n"(n) : "memory")

// ---------------- fused prep: mask scan | qkv split | W transpose ----------
// grid.x = 4 (scan) + 8192 (split) + 3072 (transposeW), 256 threads
__global__ __launch_bounds__(256)
void prep_kernel(const void* mptr, const float* __restrict__ qkv,
                 const float* __restrict__ W)
{
    __shared__ __align__(16) char shbuf[32 * 33 * 4];   // 4224B union
    const int bx  = blockIdx.x;
    const int tid = threadIdx.x;

    if (bx < 4) {
        // ---- per-batch mask scan ----
        const int b = bx;
        int* sums = (int*)shbuf;
        int* fl   = (int*)(shbuf + 1024);   // [0]=okInt [1]=okFloat
        if (tid == 0) { fl[0] = 1; fl[1] = 1; }
        __syncthreads();
        const unsigned int* w = (const unsigned int*)mptr;
        for (int i = tid; i < 2048; i += 256) {
            unsigned int x = w[i];
            if (!(x == 0u || x == 1u))          fl[0] = 0;
            if (!(x == 0u || x == 0x3F800000u)) fl[1] = 0;
        }
#pragma unroll
        for (int i = 0; i < 8; i++) g_srcidx[b * SEQ + tid * 8 + i] = 0;
        __syncthreads();
        const int flag = fl[0] ? 0 : (fl[1] ? 1 : 2);

        int keep[8], loc[8];
        int s = 0;
#pragma unroll
        for (int i = 0; i < 8; i++) {
            const int gi = b * SEQ + tid * 8 + i;
            int m;
            if (flag == 0)      m = (((const int*)mptr)[gi] != 0);
            else if (flag == 1) m = (((const float*)mptr)[gi] != 0.0f);
            else                m = (((const unsigned char*)mptr)[gi] != 0);
            keep[i] = !m;
            loc[i]  = s;
            s += keep[i];
        }
        sums[tid] = s;
        __syncthreads();
        for (int d = 1; d < 256; d <<= 1) {
            int v = (tid >= d) ? sums[tid - d] : 0;
            __syncthreads();
            sums[tid] += v;
            __syncthreads();
        }
        const int offs = sums[tid] - s;
#pragma unroll
        for (int i = 0; i < 8; i++) {
            if (keep[i]) g_srcidx[b * SEQ + offs + loc[i]] = tid * 8 + i;
        }
        if (tid == 255) {
            const int total = sums[255];
            g_nk[b]    = total;
            g_nkpad[b] = (total + 127) & ~127;
        }
    } else if (bx < 4 + 8192) {
        // ---- split qkv: fp32 -> fp16 hi/lo (n4 = 2M = 8192*256 exact) ----
        const int i = (bx - 4) * 256 + tid;
        float4 v = ((const float4*)qkv)[i];
        __half h0 = __float2half_rn(v.x), h1 = __float2half_rn(v.y);
        __half h2 = __float2half_rn(v.z), h3 = __float2half_rn(v.w);
        __half l0 = __float2half_rn(v.x - __half2float(h0));
        __half l1 = __float2half_rn(v.y - __half2float(h1));
        __half l2 = __float2half_rn(v.z - __half2float(h2));
        __half l3 = __float2half_rn(v.w - __half2float(h3));
        ((__half2*)g_qkvh)[2 * i]     = __halves2half2(h0, h1);
        ((__half2*)g_qkvh)[2 * i + 1] = __halves2half2(h2, h3);
        ((__half2*)g_qkvl)[2 * i]     = __halves2half2(l0, l1);
        ((__half2*)g_qkvl)[2 * i + 1] = __halves2half2(l2, l3);
    } else {
        // ---- transpose + split W: [1024,3072] -> [3072,1024] ----
        float (*t)[33] = (float(*)[33])shbuf;
        const int b2 = bx - (4 + 8192);
        const int gx = b2 % 96;          // N3/32 tiles
        const int gy = b2 / 96;          // DIN/32 tiles
        const int x = tid & 31, y = tid >> 5;   // (32, 8)
        const int bxc = gx * 32, byc = gy * 32;
#pragma unroll
        for (int i = y; i < 32; i += 8) t[i][x] = W[(size_t)(byc + i) * N3 + bxc + x];
        __syncthreads();
#pragma unroll
        for (int i = y; i < 32; i += 8) {
            float w = t[x][i];
            __half h = __float2half_rn(w);
            size_t idx = (size_t)(bxc + i) * DIN + byc + x;
            g_wth[idx] = h;
            g_wtl[idx] = __float2half_rn(w - __half2float(h));
        }
    }
}

// ---- transpose compacted V (fp16): vt[h][j] = g_vh[j][h] for j<nk, else 0
__global__ void transpose_v_kernel()
{
    const int b = blockIdx.z;
    const __half* in = g_vh + (size_t)b * SEQ * HD;
    __half* oh = g_vth + (size_t)b * HD * SEQ;
    const int nk = g_nk[b];

    __shared__ __half t[32][33];
    int bx = blockIdx.x * 32;   // head dim
    int by = blockIdx.y * 32;   // compact key dim
    int x = threadIdx.x, y = threadIdx.y;
#pragma unroll
    for (int i = y; i < 32; i += 8) {
        const int j = by + i;
        t[i][x] = (j < nk) ? in[(size_t)j * HD + bx + x] : __half(0.0f);
    }
    __syncthreads();
#pragma unroll
    for (int i = y; i < 32; i += 8)
        oh[(size_t)(bx + i) * SEQ + by + x] = t[x][i];
}

// ---------------- GEMM core: prologue + pipelined mainloop -----------------
#define NSTAGE   3
#define ST_AH    0
#define ST_AL    8192
#define ST_BH    16384
#define ST_BL    24576
#define STAGE_SZ 32768
#define SMEM_TOT (NSTAGE * STAGE_SZ)   // 98304

template <bool ALO, bool BLO>
__device__ __forceinline__ void gemm_core(
    float (&acc)[4][8][4], int NT,
    const __half* pAh0, const __half* pAl0,
    const __half* pBh0, const __half* pBl0,
    const int arow[4], int K,
    uint32_t sbase, uint32_t dA0, int lc,
    uint32_t abase, uint32_t bbase, const uint32_t kcofs[2])
{
    const __half *pAh[4], *pAl[4], *pBh[4], *pBl[4];
#pragma unroll
    for (int i = 0; i < 4; i++) {
        pAh[i] = pAh0 + (size_t)arow[i] * K + lc * 8;
        if (ALO) pAl[i] = pAl0 + (size_t)arow[i] * K + lc * 8;
        pBh[i] = pBh0 + (size_t)i * 32 * K;
        if (BLO) pBl[i] = pBl0 + (size_t)i * 32 * K;
    }

#pragma unroll
    for (int s = 0; s < NSTAGE - 1; s++) {
        const uint32_t sb = sbase + s * STAGE_SZ;
#pragma unroll
        for (int i = 0; i < 4; i++) {
            cpa16(sb + ST_AH + dA0 + i * 2048, pAh[i]);
            if (ALO) { cpa16(sb + ST_AL + dA0 + i * 2048, pAl[i]); pAl[i] += 32; }
            cpa16(sb + ST_BH + dA0 + i * 2048, pBh[i]);
            if (BLO) { cpa16(sb + ST_BL + dA0 + i * 2048, pBl[i]); pBl[i] += 32; }
            pAh[i] += 32; pBh[i] += 32;
        }
        CP_COMMIT();
    }

    for (int kt = 0; kt < NT; kt++) {
        CP_WAIT(NSTAGE - 2);
        __syncthreads();

        if (kt + NSTAGE - 1 < NT) {
            const uint32_t sb = sbase + ((kt + NSTAGE - 1) % NSTAGE) * STAGE_SZ;
#pragma unroll
            for (int i = 0; i < 4; i++) {
                cpa16(sb + ST_AH + dA0 + i * 2048, pAh[i]);
                if (ALO) { cpa16(sb + ST_AL + dA0 + i * 2048, pAl[i]); pAl[i] += 32; }
                cpa16(sb + ST_BH + dA0 + i * 2048, pBh[i]);
                if (BLO) { cpa16(sb + ST_BL + dA0 + i * 2048, pBl[i]); pBl[i] += 32; }
                pAh[i] += 32; pBh[i] += 32;
            }
        }
        CP_COMMIT();

        const uint32_t stb = sbase + (kt % NSTAGE) * STAGE_SZ;
#pragma unroll
        for (int ks = 0; ks < 2; ks++) {
            uint32_t ah[4][4], al[4][4], bh[4][4], bl[4][4];
#pragma unroll
            for (int mt = 0; mt < 4; mt++) {
                ldm4(ah[mt], stb + ST_AH + abase + mt * 1024 + kcofs[ks]);
                if (ALO) ldm4(al[mt], stb + ST_AL + abase + mt * 1024 + kcofs[ks]);
            }
#pragma unroll
            for (int ng = 0; ng < 4; ng++) {
                ldm4(bh[ng], stb + ST_BH + bbase + ng * 1024 + kcofs[ks]);
                if (BLO) ldm4(bl[ng], stb + ST_BL + bbase + ng * 1024 + kcofs[ks]);
            }
#pragma unroll
            for (int mt = 0; mt < 4; mt++)
#pragma unroll
                for (int ng = 0; ng < 4; ng++)
#pragma unroll
                    for (int nb = 0; nb < 2; nb++)
                        mma16816(acc[mt][ng * 2 + nb], ah[mt], bh[ng][nb], bh[ng][nb + 2]);
            if (BLO) {
#pragma unroll
                for (int mt = 0; mt < 4; mt++)
#pragma unroll
                    for (int ng = 0; ng < 4; ng++)
#pragma unroll
                        for (int nb = 0; nb < 2; nb++)
                            mma16816(acc[mt][ng * 2 + nb], ah[mt], bl[ng][nb], bl[ng][nb + 2]);
            }
            if (ALO) {
#pragma unroll
                for (int mt = 0; mt < 4; mt++)
#pragma unroll
                    for (int ng = 0; ng < 4; ng++)
#pragma unroll
                        for (int nb = 0; nb < 2; nb++)
                            mma16816(acc[mt][ng * 2 + nb], al[mt], bh[ng][nb], bh[ng][nb + 2]);
            }
        }
    }
}

// ---------------- fp16 split GEMM kernels, CTA 128x128x32, 2 CTA/SM --------
// MODE 4: MERGED projection launch (1536 linearized CTAs), uniform 3-pass:
//   CTA [0,512):    q-proj
//   CTA [512,1536): kv-proj (gathered rows) -> K split / V fp16
//                   CTAs fully in [nk, nkpad) zero their K tile instead
// MODE 1: q_split @ kc_split -> g_p                                  [3-pass]
// MODE 2: P fp16 @ vth fp16 -> out (K = nkpad dynamic)               [1-pass]
template <int MODE>
__global__ __launch_bounds__(128, 2)
void hmma_gemm(const float* __restrict__ bias, float* __restrict__ Cout)
{
    constexpr int K = (MODE == 2) ? 2048 : 1024;

    int z = blockIdx.z;
    int mBase, nBase;
    bool kv = false;
    if constexpr (MODE == 4) {
        const int bx = blockIdx.x;
        if (bx < 512) {                    // q-proj: N=1024 (8 tiles), M=8192 (64 tiles)
            nBase = (bx & 7) * 128;
            mBase = (bx >> 3) * 128;
            z = 0;
        } else {                           // kv-proj: N=2048 (16), M=2048 (16), B=4
            kv = true;
            const int b2 = bx - 512;
            nBase = (b2 & 15) * 128;
            const int rem = b2 >> 4;
            mBase = (rem & 15) * 128;
            z = rem >> 4;
            if (mBase >= g_nkpad[z]) return;
            if (mBase >= g_nk[z]) {
                // whole m-tile is pad: zero this CTA's K-column tile
                if (nBase < 1024) {
                    const int tid = threadIdx.x;
                    const uint4 zz = make_uint4(0, 0, 0, 0);
                    for (int i = tid; i < 2048; i += 128) {   // 128 rows x 16 uint4
                        const int r = i >> 4, c = i & 15;
                        size_t idx = ((size_t)z * SEQ + mBase + r) * HD + nBase + c * 8;
                        *(uint4*)(g_kch + idx) = zz;
                        *(uint4*)(g_kcl + idx) = zz;
                    }
                }
                return;
            }
        }
    } else {
        nBase = blockIdx.x * 128;
        mBase = blockIdx.y * 128;
        if constexpr (MODE == 1) { if (nBase >= g_nkpad[z]) return; }
    }

    int NT;
    if constexpr (MODE == 2) NT = g_nkpad[z] >> 5;
    else NT = 1024 / 32;

    extern __shared__ char smem[];
    const uint32_t sbase = smem_u32(smem);
    const int tid  = threadIdx.x;
    const int wid  = tid >> 5;       // 0..3
    const int lane = tid & 31;
    const int wm   = wid >> 1;       // 0..1
    const int wn   = wid & 1;        // 0..1

    const __half *Ah, *Al, *Bh, *Bl;
    if constexpr (MODE == 4) {
        if (!kv) {
            Ah = g_qkvh; Al = g_qkvl; Bh = g_wth; Bl = g_wtl;
        } else {
            Ah = g_qkvh + (size_t)z * SEQ * DIN; Al = g_qkvl + (size_t)z * SEQ * DIN;
            Bh = g_wth + (size_t)1024 * DIN;     Bl = g_wtl + (size_t)1024 * DIN;
        }
    } else if constexpr (MODE == 1) {
        Ah = g_qh  + (size_t)z * SEQ * HD; Al = g_ql  + (size_t)z * SEQ * HD;
        Bh = g_kch + (size_t)z * SEQ * HD; Bl = g_kcl + (size_t)z * SEQ * HD;
    } else {
        Ah = g_ph  + (size_t)z * SEQ * SEQ; Al = Ah;
        Bh = g_vth + (size_t)z * HD * SEQ;  Bl = Bh;
    }

    // ---- loader / fragment state ----
    const int lrow = tid >> 2;                       // 0..31
    const int lc   = tid & 3;
    const uint32_t swc = (uint32_t)((lc ^ ((lrow >> 1) & 3)) << 4);
    const uint32_t dA0 = (uint32_t)lrow * 64 + swc;
    int arow[4];
#pragma unroll
    for (int i = 0; i < 4; i++) {
        int ar = mBase + lrow + i * 32;
        if constexpr (MODE == 4) { if (kv) ar = g_srcidx[z * SEQ + ar]; }
        arow[i] = ar;
    }
    const __half* pBh0 = Bh + (size_t)(nBase + lrow) * K + lc * 8;
    const __half* pBl0 = Bl + (size_t)(nBase + lrow) * K + lc * 8;

    const int roff = (lane & 7) + ((lane >> 3) & 1) * 8;
    const int cq   = lane >> 4;
    const int xr   = (roff >> 1) & 3;
    const uint32_t abase = (uint32_t)(wm * 64 + roff) * 64;
    const uint32_t bbase = (uint32_t)(wn * 64 + roff) * 64;
    uint32_t kcofs[2];
    kcofs[0] = (uint32_t)((cq ^ xr) << 4);
    kcofs[1] = (uint32_t)(((2 + cq) ^ xr) << 4);

    float acc[4][8][4] = {};

    if constexpr (MODE == 2)
        gemm_core<false, false>(acc, NT, Ah, Al, pBh0, pBl0, arow, K,
                                sbase, dA0, lc, abase, bbase, kcofs);
    else
        gemm_core<true, true>(acc, NT, Ah, Al, pBh0, pBl0, arow, K,
                              sbase, dA0, lc, abase, bbase, kcofs);

    // ---------------- epilogue ----------------
    const int rl = lane >> 2;
    const int cl = 2 * (lane & 3);
#pragma unroll
    for (int mt = 0; mt < 4; mt++) {
#pragma unroll
        for (int nt = 0; nt < 8; nt++) {
            const int r0 = mBase + wm * 64 + mt * 16 + rl;
            const int c0 = nBase + wn * 64 + nt * 8 + cl;
            float* cc = acc[mt][nt];
            if constexpr (MODE == 4) {
                if (!kv) {
                    const float b0 = bias[c0], b1 = bias[c0 + 1];
#pragma unroll
                    for (int rr = 0; rr < 2; rr++) {
                        float w0 = (cc[2 * rr + 0] + b0) * 32.0f;
                        float w1 = (cc[2 * rr + 1] + b1) * 32.0f;
                        __half h0 = __float2half_rn(w0), h1 = __float2half_rn(w1);
                        __half l0 = __float2half_rn(w0 - __half2float(h0));
                        __half l1 = __float2half_rn(w1 - __half2float(h1));
                        size_t idx = (size_t)(r0 + 8 * rr) * HD + c0;
                        *(__half2*)(g_qh + idx) = __halves2half2(h0, h1);
                        *(__half2*)(g_ql + idx) = __halves2half2(l0, l1);
                    }
                } else {
                    const int nk = g_nk[z];
                    const float b0 = bias[1024 + c0], b1 = bias[1024 + c0 + 1];
#pragma unroll
                    for (int rr = 0; rr < 2; rr++) {
                        const int j = r0 + 8 * rr;
                        if (j >= nk) {
                            // pad row within the last active tile: zero K cols
                            if (c0 < 1024) {
                                size_t idx = ((size_t)z * SEQ + j) * HD + c0;
                                *(__half2*)(g_kch + idx) = __halves2half2(__half(0.0f), __half(0.0f));
                                *(__half2*)(g_kcl + idx) = __halves2half2(__half(0.0f), __half(0.0f));
                            }
                            continue;
                        }
                        float w0 = cc[2 * rr + 0] + b0;
                        float w1 = cc[2 * rr + 1] + b1;
                        if (c0 < 1024) {
                            __half h0 = __float2half_rn(w0), h1 = __float2half_rn(w1);
                            __half l0 = __float2half_rn(w0 - __half2float(h0));
                            __half l1 = __float2half_rn(w1 - __half2float(h1));
                            size_t idx = ((size_t)z * SEQ + j) * HD + c0;
                            *(__half2*)(g_kch + idx) = __halves2half2(h0, h1);
                            *(__half2*)(g_kcl + idx) = __halves2half2(l0, l1);
                        } else {
                            size_t idx = ((size_t)z * SEQ + j) * HD + (c0 - 1024);
                            *(__half2*)(g_vh + idx) =
                                __halves2half2(__float2half_rn(w0), __float2half_rn(w1));
                        }
                    }
                }
            } else if constexpr (MODE == 1) {
                float* Cb = g_p + (size_t)z * SEQ * SEQ;
                *(float2*)(Cb + (size_t)r0 * SEQ + c0)       = make_float2(cc[0], cc[1]);
                *(float2*)(Cb + (size_t)(r0 + 8) * SEQ + c0) = make_float2(cc[2], cc[3]);
            } else {
                float* Cb = Cout + (size_t)z * SEQ * HD;
                *(float2*)(Cb + (size_t)r0 * HD + c0)        = make_float2(cc[0], cc[1]);
                *(float2*)(Cb + (size_t)(r0 + 8) * HD + c0)  = make_float2(cc[2], cc[3]);
            }
        }
    }
}

// ---------------- softmax over compact scores: g_p -> g_ph (fp16) ----------
__global__ __launch_bounds__(256)
void softmax_kernel()
{
    const int row = blockIdx.x;          // 0..8191
    const int b   = row >> 11;
    const int nk  = g_nk[b];
    const int nkp = g_nkpad[b];
    float* p = g_p + (size_t)row * SEQ;
    __half* ph = g_ph + (size_t)row * SEQ;
    const int tid = threadIdx.x;
    __shared__ float red[256];

    float mx = -CUDART_INF_F;
#pragma unroll
    for (int t = 0; t < 8; t++) {
        int j = tid + t * 256;
        if (j < nk) mx = fmaxf(mx, p[j]);
    }
    red[tid] = mx;
    __syncthreads();
    for (int s = 128; s > 0; s >>= 1) {
        if (tid < s) red[tid] = fmaxf(red[tid], red[tid + s]);
        __syncthreads();
    }
    mx = red[0];
    __syncthreads();

    float vals[8];
    float sm = 0.0f;
#pragma unroll
    for (int t = 0; t < 8; t++) {
        int j = tid + t * 256;
        float e = (j < nk) ? __expf(p[j] - mx) : 0.0f;
        vals[t] = e;
        sm += e;
    }
    red[tid] = sm;
    __syncthreads();
    for (int s = 128; s > 0; s >>= 1) {
        if (tid < s) red[tid] += red[tid + s];
        __syncthreads();
    }
    const float inv = 1.0f / red[0];
#pragma unroll
    for (int t = 0; t < 8; t++) {
        int j = tid + t * 256;
        if (j < nkp) ph[j] = __float2half_rn(vals[t] * inv);  // 0 in pad region
    }
}

// ---------------- launch ----------------
extern "C" void kernel_launch(void* const* d_in, const int* in_sizes, int n_in,
                              void* d_out, int out_size)
{
    const float* qkv  = (const float*)d_in[0];
    const void*  mask = d_in[1];
    const float* W    = (const float*)d_in[2];
    const float* bqkv = (const float*)d_in[3];
    float* out = (float*)d_out;

    cudaFuncSetAttribute(hmma_gemm<1>, cudaFuncAttributeMaxDynamicSharedMemorySize, SMEM_TOT);
    cudaFuncSetAttribute(hmma_gemm<2>, cudaFuncAttributeMaxDynamicSharedMemorySize, SMEM_TOT);
    cudaFuncSetAttribute(hmma_gemm<4>, cudaFuncAttributeMaxDynamicSharedMemorySize, SMEM_TOT);

    // fused prep: scan (4) + split (8192) + transposeW (3072)
    prep_kernel<<<4 + 8192 + 3072, 256>>>(mask, qkv, W);

    // MERGED projections: q-proj (512 CTAs) + kv-proj (1024 CTAs), wave-packed
    // (pad-zeroing of compacted K folded into kv CTAs)
    hmma_gemm<4><<<1536, 128, SMEM_TOT>>>(bqkv, nullptr);

    // transpose compacted V (fp16) -> V^T fp16
    {
        dim3 grid(DIN / 32, SEQ / 32, BATCH);
        transpose_v_kernel<<<grid, dim3(32, 8)>>>();
    }
    // GEMM2: scores = q @ kc^T (N limited to nkpad via early exit)
    {
        dim3 grid(SEQ / 128, SEQ / 128, BATCH);
        hmma_gemm<1><<<grid, 128, SMEM_TOT>>>(nullptr, nullptr);
    }
    softmax_kernel<<<BATCH * SEQ, 256>>>();
    // GEMM3: out = P_fp16 @ V^T fp16 (K = nkpad dynamic, 1-pass)
    {
        dim3 grid(HD / 128, SEQ / 128, BATCH);
        hmma_gemm<2><<<grid, 128, SMEM_TOT>>>(nullptr, out);
    }
}

// round 15
// speedup vs baseline: 5.3626x; 1.0218x over previous
#include <cuda_runtime.h>
#include <cuda_fp16.h>
#include <math_constants.h>
#include <cstdint>

// Problem constants
#define BATCH 4
#define SEQ   2048
#define DIN   1024
#define HD    1024
#define N3    3072   // 3*HD

// ---------------- device scratch (no allocations allowed) ----------------
__device__ __align__(16) __half g_qkvh[BATCH * SEQ * DIN];
__device__ __align__(16) __half g_qkvl[BATCH * SEQ * DIN];
__device__ __align__(16) __half g_wth[N3 * DIN];
__device__ __align__(16) __half g_wtl[N3 * DIN];
__device__ __align__(16) __half g_qh[BATCH * SEQ * HD];
__device__ __align__(16) __half g_ql[BATCH * SEQ * HD];
__device__ __align__(16) __half g_kch[BATCH * SEQ * HD];   // compacted keys (split)
__device__ __align__(16) __half g_kcl[BATCH * SEQ * HD];
__device__ __align__(16) __half g_vh[BATCH * SEQ * HD];    // compacted V (fp16 rows)
__device__ __align__(16) __half g_vth[BATCH * HD * SEQ];   // compacted V^T (fp16)
__device__ __align__(16) float  g_p[(size_t)BATCH * SEQ * SEQ];
__device__ __align__(16) __half g_ph[(size_t)BATCH * SEQ * SEQ];  // P as fp16
__device__ int g_srcidx[BATCH * SEQ];   // compact j -> original position (0 for j >= nk)
__device__ int g_nk[BATCH];
__device__ int g_nkpad[BATCH];          // ceil128(nk)

// ---------------- helpers ----------------
__device__ __forceinline__ uint32_t smem_u32(const void* p) {
    uint32_t a;
    asm("{ .reg .u64 t; cvta.to.shared.u64 t, %1; cvt.u32.u64 %0, t; }" : "=r"(a) : "l"(p));
    return a;
}
__device__ __forceinline__ void ldm4(uint32_t* r, uint32_t addr) {
    asm volatile("ldmatrix.sync.aligned.m8n8.x4.shared.b16 {%0,%1,%2,%3}, [%4];"
                 : "=r"(r[0]), "=r"(r[1]), "=r"(r[2]), "=r"(r[3]) : "r"(addr));
}
__device__ __forceinline__ void mma16816(float* c, const uint32_t* a,
                                         uint32_t b0, uint32_t b1) {
    asm volatile(
        "mma.sync.aligned.m16n8k16.row.col.f32.f16.f16.f32 "
        "{%0,%1,%2,%3}, {%4,%5,%6,%7}, {%8,%9}, {%0,%1,%2,%3};"
        : "+f"(c[0]), "+f"(c[1]), "+f"(c[2]), "+f"(c[3])
        : "r"(a[0]), "r"(a[1]), "r"(a[2]), "r"(a[3]), "r"(b0), "r"(b1));
}
__device__ __forceinline__ void cpa16(uint32_t dst, const void* src) {
    asm volatile("cp.async.cg.shared.global [%0], [%1], 16;" :: "r"(dst), "l"(src));
}
#define CP_COMMIT() asm volatile("cp.async.commit_group;" ::: "memory")
#define CP_WAIT(n)  asm volatile("cp.async.wait_group %0;" :: "n"(n) : "memory")

// ---------------- fused prep: mask scan | qkv split | W transpose ----------
__global__ __launch_bounds__(256)
void prep_kernel(const void* mptr, const float* __restrict__ qkv,
                 const float* __restrict__ W)
{
    __shared__ __align__(16) char shbuf[32 * 33 * 4];
    const int bx  = blockIdx.x;
    const int tid = threadIdx.x;

    if (bx < 4) {
        const int b = bx;
        int* sums = (int*)shbuf;
        int* fl   = (int*)(shbuf + 1024);
        if (tid == 0) { fl[0] = 1; fl[1] = 1; }
        __syncthreads();
        const unsigned int* w = (const unsigned int*)mptr;
        for (int i = tid; i < 2048; i += 256) {
            unsigned int x = w[i];
            if (!(x == 0u || x == 1u))          fl[0] = 0;
            if (!(x == 0u || x == 0x3F800000u)) fl[1] = 0;
        }
#pragma unroll
        for (int i = 0; i < 8; i++) g_srcidx[b * SEQ + tid * 8 + i] = 0;
        __syncthreads();
        const int flag = fl[0] ? 0 : (fl[1] ? 1 : 2);

        int keep[8], loc[8];
        int s = 0;
#pragma unroll
        for (int i = 0; i < 8; i++) {
            const int gi = b * SEQ + tid * 8 + i;
            int m;
            if (flag == 0)      m = (((const int*)mptr)[gi] != 0);
            else if (flag == 1) m = (((const float*)mptr)[gi] != 0.0f);
            else                m = (((const unsigned char*)mptr)[gi] != 0);
            keep[i] = !m;
            loc[i]  = s;
            s += keep[i];
        }
        sums[tid] = s;
        __syncthreads();
        for (int d = 1; d < 256; d <<= 1) {
            int v = (tid >= d) ? sums[tid - d] : 0;
            __syncthreads();
            sums[tid] += v;
            __syncthreads();
        }
        const int offs = sums[tid] - s;
#pragma unroll
        for (int i = 0; i < 8; i++) {
            if (keep[i]) g_srcidx[b * SEQ + offs + loc[i]] = tid * 8 + i;
        }
        if (tid == 255) {
            const int total = sums[255];
            g_nk[b]    = total;
            g_nkpad[b] = (total + 127) & ~127;
        }
    } else if (bx < 4 + 8192) {
        const int i = (bx - 4) * 256 + tid;
        float4 v = ((const float4*)qkv)[i];
        __half h0 = __float2half_rn(v.x), h1 = __float2half_rn(v.y);
        __half h2 = __float2half_rn(v.z), h3 = __float2half_rn(v.w);
        __half l0 = __float2half_rn(v.x - __half2float(h0));
        __half l1 = __float2half_rn(v.y - __half2float(h1));
        __half l2 = __float2half_rn(v.z - __half2float(h2));
        __half l3 = __float2half_rn(v.w - __half2float(h3));
        ((__half2*)g_qkvh)[2 * i]     = __halves2half2(h0, h1);
        ((__half2*)g_qkvh)[2 * i + 1] = __halves2half2(h2, h3);
        ((__half2*)g_qkvl)[2 * i]     = __halves2half2(l0, l1);
        ((__half2*)g_qkvl)[2 * i + 1] = __halves2half2(l2, l3);
    } else {
        float (*t)[33] = (float(*)[33])shbuf;
        const int b2 = bx - (4 + 8192);
        const int gx = b2 % 96;
        const int gy = b2 / 96;
        const int x = tid & 31, y = tid >> 5;
        const int bxc = gx * 32, byc = gy * 32;
#pragma unroll
        for (int i = y; i < 32; i += 8) t[i][x] = W[(size_t)(byc + i) * N3 + bxc + x];
        __syncthreads();
#pragma unroll
        for (int i = y; i < 32; i += 8) {
            float w = t[x][i];
            __half h = __float2half_rn(w);
            size_t idx = (size_t)(bxc + i) * DIN + byc + x;
            g_wth[idx] = h;
            g_wtl[idx] = __float2half_rn(w - __half2float(h));
        }
    }
}

// ---------------- GEMM core: prologue + pipelined mainloop -----------------
#define NSTAGE   3
#define ST_AH    0
#define ST_AL    8192
#define ST_BH    16384
#define ST_BL    24576
#define STAGE_SZ 32768
#define SMEM_TOT (NSTAGE * STAGE_SZ)   // 98304

template <bool ALO, bool BLO>
__device__ __forceinline__ void gemm_core(
    float (&acc)[4][8][4], int NT,
    const __half* pAh0, const __half* pAl0,
    const __half* pBh0, const __half* pBl0,
    const int arow[4], int K,
    uint32_t sbase, uint32_t dA0, int lc,
    uint32_t abase, uint32_t bbase, const uint32_t kcofs[2])
{
    const __half *pAh[4], *pAl[4], *pBh[4], *pBl[4];
#pragma unroll
    for (int i = 0; i < 4; i++) {
        pAh[i] = pAh0 + (size_t)arow[i] * K + lc * 8;
        if (ALO) pAl[i] = pAl0 + (size_t)arow[i] * K + lc * 8;
        pBh[i] = pBh0 + (size_t)i * 32 * K;
        if (BLO) pBl[i] = pBl0 + (size_t)i * 32 * K;
    }

#pragma unroll
    for (int s = 0; s < NSTAGE - 1; s++) {
        const uint32_t sb = sbase + s * STAGE_SZ;
#pragma unroll
        for (int i = 0; i < 4; i++) {
            cpa16(sb + ST_AH + dA0 + i * 2048, pAh[i]);
            if (ALO) { cpa16(sb + ST_AL + dA0 + i * 2048, pAl[i]); pAl[i] += 32; }
            cpa16(sb + ST_BH + dA0 + i * 2048, pBh[i]);
            if (BLO) { cpa16(sb + ST_BL + dA0 + i * 2048, pBl[i]); pBl[i] += 32; }
            pAh[i] += 32; pBh[i] += 32;
        }
        CP_COMMIT();
    }

    for (int kt = 0; kt < NT; kt++) {
        CP_WAIT(NSTAGE - 2);
        __syncthreads();

        if (kt + NSTAGE - 1 < NT) {
            const uint32_t sb = sbase + ((kt + NSTAGE - 1) % NSTAGE) * STAGE_SZ;
#pragma unroll
            for (int i = 0; i < 4; i++) {
                cpa16(sb + ST_AH + dA0 + i * 2048, pAh[i]);
                if (ALO) { cpa16(sb + ST_AL + dA0 + i * 2048, pAl[i]); pAl[i] += 32; }
                cpa16(sb + ST_BH + dA0 + i * 2048, pBh[i]);
                if (BLO) { cpa16(sb + ST_BL + dA0 + i * 2048, pBl[i]); pBl[i] += 32; }
                pAh[i] += 32; pBh[i] += 32;
            }
        }
        CP_COMMIT();

        const uint32_t stb = sbase + (kt % NSTAGE) * STAGE_SZ;
#pragma unroll
        for (int ks = 0; ks < 2; ks++) {
            uint32_t ah[4][4], al[4][4], bh[4][4], bl[4][4];
#pragma unroll
            for (int mt = 0; mt < 4; mt++) {
                ldm4(ah[mt], stb + ST_AH + abase + mt * 1024 + kcofs[ks]);
                if (ALO) ldm4(al[mt], stb + ST_AL + abase + mt * 1024 + kcofs[ks]);
            }
#pragma unroll
            for (int ng = 0; ng < 4; ng++) {
                ldm4(bh[ng], stb + ST_BH + bbase + ng * 1024 + kcofs[ks]);
                if (BLO) ldm4(bl[ng], stb + ST_BL + bbase + ng * 1024 + kcofs[ks]);
            }
#pragma unroll
            for (int mt = 0; mt < 4; mt++)
#pragma unroll
                for (int ng = 0; ng < 4; ng++)
#pragma unroll
                    for (int nb = 0; nb < 2; nb++)
                        mma16816(acc[mt][ng * 2 + nb], ah[mt], bh[ng][nb], bh[ng][nb + 2]);
            if (BLO) {
#pragma unroll
                for (int mt = 0; mt < 4; mt++)
#pragma unroll
                    for (int ng = 0; ng < 4; ng++)
#pragma unroll
                        for (int nb = 0; nb < 2; nb++)
                            mma16816(acc[mt][ng * 2 + nb], ah[mt], bl[ng][nb], bl[ng][nb + 2]);
            }
            if (ALO) {
#pragma unroll
                for (int mt = 0; mt < 4; mt++)
#pragma unroll
                    for (int ng = 0; ng < 4; ng++)
#pragma unroll
                        for (int nb = 0; nb < 2; nb++)
                            mma16816(acc[mt][ng * 2 + nb], al[mt], bh[ng][nb], bh[ng][nb + 2]);
            }
        }
    }
}

// ---------------- fp16 split GEMM kernels, CTA 128x128x32, 2 CTA/SM --------
// MODE 4: MERGED projection launch (1536 linearized CTAs), uniform 3-pass
// MODE 1: GEMM2 + V-transpose strips merged (1024 + 256 CTAs)
// MODE 2: P fp16 @ vth fp16 -> out (K = nkpad dynamic)               [1-pass]
template <int MODE>
__global__ __launch_bounds__(128, 2)
void hmma_gemm(const float* __restrict__ bias, float* __restrict__ Cout)
{
    constexpr int K = (MODE == 2) ? 2048 : 1024;
    extern __shared__ char smem[];

    int z = blockIdx.z;
    int mBase, nBase;
    bool kv = false;
    if constexpr (MODE == 4) {
        const int bx = blockIdx.x;
        if (bx < 512) {
            nBase = (bx & 7) * 128;
            mBase = (bx >> 3) * 128;
            z = 0;
        } else {
            kv = true;
            const int b2 = bx - 512;
            nBase = (b2 & 15) * 128;
            const int rem = b2 >> 4;
            mBase = (rem & 15) * 128;
            z = rem >> 4;
            if (mBase >= g_nkpad[z]) return;
            if (mBase >= g_nk[z]) {
                if (nBase < 1024) {
                    const int tid = threadIdx.x;
                    const uint4 zz = make_uint4(0, 0, 0, 0);
                    for (int i = tid; i < 2048; i += 128) {
                        const int r = i >> 4, c = i & 15;
                        size_t idx = ((size_t)z * SEQ + mBase + r) * HD + nBase + c * 8;
                        *(uint4*)(g_kch + idx) = zz;
                        *(uint4*)(g_kcl + idx) = zz;
                    }
                }
                return;
            }
        }
    } else if constexpr (MODE == 1) {
        const int bx = blockIdx.x;
        if (bx >= 1024) {
            // ---- V-transpose strip: (batch zb, 32-wide key band), 32 h-tiles ----
            const int tb  = bx - 1024;
            const int zb  = tb >> 6;           // 0..3
            const int by  = (tb & 63) * 32;    // key band
            const int nkb = g_nk[zb];
            const __half* in = g_vh + (size_t)zb * SEQ * HD;
            __half* oh = g_vth + (size_t)zb * HD * SEQ;
            __half (*t)[33] = (__half(*)[33])smem;
            const int x = threadIdx.x & 31, y = threadIdx.x >> 5;  // (32,4)
            for (int hx = 0; hx < HD; hx += 32) {
#pragma unroll
                for (int i = y; i < 32; i += 4) {
                    const int j = by + i;
                    t[i][x] = (j < nkb) ? in[(size_t)j * HD + hx + x] : __half(0.0f);
                }
                __syncthreads();
#pragma unroll
                for (int i = y; i < 32; i += 4)
                    oh[(size_t)(hx + i) * SEQ + by + x] = t[x][i];
                __syncthreads();
            }
            return;
        }
        nBase = (bx & 15) * 128;
        mBase = ((bx >> 4) & 15) * 128;
        z = bx >> 8;
        if (nBase >= g_nkpad[z]) return;
    } else {
        nBase = blockIdx.x * 128;
        mBase = blockIdx.y * 128;
    }

    int NT;
    if constexpr (MODE == 2) NT = g_nkpad[z] >> 5;
    else NT = 1024 / 32;

    const uint32_t sbase = smem_u32(smem);
    const int tid  = threadIdx.x;
    const int wid  = tid >> 5;
    const int lane = tid & 31;
    const int wm   = wid >> 1;
    const int wn   = wid & 1;

    const __half *Ah, *Al, *Bh, *Bl;
    if constexpr (MODE == 4) {
        if (!kv) {
            Ah = g_qkvh; Al = g_qkvl; Bh = g_wth; Bl = g_wtl;
        } else {
            Ah = g_qkvh + (size_t)z * SEQ * DIN; Al = g_qkvl + (size_t)z * SEQ * DIN;
            Bh = g_wth + (size_t)1024 * DIN;     Bl = g_wtl + (size_t)1024 * DIN;
        }
    } else if constexpr (MODE == 1) {
        Ah = g_qh  + (size_t)z * SEQ * HD; Al = g_ql  + (size_t)z * SEQ * HD;
        Bh = g_kch + (size_t)z * SEQ * HD; Bl = g_kcl + (size_t)z * SEQ * HD;
    } else {
        Ah = g_ph  + (size_t)z * SEQ * SEQ; Al = Ah;
        Bh = g_vth + (size_t)z * HD * SEQ;  Bl = Bh;
    }

    const int lrow = tid >> 2;
    const int lc   = tid & 3;
    const uint32_t swc = (uint32_t)((lc ^ ((lrow >> 1) & 3)) << 4);
    const uint32_t dA0 = (uint32_t)lrow * 64 + swc;
    int arow[4];
#pragma unroll
    for (int i = 0; i < 4; i++) {
        int ar = mBase + lrow + i * 32;
        if constexpr (MODE == 4) { if (kv) ar = g_srcidx[z * SEQ + ar]; }
        arow[i] = ar;
    }
    const __half* pBh0 = Bh + (size_t)(nBase + lrow) * K + lc * 8;
    const __half* pBl0 = Bl + (size_t)(nBase + lrow) * K + lc * 8;

    const int roff = (lane & 7) + ((lane >> 3) & 1) * 8;
    const int cq   = lane >> 4;
    const int xr   = (roff >> 1) & 3;
    const uint32_t abase = (uint32_t)(wm * 64 + roff) * 64;
    const uint32_t bbase = (uint32_t)(wn * 64 + roff) * 64;
    uint32_t kcofs[2];
    kcofs[0] = (uint32_t)((cq ^ xr) << 4);
    kcofs[1] = (uint32_t)(((2 + cq) ^ xr) << 4);

    float acc[4][8][4] = {};

    if constexpr (MODE == 2)
        gemm_core<false, false>(acc, NT, Ah, Al, pBh0, pBl0, arow, K,
                                sbase, dA0, lc, abase, bbase, kcofs);
    else
        gemm_core<true, true>(acc, NT, Ah, Al, pBh0, pBl0, arow, K,
                              sbase, dA0, lc, abase, bbase, kcofs);

    // ---------------- epilogue ----------------
    const int rl = lane >> 2;
    const int cl = 2 * (lane & 3);
#pragma unroll
    for (int mt = 0; mt < 4; mt++) {
#pragma unroll
        for (int nt = 0; nt < 8; nt++) {
            const int r0 = mBase + wm * 64 + mt * 16 + rl;
            const int c0 = nBase + wn * 64 + nt * 8 + cl;
            float* cc = acc[mt][nt];
            if constexpr (MODE == 4) {
                if (!kv) {
                    const float b0 = bias[c0], b1 = bias[c0 + 1];
#pragma unroll
                    for (int rr = 0; rr < 2; rr++) {
                        float w0 = (cc[2 * rr + 0] + b0) * 32.0f;
                        float w1 = (cc[2 * rr + 1] + b1) * 32.0f;
                        __half h0 = __float2half_rn(w0), h1 = __float2half_rn(w1);
                        __half l0 = __float2half_rn(w0 - __half2float(h0));
                        __half l1 = __float2half_rn(w1 - __half2float(h1));
                        size_t idx = (size_t)(r0 + 8 * rr) * HD + c0;
                        *(__half2*)(g_qh + idx) = __halves2half2(h0, h1);
                        *(__half2*)(g_ql + idx) = __halves2half2(l0, l1);
                    }
                } else {
                    const int nk = g_nk[z];
                    const float b0 = bias[1024 + c0], b1 = bias[1024 + c0 + 1];
#pragma unroll
                    for (int rr = 0; rr < 2; rr++) {
                        const int j = r0 + 8 * rr;
                        if (j >= nk) {
                            if (c0 < 1024) {
                                size_t idx = ((size_t)z * SEQ + j) * HD + c0;
                                *(__half2*)(g_kch + idx) = __halves2half2(__half(0.0f), __half(0.0f));
                                *(__half2*)(g_kcl + idx) = __halves2half2(__half(0.0f), __half(0.0f));
                            }
                            continue;
                        }
                        float w0 = cc[2 * rr + 0] + b0;
                        float w1 = cc[2 * rr + 1] + b1;
                        if (c0 < 1024) {
                            __half h0 = __float2half_rn(w0), h1 = __float2half_rn(w1);
                            __half l0 = __float2half_rn(w0 - __half2float(h0));
                            __half l1 = __float2half_rn(w1 - __half2float(h1));
                            size_t idx = ((size_t)z * SEQ + j) * HD + c0;
                            *(__half2*)(g_kch + idx) = __halves2half2(h0, h1);
                            *(__half2*)(g_kcl + idx) = __halves2half2(l0, l1);
                        } else {
                            size_t idx = ((size_t)z * SEQ + j) * HD + (c0 - 1024);
                            *(__half2*)(g_vh + idx) =
                                __halves2half2(__float2half_rn(w0), __float2half_rn(w1));
                        }
                    }
                }
            } else if constexpr (MODE == 1) {
                float* Cb = g_p + (size_t)z * SEQ * SEQ;
                *(float2*)(Cb + (size_t)r0 * SEQ + c0)       = make_float2(cc[0], cc[1]);
                *(float2*)(Cb + (size_t)(r0 + 8) * SEQ + c0) = make_float2(cc[2], cc[3]);
            } else {
                float* Cb = Cout + (size_t)z * SEQ * HD;
                *(float2*)(Cb + (size_t)r0 * HD + c0)        = make_float2(cc[0], cc[1]);
                *(float2*)(Cb + (size_t)(r0 + 8) * HD + c0)  = make_float2(cc[2], cc[3]);
            }
        }
    }
}

// ---------------- softmax over compact scores: g_p -> g_ph (fp16) ----------
// vectorized: float4 loads, 8B __half2x2 stores; nkpad is 128-aligned
__global__ __launch_bounds__(256)
void softmax_kernel()
{
    const int row = blockIdx.x;          // 0..8191
    const int b   = row >> 11;
    const int nk  = g_nk[b];
    const int nkp = g_nkpad[b];
    const float* p = g_p + (size_t)row * SEQ;
    __half* ph = g_ph + (size_t)row * SEQ;
    const int tid = threadIdx.x;
    __shared__ float red[256];

    // two float4 groups per thread: cols 4*tid + {0..3} and 1024 + 4*tid + {0..3}
    float4 v[2];
    const int j0 = 4 * tid;
#pragma unroll
    for (int t = 0; t < 2; t++)
        v[t] = *(const float4*)(p + j0 + t * 1024);

    float mx = -CUDART_INF_F;
#pragma unroll
    for (int t = 0; t < 2; t++) {
        const int jb = j0 + t * 1024;
        const float* f = (const float*)&v[t];
#pragma unroll
        for (int e = 0; e < 4; e++)
            if (jb + e < nk) mx = fmaxf(mx, f[e]);
    }
    red[tid] = mx;
    __syncthreads();
    for (int s = 128; s > 0; s >>= 1) {
        if (tid < s) red[tid] = fmaxf(red[tid], red[tid + s]);
        __syncthreads();
    }
    mx = red[0];
    __syncthreads();

    float ev[2][4];
    float sm = 0.0f;
#pragma unroll
    for (int t = 0; t < 2; t++) {
        const int jb = j0 + t * 1024;
        const float* f = (const float*)&v[t];
#pragma unroll
        for (int e = 0; e < 4; e++) {
            float x = (jb + e < nk) ? __expf(f[e] - mx) : 0.0f;
            ev[t][e] = x;
            sm += x;
        }
    }
    red[tid] = sm;
    __syncthreads();
    for (int s = 128; s > 0; s >>= 1) {
        if (tid < s) red[tid] += red[tid + s];
        __syncthreads();
    }
    const float inv = 1.0f / red[0];

#pragma unroll
    for (int t = 0; t < 2; t++) {
        const int jb = j0 + t * 1024;
        if (jb < nkp) {   // 4-group fully inside (nkp 128-aligned)
            __half2 o0 = __halves2half2(__float2half_rn(ev[t][0] * inv),
                                        __float2half_rn(ev[t][1] * inv));
            __half2 o1 = __halves2half2(__float2half_rn(ev[t][2] * inv),
                                        __float2half_rn(ev[t][3] * inv));
            __half2* dst = (__half2*)(ph + jb);
            dst[0] = o0;
            dst[1] = o1;
        }
    }
}

// ---------------- launch ----------------
extern "C" void kernel_launch(void* const* d_in, const int* in_sizes, int n_in,
                              void* d_out, int out_size)
{
    const float* qkv  = (const float*)d_in[0];
    const void*  mask = d_in[1];
    const float* W    = (const float*)d_in[2];
    const float* bqkv = (const float*)d_in[3];
    float* out = (float*)d_out;

    cudaFuncSetAttribute(hmma_gemm<1>, cudaFuncAttributeMaxDynamicSharedMemorySize, SMEM_TOT);
    cudaFuncSetAttribute(hmma_gemm<2>, cudaFuncAttributeMaxDynamicSharedMemorySize, SMEM_TOT);
    cudaFuncSetAttribute(hmma_gemm<4>, cudaFuncAttributeMaxDynamicSharedMemorySize, SMEM_TOT);

    // fused prep: scan (4) + split (8192) + transposeW (3072)
    prep_kernel<<<4 + 8192 + 3072, 256>>>(mask, qkv, W);

    // MERGED projections (pad-zeroing folded in)
    hmma_gemm<4><<<1536, 128, SMEM_TOT>>>(bqkv, nullptr);

    // GEMM2 (1024 CTAs) + V-transpose strips (256 CTAs), one launch
    hmma_gemm<1><<<1024 + 256, 128, SMEM_TOT>>>(nullptr, nullptr);

    softmax_kernel<<<BATCH * SEQ, 256>>>();

    // GEMM3: out = P_fp16 @ V^T fp16 (K = nkpad dynamic, 1-pass)
    {
        dim3 grid(HD / 128, SEQ / 128, BATCH);
        hmma_gemm<2><<<grid, 128, SMEM_TOT>>>(nullptr, out);
    }
}

// round 16
// speedup vs baseline: 5.4078x; 1.0084x over previous
#include <cuda_runtime.h>
#include <cuda_fp16.h>
#include <math_constants.h>
#include <cstdint>

// Problem constants
#define BATCH 4
#define SEQ   2048
#define DIN   1024
#define HD    1024
#define N3    3072   // 3*HD

// ---------------- device scratch (no allocations allowed) ----------------
__device__ __align__(16) __half g_qkvh[BATCH * SEQ * DIN];
__device__ __align__(16) __half g_qkvl[BATCH * SEQ * DIN];
__device__ __align__(16) __half g_wth[N3 * DIN];
__device__ __align__(16) __half g_wtl[N3 * DIN];
__device__ __align__(16) __half g_qh[BATCH * SEQ * HD];
__device__ __align__(16) __half g_ql[BATCH * SEQ * HD];
__device__ __align__(16) __half g_kch[BATCH * SEQ * HD];   // compacted keys (split)
__device__ __align__(16) __half g_kcl[BATCH * SEQ * HD];
__device__ __align__(16) __half g_vh[BATCH * SEQ * HD];    // compacted V (fp16 rows)
__device__ __align__(16) __half g_vth[BATCH * HD * SEQ];   // compacted V^T (fp16)
__device__ __align__(16) float  g_p[(size_t)BATCH * SEQ * SEQ];
__device__ __align__(16) __half g_ph[(size_t)BATCH * SEQ * SEQ];  // P as fp16
__device__ int g_srcidx[BATCH * SEQ];   // compact j -> original position (0 for j >= nk)
__device__ int g_nk[BATCH];
__device__ int g_nkpad[BATCH];          // ceil128(nk)

// ---------------- helpers ----------------
__device__ __forceinline__ uint32_t smem_u32(const void* p) {
    uint32_t a;
    asm("{ .reg .u64 t; cvta.to.shared.u64 t, %1; cvt.u32.u64 %0, t; }" : "=r"(a) : "l"(p));
    return a;
}
__device__ __forceinline__ void ldm4(uint32_t* r, uint32_t addr) {
    asm volatile("ldmatrix.sync.aligned.m8n8.x4.shared.b16 {%0,%1,%2,%3}, [%4];"
                 : "=r"(r[0]), "=r"(r[1]), "=r"(r[2]), "=r"(r[3]) : "r"(addr));
}
__device__ __forceinline__ void mma16816(float* c, const uint32_t* a,
                                         uint32_t b0, uint32_t b1) {
    asm volatile(
        "mma.sync.aligned.m16n8k16.row.col.f32.f16.f16.f32 "
        "{%0,%1,%2,%3}, {%4,%5,%6,%7}, {%8,%9}, {%0,%1,%2,%3};"
        : "+f"(c[0]), "+f"(c[1]), "+f"(c[2]), "+f"(c[3])
        : "r"(a[0]), "r"(a[1]), "r"(a[2]), "r"(a[3]), "r"(b0), "r"(b1));
}
__device__ __forceinline__ void cpa16(uint32_t dst, const void* src) {
    asm volatile("cp.async.cg.shared.global [%0], [%1], 16;" :: "r"(dst), "l"(src));
}
#define CP_COMMIT() asm volatile("cp.async.commit_group;" ::: "memory")
#define CP_WAIT(n)  asm volatile("cp.async.wait_group %0;" :: "n"(n) : "memory")

// ---------------- fused prep: mask scan | qkv split | W transpose ----------
__global__ __launch_bounds__(256)
void prep_kernel(const void* mptr, const float* __restrict__ qkv,
                 const float* __restrict__ W)
{
    __shared__ __align__(16) char shbuf[32 * 33 * 4];
    const int bx  = blockIdx.x;
    const int tid = threadIdx.x;

    if (bx < 4) {
        const int b = bx;
        int* sums = (int*)shbuf;
        int* fl   = (int*)(shbuf + 1024);
        if (tid == 0) { fl[0] = 1; fl[1] = 1; }
        __syncthreads();
        const unsigned int* w = (const unsigned int*)mptr;
        for (int i = tid; i < 2048; i += 256) {
            unsigned int x = w[i];
            if (!(x == 0u || x == 1u))          fl[0] = 0;
            if (!(x == 0u || x == 0x3F800000u)) fl[1] = 0;
        }
#pragma unroll
        for (int i = 0; i < 8; i++) g_srcidx[b * SEQ + tid * 8 + i] = 0;
        __syncthreads();
        const int flag = fl[0] ? 0 : (fl[1] ? 1 : 2);

        int keep[8], loc[8];
        int s = 0;
#pragma unroll
        for (int i = 0; i < 8; i++) {
            const int gi = b * SEQ + tid * 8 + i;
            int m;
            if (flag == 0)      m = (((const int*)mptr)[gi] != 0);
            else if (flag == 1) m = (((const float*)mptr)[gi] != 0.0f);
            else                m = (((const unsigned char*)mptr)[gi] != 0);
            keep[i] = !m;
            loc[i]  = s;
            s += keep[i];
        }
        sums[tid] = s;
        __syncthreads();
        for (int d = 1; d < 256; d <<= 1) {
            int v = (tid >= d) ? sums[tid - d] : 0;
            __syncthreads();
            sums[tid] += v;
            __syncthreads();
        }
        const int offs = sums[tid] - s;
#pragma unroll
        for (int i = 0; i < 8; i++) {
            if (keep[i]) g_srcidx[b * SEQ + offs + loc[i]] = tid * 8 + i;
        }
        if (tid == 255) {
            const int total = sums[255];
            g_nk[b]    = total;
            g_nkpad[b] = (total + 127) & ~127;
        }
    } else if (bx < 4 + 8192) {
        const int i = (bx - 4) * 256 + tid;
        float4 v = ((const float4*)qkv)[i];
        __half h0 = __float2half_rn(v.x), h1 = __float2half_rn(v.y);
        __half h2 = __float2half_rn(v.z), h3 = __float2half_rn(v.w);
        __half l0 = __float2half_rn(v.x - __half2float(h0));
        __half l1 = __float2half_rn(v.y - __half2float(h1));
        __half l2 = __float2half_rn(v.z - __half2float(h2));
        __half l3 = __float2half_rn(v.w - __half2float(h3));
        ((__half2*)g_qkvh)[2 * i]     = __halves2half2(h0, h1);
        ((__half2*)g_qkvh)[2 * i + 1] = __halves2half2(h2, h3);
        ((__half2*)g_qkvl)[2 * i]     = __halves2half2(l0, l1);
        ((__half2*)g_qkvl)[2 * i + 1] = __halves2half2(l2, l3);
    } else {
        float (*t)[33] = (float(*)[33])shbuf;
        const int b2 = bx - (4 + 8192);
        const int gx = b2 % 96;
        const int gy = b2 / 96;
        const int x = tid & 31, y = tid >> 5;
        const int bxc = gx * 32, byc = gy * 32;
#pragma unroll
        for (int i = y; i < 32; i += 8) t[i][x] = W[(size_t)(byc + i) * N3 + bxc + x];
        __syncthreads();
#pragma unroll
        for (int i = y; i < 32; i += 8) {
            float w = t[x][i];
            __half h = __float2half_rn(w);
            size_t idx = (size_t)(bxc + i) * DIN + byc + x;
            g_wth[idx] = h;
            g_wtl[idx] = __float2half_rn(w - __half2float(h));
        }
    }
}

// ---------------- GEMM core: prologue + pipelined mainloop -----------------
#define NSTAGE   3
#define ST_AH    0
#define ST_AL    8192
#define ST_BH    16384
#define ST_BL    24576
#define STAGE_SZ 32768
#define SMEM_TOT (NSTAGE * STAGE_SZ)   // 98304

template <bool ALO, bool BLO>
__device__ __forceinline__ void gemm_core(
    float (&acc)[4][8][4], int NT,
    const __half* pAh0, const __half* pAl0,
    const __half* pBh0, const __half* pBl0,
    const int arow[4], int K,
    uint32_t sbase, uint32_t dA0, int lc,
    uint32_t abase, uint32_t bbase, const uint32_t kcofs[2])
{
    const __half *pAh[4], *pAl[4], *pBh[4], *pBl[4];
#pragma unroll
    for (int i = 0; i < 4; i++) {
        pAh[i] = pAh0 + (size_t)arow[i] * K + lc * 8;
        if (ALO) pAl[i] = pAl0 + (size_t)arow[i] * K + lc * 8;
        pBh[i] = pBh0 + (size_t)i * 32 * K;
        if (BLO) pBl[i] = pBl0 + (size_t)i * 32 * K;
    }

#pragma unroll
    for (int s = 0; s < NSTAGE - 1; s++) {
        const uint32_t sb = sbase + s * STAGE_SZ;
#pragma unroll
        for (int i = 0; i < 4; i++) {
            cpa16(sb + ST_AH + dA0 + i * 2048, pAh[i]);
            if (ALO) { cpa16(sb + ST_AL + dA0 + i * 2048, pAl[i]); pAl[i] += 32; }
            cpa16(sb + ST_BH + dA0 + i * 2048, pBh[i]);
            if (BLO) { cpa16(sb + ST_BL + dA0 + i * 2048, pBl[i]); pBl[i] += 32; }
            pAh[i] += 32; pBh[i] += 32;
        }
        CP_COMMIT();
    }

    for (int kt = 0; kt < NT; kt++) {
        CP_WAIT(NSTAGE - 2);
        __syncthreads();

        if (kt + NSTAGE - 1 < NT) {
            const uint32_t sb = sbase + ((kt + NSTAGE - 1) % NSTAGE) * STAGE_SZ;
#pragma unroll
            for (int i = 0; i < 4; i++) {
                cpa16(sb + ST_AH + dA0 + i * 2048, pAh[i]);
                if (ALO) { cpa16(sb + ST_AL + dA0 + i * 2048, pAl[i]); pAl[i] += 32; }
                cpa16(sb + ST_BH + dA0 + i * 2048, pBh[i]);
                if (BLO) { cpa16(sb + ST_BL + dA0 + i * 2048, pBl[i]); pBl[i] += 32; }
                pAh[i] += 32; pBh[i] += 32;
            }
        }
        CP_COMMIT();

        const uint32_t stb = sbase + (kt % NSTAGE) * STAGE_SZ;
#pragma unroll
        for (int ks = 0; ks < 2; ks++) {
            uint32_t ah[4][4], al[4][4], bh[4][4], bl[4][4];
#pragma unroll
            for (int mt = 0; mt < 4; mt++) {
                ldm4(ah[mt], stb + ST_AH + abase + mt * 1024 + kcofs[ks]);
                if (ALO) ldm4(al[mt], stb + ST_AL + abase + mt * 1024 + kcofs[ks]);
            }
#pragma unroll
            for (int ng = 0; ng < 4; ng++) {
                ldm4(bh[ng], stb + ST_BH + bbase + ng * 1024 + kcofs[ks]);
                if (BLO) ldm4(bl[ng], stb + ST_BL + bbase + ng * 1024 + kcofs[ks]);
            }
#pragma unroll
            for (int mt = 0; mt < 4; mt++)
#pragma unroll
                for (int ng = 0; ng < 4; ng++)
#pragma unroll
                    for (int nb = 0; nb < 2; nb++)
                        mma16816(acc[mt][ng * 2 + nb], ah[mt], bh[ng][nb], bh[ng][nb + 2]);
            if (BLO) {
#pragma unroll
                for (int mt = 0; mt < 4; mt++)
#pragma unroll
                    for (int ng = 0; ng < 4; ng++)
#pragma unroll
                        for (int nb = 0; nb < 2; nb++)
                            mma16816(acc[mt][ng * 2 + nb], ah[mt], bl[ng][nb], bl[ng][nb + 2]);
            }
            if (ALO) {
#pragma unroll
                for (int mt = 0; mt < 4; mt++)
#pragma unroll
                    for (int ng = 0; ng < 4; ng++)
#pragma unroll
                        for (int nb = 0; nb < 2; nb++)
                            mma16816(acc[mt][ng * 2 + nb], al[mt], bh[ng][nb], bh[ng][nb + 2]);
            }
        }
    }
}

// ---------------- fp16 split GEMM kernels, CTA 128x128x32, 2 CTA/SM --------
// MODE 4: MERGED projection launch (1536 linearized CTAs), uniform 3-pass
// MODE 1: GEMM2 + V-transpose strips merged (1024 + 256 CTAs)
// MODE 2: P fp16 @ vth fp16 -> out (K = nkpad dynamic)               [1-pass]
template <int MODE>
__global__ __launch_bounds__(128, 2)
void hmma_gemm(const float* __restrict__ bias, float* __restrict__ Cout)
{
    constexpr int K = (MODE == 2) ? 2048 : 1024;
    extern __shared__ char smem[];

    int z = blockIdx.z;
    int mBase, nBase;
    bool kv = false;
    if constexpr (MODE == 4) {
        const int bx = blockIdx.x;
        if (bx < 512) {
            nBase = (bx & 7) * 128;
            mBase = (bx >> 3) * 128;
            z = 0;
        } else {
            kv = true;
            const int b2 = bx - 512;
            nBase = (b2 & 15) * 128;
            const int rem = b2 >> 4;
            mBase = (rem & 15) * 128;
            z = rem >> 4;
            if (mBase >= g_nkpad[z]) return;
            if (mBase >= g_nk[z]) {
                if (nBase < 1024) {
                    const int tid = threadIdx.x;
                    const uint4 zz = make_uint4(0, 0, 0, 0);
                    for (int i = tid; i < 2048; i += 128) {
                        const int r = i >> 4, c = i & 15;
                        size_t idx = ((size_t)z * SEQ + mBase + r) * HD + nBase + c * 8;
                        *(uint4*)(g_kch + idx) = zz;
                        *(uint4*)(g_kcl + idx) = zz;
                    }
                }
                return;
            }
        }
    } else if constexpr (MODE == 1) {
        const int bx = blockIdx.x;
        if (bx >= 1024) {
            // ---- V-transpose strip: (batch zb, 32-wide key band), 32 h-tiles ----
            const int tb  = bx - 1024;
            const int zb  = tb >> 6;           // 0..3
            const int by  = (tb & 63) * 32;    // key band
            const int nkb = g_nk[zb];
            const __half* in = g_vh + (size_t)zb * SEQ * HD;
            __half* oh = g_vth + (size_t)zb * HD * SEQ;
            __half (*t)[33] = (__half(*)[33])smem;
            const int x = threadIdx.x & 31, y = threadIdx.x >> 5;  // (32,4)
            for (int hx = 0; hx < HD; hx += 32) {
#pragma unroll
                for (int i = y; i < 32; i += 4) {
                    const int j = by + i;
                    t[i][x] = (j < nkb) ? in[(size_t)j * HD + hx + x] : __half(0.0f);
                }
                __syncthreads();
#pragma unroll
                for (int i = y; i < 32; i += 4)
                    oh[(size_t)(hx + i) * SEQ + by + x] = t[x][i];
                __syncthreads();
            }
            return;
        }
        nBase = (bx & 15) * 128;
        mBase = ((bx >> 4) & 15) * 128;
        z = bx >> 8;
        if (nBase >= g_nkpad[z]) return;
    } else {
        nBase = blockIdx.x * 128;
        mBase = blockIdx.y * 128;
    }

    int NT;
    if constexpr (MODE == 2) NT = g_nkpad[z] >> 5;
    else NT = 1024 / 32;

    const uint32_t sbase = smem_u32(smem);
    const int tid  = threadIdx.x;
    const int wid  = tid >> 5;
    const int lane = tid & 31;
    const int wm   = wid >> 1;
    const int wn   = wid & 1;

    const __half *Ah, *Al, *Bh, *Bl;
    if constexpr (MODE == 4) {
        if (!kv) {
            Ah = g_qkvh; Al = g_qkvl; Bh = g_wth; Bl = g_wtl;
        } else {
            Ah = g_qkvh + (size_t)z * SEQ * DIN; Al = g_qkvl + (size_t)z * SEQ * DIN;
            Bh = g_wth + (size_t)1024 * DIN;     Bl = g_wtl + (size_t)1024 * DIN;
        }
    } else if constexpr (MODE == 1) {
        Ah = g_qh  + (size_t)z * SEQ * HD; Al = g_ql  + (size_t)z * SEQ * HD;
        Bh = g_kch + (size_t)z * SEQ * HD; Bl = g_kcl + (size_t)z * SEQ * HD;
    } else {
        Ah = g_ph  + (size_t)z * SEQ * SEQ; Al = Ah;
        Bh = g_vth + (size_t)z * HD * SEQ;  Bl = Bh;
    }

    const int lrow = tid >> 2;
    const int lc   = tid & 3;
    const uint32_t swc = (uint32_t)((lc ^ ((lrow >> 1) & 3)) << 4);
    const uint32_t dA0 = (uint32_t)lrow * 64 + swc;
    int arow[4];
#pragma unroll
    for (int i = 0; i < 4; i++) {
        int ar = mBase + lrow + i * 32;
        if constexpr (MODE == 4) { if (kv) ar = g_srcidx[z * SEQ + ar]; }
        arow[i] = ar;
    }
    const __half* pBh0 = Bh + (size_t)(nBase + lrow) * K + lc * 8;
    const __half* pBl0 = Bl + (size_t)(nBase + lrow) * K + lc * 8;

    const int roff = (lane & 7) + ((lane >> 3) & 1) * 8;
    const int cq   = lane >> 4;
    const int xr   = (roff >> 1) & 3;
    const uint32_t abase = (uint32_t)(wm * 64 + roff) * 64;
    const uint32_t bbase = (uint32_t)(wn * 64 + roff) * 64;
    uint32_t kcofs[2];
    kcofs[0] = (uint32_t)((cq ^ xr) << 4);
    kcofs[1] = (uint32_t)(((2 + cq) ^ xr) << 4);

    float acc[4][8][4] = {};

    if constexpr (MODE == 2)
        gemm_core<false, false>(acc, NT, Ah, Al, pBh0, pBl0, arow, K,
                                sbase, dA0, lc, abase, bbase, kcofs);
    else
        gemm_core<true, true>(acc, NT, Ah, Al, pBh0, pBl0, arow, K,
                              sbase, dA0, lc, abase, bbase, kcofs);

    // ---------------- epilogue ----------------
    const int rl = lane >> 2;
    const int cl = 2 * (lane & 3);
#pragma unroll
    for (int mt = 0; mt < 4; mt++) {
#pragma unroll
        for (int nt = 0; nt < 8; nt++) {
            const int r0 = mBase + wm * 64 + mt * 16 + rl;
            const int c0 = nBase + wn * 64 + nt * 8 + cl;
            float* cc = acc[mt][nt];
            if constexpr (MODE == 4) {
                if (!kv) {
                    const float b0 = bias[c0], b1 = bias[c0 + 1];
#pragma unroll
                    for (int rr = 0; rr < 2; rr++) {
                        float w0 = (cc[2 * rr + 0] + b0) * 32.0f;
                        float w1 = (cc[2 * rr + 1] + b1) * 32.0f;
                        __half h0 = __float2half_rn(w0), h1 = __float2half_rn(w1);
                        __half l0 = __float2half_rn(w0 - __half2float(h0));
                        __half l1 = __float2half_rn(w1 - __half2float(h1));
                        size_t idx = (size_t)(r0 + 8 * rr) * HD + c0;
                        *(__half2*)(g_qh + idx) = __halves2half2(h0, h1);
                        *(__half2*)(g_ql + idx) = __halves2half2(l0, l1);
                    }
                } else {
                    const int nk = g_nk[z];
                    const float b0 = bias[1024 + c0], b1 = bias[1024 + c0 + 1];
#pragma unroll
                    for (int rr = 0; rr < 2; rr++) {
                        const int j = r0 + 8 * rr;
                        if (j >= nk) {
                            if (c0 < 1024) {
                                size_t idx = ((size_t)z * SEQ + j) * HD + c0;
                                *(__half2*)(g_kch + idx) = __halves2half2(__half(0.0f), __half(0.0f));
                                *(__half2*)(g_kcl + idx) = __halves2half2(__half(0.0f), __half(0.0f));
                            }
                            continue;
                        }
                        float w0 = cc[2 * rr + 0] + b0;
                        float w1 = cc[2 * rr + 1] + b1;
                        if (c0 < 1024) {
                            __half h0 = __float2half_rn(w0), h1 = __float2half_rn(w1);
                            __half l0 = __float2half_rn(w0 - __half2float(h0));
                            __half l1 = __float2half_rn(w1 - __half2float(h1));
                            size_t idx = ((size_t)z * SEQ + j) * HD + c0;
                            *(__half2*)(g_kch + idx) = __halves2half2(h0, h1);
                            *(__half2*)(g_kcl + idx) = __halves2half2(l0, l1);
                        } else {
                            size_t idx = ((size_t)z * SEQ + j) * HD + (c0 - 1024);
                            *(__half2*)(g_vh + idx) =
                                __halves2half2(__float2half_rn(w0), __float2half_rn(w1));
                        }
                    }
                }
            } else if constexpr (MODE == 1) {
                float* Cb = g_p + (size_t)z * SEQ * SEQ;
                *(float2*)(Cb + (size_t)r0 * SEQ + c0)       = make_float2(cc[0], cc[1]);
                *(float2*)(Cb + (size_t)(r0 + 8) * SEQ + c0) = make_float2(cc[2], cc[3]);
            } else {
                float* Cb = Cout + (size_t)z * SEQ * HD;
                *(float2*)(Cb + (size_t)r0 * HD + c0)        = make_float2(cc[0], cc[1]);
                *(float2*)(Cb + (size_t)(r0 + 8) * HD + c0)  = make_float2(cc[2], cc[3]);
            }
        }
    }
}

// ---------------- softmax over compact scores: g_p -> g_ph (fp16) ----------
// nkpad-limited loads; warp-shuffle + 8-slot reductions
__global__ __launch_bounds__(256)
void softmax_kernel()
{
    const int row = blockIdx.x;          // 0..8191
    const int b   = row >> 11;
    const int nk  = g_nk[b];
    const int nkp = g_nkpad[b];
    const float* p = g_p + (size_t)row * SEQ;
    __half* ph = g_ph + (size_t)row * SEQ;
    const int tid  = threadIdx.x;
    const int lane = tid & 31;
    const int wrp  = tid >> 5;
    __shared__ float red[8];

    const int j0 = 4 * tid;
    float4 v[2];
    bool have[2];
#pragma unroll
    for (int t = 0; t < 2; t++) {
        const int jb = j0 + t * 1024;
        have[t] = (jb < nkp);
        if (have[t]) v[t] = *(const float4*)(p + jb);
        else         v[t] = make_float4(0.f, 0.f, 0.f, 0.f);
    }

    float mx = -CUDART_INF_F;
#pragma unroll
    for (int t = 0; t < 2; t++) {
        if (!have[t]) continue;
        const int jb = j0 + t * 1024;
        const float* f = (const float*)&v[t];
#pragma unroll
        for (int e = 0; e < 4; e++)
            if (jb + e < nk) mx = fmaxf(mx, f[e]);
    }
#pragma unroll
    for (int o = 16; o > 0; o >>= 1)
        mx = fmaxf(mx, __shfl_xor_sync(0xFFFFFFFFu, mx, o));
    if (lane == 0) red[wrp] = mx;
    __syncthreads();
    {
        float m = red[0];
#pragma unroll
        for (int i = 1; i < 8; i++) m = fmaxf(m, red[i]);
        mx = m;
    }
    __syncthreads();

    float ev[2][4];
    float sm = 0.0f;
#pragma unroll
    for (int t = 0; t < 2; t++) {
        const int jb = j0 + t * 1024;
        const float* f = (const float*)&v[t];
#pragma unroll
        for (int e = 0; e < 4; e++) {
            float x = (have[t] && (jb + e < nk)) ? __expf(f[e] - mx) : 0.0f;
            ev[t][e] = x;
            sm += x;
        }
    }
#pragma unroll
    for (int o = 16; o > 0; o >>= 1)
        sm += __shfl_xor_sync(0xFFFFFFFFu, sm, o);
    if (lane == 0) red[wrp] = sm;
    __syncthreads();
    {
        float s = red[0];
#pragma unroll
        for (int i = 1; i < 8; i++) s += red[i];
        sm = s;
    }
    const float inv = 1.0f / sm;

#pragma unroll
    for (int t = 0; t < 2; t++) {
        if (!have[t]) continue;
        const int jb = j0 + t * 1024;
        __half2 o0 = __halves2half2(__float2half_rn(ev[t][0] * inv),
                                    __float2half_rn(ev[t][1] * inv));
        __half2 o1 = __halves2half2(__float2half_rn(ev[t][2] * inv),
                                    __float2half_rn(ev[t][3] * inv));
        __half2* dst = (__half2*)(ph + jb);
        dst[0] = o0;
        dst[1] = o1;
    }
}

// ---------------- launch ----------------
extern "C" void kernel_launch(void* const* d_in, const int* in_sizes, int n_in,
                              void* d_out, int out_size)
{
    const float* qkv  = (const float*)d_in[0];
    const void*  mask = d_in[1];
    const float* W    = (const float*)d_in[2];
    const float* bqkv = (const float*)d_in[3];
    float* out = (float*)d_out;

    cudaFuncSetAttribute(hmma_gemm<1>, cudaFuncAttributeMaxDynamicSharedMemorySize, SMEM_TOT);
    cudaFuncSetAttribute(hmma_gemm<2>, cudaFuncAttributeMaxDynamicSharedMemorySize, SMEM_TOT);
    cudaFuncSetAttribute(hmma_gemm<4>, cudaFuncAttributeMaxDynamicSharedMemorySize, SMEM_TOT);

    // fused prep: scan (4) + split (8192) + transposeW (3072)
    prep_kernel<<<4 + 8192 + 3072, 256>>>(mask, qkv, W);

    // MERGED projections (pad-zeroing folded in)
    hmma_gemm<4><<<1536, 128, SMEM_TOT>>>(bqkv, nullptr);

    // GEMM2 (1024 CTAs) + V-transpose strips (256 CTAs), one launch
    hmma_gemm<1><<<1024 + 256, 128, SMEM_TOT>>>(nullptr, nullptr);

    softmax_kernel<<<BATCH * SEQ, 256>>>();

    // GEMM3: out = P_fp16 @ V^T fp16 (K = nkpad dynamic, 1-pass)
    {
        dim3 grid(HD / 128, SEQ / 128, BATCH);
        hmma_gemm<2><<<grid, 128, SMEM_TOT>>>(nullptr, out);
    }
}

// round 17
// speedup vs baseline: 5.4492x; 1.0077x over previous
#include <cuda_runtime.h>
#include <cuda_fp16.h>
#include <math_constants.h>
#include <cstdint>

// Problem constants
#define BATCH 4
#define SEQ   2048
#define DIN   1024
#define HD    1024
#define N3    3072   // 3*HD

// ---------------- device scratch (no allocations allowed) ----------------
__device__ __align__(16) __half g_qkvh[BATCH * SEQ * DIN];
__device__ __align__(16) __half g_qkvl[BATCH * SEQ * DIN];
__device__ __align__(16) __half g_wth[N3 * DIN];
__device__ __align__(16) __half g_wtl[N3 * DIN];
__device__ __align__(16) __half g_qh[BATCH * SEQ * HD];
__device__ __align__(16) __half g_ql[BATCH * SEQ * HD];
__device__ __align__(16) __half g_kch[BATCH * SEQ * HD];   // compacted keys (split)
__device__ __align__(16) __half g_kcl[BATCH * SEQ * HD];
__device__ __align__(16) __half g_vh[BATCH * SEQ * HD];    // compacted V (fp16 rows)
__device__ __align__(16) __half g_vth[BATCH * HD * SEQ];   // compacted V^T (fp16)
__device__ __align__(16) float  g_p[(size_t)BATCH * SEQ * SEQ];
__device__ __align__(16) __half g_ph[(size_t)BATCH * SEQ * SEQ];  // P as fp16
__device__ int g_srcidx[BATCH * SEQ];   // compact j -> original position (0 for j >= nk)
__device__ int g_nk[BATCH];
__device__ int g_nkpad[BATCH];          // ceil128(nk)

// ---------------- helpers ----------------
__device__ __forceinline__ uint32_t smem_u32(const void* p) {
    uint32_t a;
    asm("{ .reg .u64 t; cvta.to.shared.u64 t, %1; cvt.u32.u64 %0, t; }" : "=r"(a) : "l"(p));
    return a;
}
__device__ __forceinline__ void ldm4(uint32_t* r, uint32_t addr) {
    asm volatile("ldmatrix.sync.aligned.m8n8.x4.shared.b16 {%0,%1,%2,%3}, [%4];"
                 : "=r"(r[0]), "=r"(r[1]), "=r"(r[2]), "=r"(r[3]) : "r"(addr));
}
__device__ __forceinline__ void mma16816(float* c, const uint32_t* a,
                                         uint32_t b0, uint32_t b1) {
    asm volatile(
        "mma.sync.aligned.m16n8k16.row.col.f32.f16.f16.f32 "
        "{%0,%1,%2,%3}, {%4,%5,%6,%7}, {%8,%9}, {%0,%1,%2,%3};"
        : "+f"(c[0]), "+f"(c[1]), "+f"(c[2]), "+f"(c[3])
        : "r"(a[0]), "r"(a[1]), "r"(a[2]), "r"(a[3]), "r"(b0), "r"(b1));
}
__device__ __forceinline__ void cpa16(uint32_t dst, const void* src) {
    asm volatile("cp.async.cg.shared.global [%0], [%1], 16;" :: "r"(dst), "l"(src));
}
#define CP_COMMIT() asm volatile("cp.async.commit_group;" ::: "memory")
#define CP_WAIT(n)  asm volatile("cp.async.wait_group %0;" :: "n"(n) : "memory")

// ---------------- fused prep: mask scan | qkv split | W transpose ----------
__global__ __launch_bounds__(256)
void prep_kernel(const void* mptr, const float* __restrict__ qkv,
                 const float* __restrict__ W)
{
    __shared__ __align__(16) char shbuf[32 * 33 * 4];
    const int bx  = blockIdx.x;
    const int tid = threadIdx.x;

    if (bx < 4) {
        const int b = bx;
        int* sums = (int*)shbuf;
        int* fl   = (int*)(shbuf + 1024);
        if (tid == 0) { fl[0] = 1; fl[1] = 1; }
        __syncthreads();
        const unsigned int* w = (const unsigned int*)mptr;
        for (int i = tid; i < 2048; i += 256) {
            unsigned int x = w[i];
            if (!(x == 0u || x == 1u))          fl[0] = 0;
            if (!(x == 0u || x == 0x3F800000u)) fl[1] = 0;
        }
#pragma unroll
        for (int i = 0; i < 8; i++) g_srcidx[b * SEQ + tid * 8 + i] = 0;
        __syncthreads();
        const int flag = fl[0] ? 0 : (fl[1] ? 1 : 2);

        int keep[8], loc[8];
        int s = 0;
#pragma unroll
        for (int i = 0; i < 8; i++) {
            const int gi = b * SEQ + tid * 8 + i;
            int m;
            if (flag == 0)      m = (((const int*)mptr)[gi] != 0);
            else if (flag == 1) m = (((const float*)mptr)[gi] != 0.0f);
            else                m = (((const unsigned char*)mptr)[gi] != 0);
            keep[i] = !m;
            loc[i]  = s;
            s += keep[i];
        }
        sums[tid] = s;
        __syncthreads();
        for (int d = 1; d < 256; d <<= 1) {
            int v = (tid >= d) ? sums[tid - d] : 0;
            __syncthreads();
            sums[tid] += v;
            __syncthreads();
        }
        const int offs = sums[tid] - s;
#pragma unroll
        for (int i = 0; i < 8; i++) {
            if (keep[i]) g_srcidx[b * SEQ + offs + loc[i]] = tid * 8 + i;
        }
        if (tid == 255) {
            const int total = sums[255];
            g_nk[b]    = total;
            g_nkpad[b] = (total + 127) & ~127;
        }
    } else if (bx < 4 + 8192) {
        const int i = (bx - 4) * 256 + tid;
        float4 v = ((const float4*)qkv)[i];
        __half h0 = __float2half_rn(v.x), h1 = __float2half_rn(v.y);
        __half h2 = __float2half_rn(v.z), h3 = __float2half_rn(v.w);
        __half l0 = __float2half_rn(v.x - __half2float(h0));
        __half l1 = __float2half_rn(v.y - __half2float(h1));
        __half l2 = __float2half_rn(v.z - __half2float(h2));
        __half l3 = __float2half_rn(v.w - __half2float(h3));
        ((__half2*)g_qkvh)[2 * i]     = __halves2half2(h0, h1);
        ((__half2*)g_qkvh)[2 * i + 1] = __halves2half2(h2, h3);
        ((__half2*)g_qkvl)[2 * i]     = __halves2half2(l0, l1);
        ((__half2*)g_qkvl)[2 * i + 1] = __halves2half2(l2, l3);
    } else {
        float (*t)[33] = (float(*)[33])shbuf;
        const int b2 = bx - (4 + 8192);
        const int gx = b2 % 96;
        const int gy = b2 / 96;
        const int x = tid & 31, y = tid >> 5;
        const int bxc = gx * 32, byc = gy * 32;
#pragma unroll
        for (int i = y; i < 32; i += 8) t[i][x] = W[(size_t)(byc + i) * N3 + bxc + x];
        __syncthreads();
#pragma unroll
        for (int i = y; i < 32; i += 8) {
            float w = t[x][i];
            __half h = __float2half_rn(w);
            size_t idx = (size_t)(bxc + i) * DIN + byc + x;
            g_wth[idx] = h;
            g_wtl[idx] = __float2half_rn(w - __half2float(h));
        }
    }
}

// ---------------- GEMM core: prologue + pipelined mainloop -----------------
#define NSTAGE   3
#define ST_AH    0
#define ST_AL    8192
#define ST_BH    16384
#define ST_BL    24576
#define STAGE_SZ 32768
#define SMEM_TOT (NSTAGE * STAGE_SZ)   // 98304

template <bool ALO, bool BLO>
__device__ __forceinline__ void gemm_core(
    float (&acc)[4][8][4], int NT,
    const __half* pAh0, const __half* pAl0,
    const __half* pBh0, const __half* pBl0,
    const int arow[4], int K,
    uint32_t sbase, uint32_t dA0, int lc,
    uint32_t abase, uint32_t bbase, const uint32_t kcofs[2])
{
    const __half *pAh[4], *pAl[4], *pBh[4], *pBl[4];
#pragma unroll
    for (int i = 0; i < 4; i++) {
        pAh[i] = pAh0 + (size_t)arow[i] * K + lc * 8;
        if (ALO) pAl[i] = pAl0 + (size_t)arow[i] * K + lc * 8;
        pBh[i] = pBh0 + (size_t)i * 32 * K;
        if (BLO) pBl[i] = pBl0 + (size_t)i * 32 * K;
    }

#pragma unroll
    for (int s = 0; s < NSTAGE - 1; s++) {
        const uint32_t sb = sbase + s * STAGE_SZ;
#pragma unroll
        for (int i = 0; i < 4; i++) {
            cpa16(sb + ST_AH + dA0 + i * 2048, pAh[i]);
            if (ALO) { cpa16(sb + ST_AL + dA0 + i * 2048, pAl[i]); pAl[i] += 32; }
            cpa16(sb + ST_BH + dA0 + i * 2048, pBh[i]);
            if (BLO) { cpa16(sb + ST_BL + dA0 + i * 2048, pBl[i]); pBl[i] += 32; }
            pAh[i] += 32; pBh[i] += 32;
        }
        CP_COMMIT();
    }

    for (int kt = 0; kt < NT; kt++) {
        CP_WAIT(NSTAGE - 2);
        __syncthreads();

        if (kt + NSTAGE - 1 < NT) {
            const uint32_t sb = sbase + ((kt + NSTAGE - 1) % NSTAGE) * STAGE_SZ;
#pragma unroll
            for (int i = 0; i < 4; i++) {
                cpa16(sb + ST_AH + dA0 + i * 2048, pAh[i]);
                if (ALO) { cpa16(sb + ST_AL + dA0 + i * 2048, pAl[i]); pAl[i] += 32; }
                cpa16(sb + ST_BH + dA0 + i * 2048, pBh[i]);
                if (BLO) { cpa16(sb + ST_BL + dA0 + i * 2048, pBl[i]); pBl[i] += 32; }
                pAh[i] += 32; pBh[i] += 32;
            }
        }
        CP_COMMIT();

        const uint32_t stb = sbase + (kt % NSTAGE) * STAGE_SZ;
#pragma unroll
        for (int ks = 0; ks < 2; ks++) {
            uint32_t ah[4][4], al[4][4], bh[4][4], bl[4][4];
#pragma unroll
            for (int mt = 0; mt < 4; mt++) {
                ldm4(ah[mt], stb + ST_AH + abase + mt * 1024 + kcofs[ks]);
                if (ALO) ldm4(al[mt], stb + ST_AL + abase + mt * 1024 + kcofs[ks]);
            }
#pragma unroll
            for (int ng = 0; ng < 4; ng++) {
                ldm4(bh[ng], stb + ST_BH + bbase + ng * 1024 + kcofs[ks]);
                if (BLO) ldm4(bl[ng], stb + ST_BL + bbase + ng * 1024 + kcofs[ks]);
            }
#pragma unroll
            for (int mt = 0; mt < 4; mt++)
#pragma unroll
                for (int ng = 0; ng < 4; ng++)
#pragma unroll
                    for (int nb = 0; nb < 2; nb++)
                        mma16816(acc[mt][ng * 2 + nb], ah[mt], bh[ng][nb], bh[ng][nb + 2]);
            if (BLO) {
#pragma unroll
                for (int mt = 0; mt < 4; mt++)
#pragma unroll
                    for (int ng = 0; ng < 4; ng++)
#pragma unroll
                        for (int nb = 0; nb < 2; nb++)
                            mma16816(acc[mt][ng * 2 + nb], ah[mt], bl[ng][nb], bl[ng][nb + 2]);
            }
            if (ALO) {
#pragma unroll
                for (int mt = 0; mt < 4; mt++)
#pragma unroll
                    for (int ng = 0; ng < 4; ng++)
#pragma unroll
                        for (int nb = 0; nb < 2; nb++)
                            mma16816(acc[mt][ng * 2 + nb], al[mt], bh[ng][nb], bh[ng][nb + 2]);
            }
        }
    }
}

// ---------------- fp16 split GEMM kernels, CTA 128x128x32, 2 CTA/SM --------
// MODE 4: MERGED projection launch (1536 linearized CTAs), uniform 3-pass
// MODE 1: GEMM2 + V-transpose strips merged (1024 + 256 CTAs)
// MODE 2: P fp16 @ vth fp16 -> out (K = nkpad dynamic)               [1-pass]
template <int MODE>
__global__ __launch_bounds__(128, 2)
void hmma_gemm(const float* __restrict__ bias, float* __restrict__ Cout)
{
    constexpr int K = (MODE == 2) ? 2048 : 1024;
    extern __shared__ char smem[];

    int z = blockIdx.z;
    int mBase, nBase;
    bool kv = false;
    if constexpr (MODE == 4) {
        const int bx = blockIdx.x;
        if (bx < 512) {
            nBase = (bx & 7) * 128;
            mBase = (bx >> 3) * 128;
            z = 0;
        } else {
            kv = true;
            const int b2 = bx - 512;
            nBase = (b2 & 15) * 128;
            const int rem = b2 >> 4;
            mBase = (rem & 15) * 128;
            z = rem >> 4;
            if (mBase >= g_nkpad[z]) return;
            if (mBase >= g_nk[z]) {
                if (nBase < 1024) {
                    const int tid = threadIdx.x;
                    const uint4 zz = make_uint4(0, 0, 0, 0);
                    for (int i = tid; i < 2048; i += 128) {
                        const int r = i >> 4, c = i & 15;
                        size_t idx = ((size_t)z * SEQ + mBase + r) * HD + nBase + c * 8;
                        *(uint4*)(g_kch + idx) = zz;
                        *(uint4*)(g_kcl + idx) = zz;
                    }
                }
                return;
            }
        }
    } else if constexpr (MODE == 1) {
        const int bx = blockIdx.x;
        if (bx >= 1024) {
            // ---- V-transpose strip: (batch zb, 32-wide key band), 32 h-tiles ----
            const int tb  = bx - 1024;
            const int zb  = tb >> 6;           // 0..3
            const int by  = (tb & 63) * 32;    // key band
            const int nkb = g_nk[zb];
            const __half* in = g_vh + (size_t)zb * SEQ * HD;
            __half* oh = g_vth + (size_t)zb * HD * SEQ;
            __half (*t)[33] = (__half(*)[33])smem;
            const int x = threadIdx.x & 31, y = threadIdx.x >> 5;  // (32,4)
            for (int hx = 0; hx < HD; hx += 32) {
#pragma unroll
                for (int i = y; i < 32; i += 4) {
                    const int j = by + i;
                    t[i][x] = (j < nkb) ? in[(size_t)j * HD + hx + x] : __half(0.0f);
                }
                __syncthreads();
#pragma unroll
                for (int i = y; i < 32; i += 4)
                    oh[(size_t)(hx + i) * SEQ + by + x] = t[x][i];
                __syncthreads();
            }
            return;
        }
        nBase = (bx & 15) * 128;
        mBase = ((bx >> 4) & 15) * 128;
        z = bx >> 8;
        if (nBase >= g_nkpad[z]) return;
    } else {
        nBase = blockIdx.x * 128;
        mBase = blockIdx.y * 128;
    }

    int NT;
    if constexpr (MODE == 2) NT = g_nkpad[z] >> 5;
    else NT = 1024 / 32;

    const uint32_t sbase = smem_u32(smem);
    const int tid  = threadIdx.x;
    const int wid  = tid >> 5;
    const int lane = tid & 31;
    const int wm   = wid >> 1;
    const int wn   = wid & 1;

    const __half *Ah, *Al, *Bh, *Bl;
    if constexpr (MODE == 4) {
        if (!kv) {
            Ah = g_qkvh; Al = g_qkvl; Bh = g_wth; Bl = g_wtl;
        } else {
            Ah = g_qkvh + (size_t)z * SEQ * DIN; Al = g_qkvl + (size_t)z * SEQ * DIN;
            Bh = g_wth + (size_t)1024 * DIN;     Bl = g_wtl + (size_t)1024 * DIN;
        }
    } else if constexpr (MODE == 1) {
        Ah = g_qh  + (size_t)z * SEQ * HD; Al = g_ql  + (size_t)z * SEQ * HD;
        Bh = g_kch + (size_t)z * SEQ * HD; Bl = g_kcl + (size_t)z * SEQ * HD;
    } else {
        Ah = g_ph  + (size_t)z * SEQ * SEQ; Al = Ah;
        Bh = g_vth + (size_t)z * HD * SEQ;  Bl = Bh;
    }

    const int lrow = tid >> 2;
    const int lc   = tid & 3;
    const uint32_t swc = (uint32_t)((lc ^ ((lrow >> 1) & 3)) << 4);
    const uint32_t dA0 = (uint32_t)lrow * 64 + swc;
    int arow[4];
#pragma unroll
    for (int i = 0; i < 4; i++) {
        int ar = mBase + lrow + i * 32;
        if constexpr (MODE == 4) { if (kv) ar = g_srcidx[z * SEQ + ar]; }
        arow[i] = ar;
    }
    const __half* pBh0 = Bh + (size_t)(nBase + lrow) * K + lc * 8;
    const __half* pBl0 = Bl + (size_t)(nBase + lrow) * K + lc * 8;

    const int roff = (lane & 7) + ((lane >> 3) & 1) * 8;
    const int cq   = lane >> 4;
    const int xr   = (roff >> 1) & 3;
    const uint32_t abase = (uint32_t)(wm * 64 + roff) * 64;
    const uint32_t bbase = (uint32_t)(wn * 64 + roff) * 64;
    uint32_t kcofs[2];
    kcofs[0] = (uint32_t)((cq ^ xr) << 4);
    kcofs[1] = (uint32_t)(((2 + cq) ^ xr) << 4);

    float acc[4][8][4] = {};

    if constexpr (MODE == 2)
        gemm_core<false, false>(acc, NT, Ah, Al, pBh0, pBl0, arow, K,
                                sbase, dA0, lc, abase, bbase, kcofs);
    else
        gemm_core<true, true>(acc, NT, Ah, Al, pBh0, pBl0, arow, K,
                              sbase, dA0, lc, abase, bbase, kcofs);

    // ---------------- epilogue ----------------
    const int rl = lane >> 2;
    const int cl = 2 * (lane & 3);
#pragma unroll
    for (int mt = 0; mt < 4; mt++) {
#pragma unroll
        for (int nt = 0; nt < 8; nt++) {
            const int r0 = mBase + wm * 64 + mt * 16 + rl;
            const int c0 = nBase + wn * 64 + nt * 8 + cl;
            float* cc = acc[mt][nt];
            if constexpr (MODE == 4) {
                if (!kv) {
                    const float b0 = bias[c0], b1 = bias[c0 + 1];
#pragma unroll
                    for (int rr = 0; rr < 2; rr++) {
                        float w0 = (cc[2 * rr + 0] + b0) * 32.0f;
                        float w1 = (cc[2 * rr + 1] + b1) * 32.0f;
                        __half h0 = __float2half_rn(w0), h1 = __float2half_rn(w1);
                        __half l0 = __float2half_rn(w0 - __half2float(h0));
                        __half l1 = __float2half_rn(w1 - __half2float(h1));
                        size_t idx = (size_t)(r0 + 8 * rr) * HD + c0;
                        *(__half2*)(g_qh + idx) = __halves2half2(h0, h1);
                        *(__half2*)(g_ql + idx) = __halves2half2(l0, l1);
                    }
                } else {
                    const int nk = g_nk[z];
                    const float b0 = bias[1024 + c0], b1 = bias[1024 + c0 + 1];
#pragma unroll
                    for (int rr = 0; rr < 2; rr++) {
                        const int j = r0 + 8 * rr;
                        if (j >= nk) {
                            if (c0 < 1024) {
                                size_t idx = ((size_t)z * SEQ + j) * HD + c0;
                                *(__half2*)(g_kch + idx) = __halves2half2(__half(0.0f), __half(0.0f));
                                *(__half2*)(g_kcl + idx) = __halves2half2(__half(0.0f), __half(0.0f));
                            }
                            continue;
                        }
                        float w0 = cc[2 * rr + 0] + b0;
                        float w1 = cc[2 * rr + 1] + b1;
                        if (c0 < 1024) {
                            __half h0 = __float2half_rn(w0), h1 = __float2half_rn(w1);
                            __half l0 = __float2half_rn(w0 - __half2float(h0));
                            __half l1 = __float2half_rn(w1 - __half2float(h1));
                            size_t idx = ((size_t)z * SEQ + j) * HD + c0;
                            *(__half2*)(g_kch + idx) = __halves2half2(h0, h1);
                            *(__half2*)(g_kcl + idx) = __halves2half2(l0, l1);
                        } else {
                            size_t idx = ((size_t)z * SEQ + j) * HD + (c0 - 1024);
                            *(__half2*)(g_vh + idx) =
                                __halves2half2(__float2half_rn(w0), __float2half_rn(w1));
                        }
                    }
                }
            } else if constexpr (MODE == 1) {
                float* Cb = g_p + (size_t)z * SEQ * SEQ;
                *(float2*)(Cb + (size_t)r0 * SEQ + c0)       = make_float2(cc[0], cc[1]);
                *(float2*)(Cb + (size_t)(r0 + 8) * SEQ + c0) = make_float2(cc[2], cc[3]);
            } else {
                float* Cb = Cout + (size_t)z * SEQ * HD;
                *(float2*)(Cb + (size_t)r0 * HD + c0)        = make_float2(cc[0], cc[1]);
                *(float2*)(Cb + (size_t)(r0 + 8) * HD + c0)  = make_float2(cc[2], cc[3]);
            }
        }
    }
}

// ---------------- softmax over compact scores: g_p -> g_ph (fp16) ----------
// nkpad-limited loads; group-level guard fast path; shuffle reductions
__global__ __launch_bounds__(256)
void softmax_kernel()
{
    const int row = blockIdx.x;          // 0..8191
    const int b   = row >> 11;
    const int nk  = g_nk[b];
    const int nkp = g_nkpad[b];
    const float* p = g_p + (size_t)row * SEQ;
    __half* ph = g_ph + (size_t)row * SEQ;
    const int tid  = threadIdx.x;
    const int lane = tid & 31;
    const int wrp  = tid >> 5;
    __shared__ float red[8];

    const int j0 = 4 * tid;
    float4 v[2];
    bool have[2], full[2];
#pragma unroll
    for (int t = 0; t < 2; t++) {
        const int jb = j0 + t * 1024;
        have[t] = (jb < nkp);
        full[t] = (jb + 4 <= nk);
        if (have[t]) v[t] = *(const float4*)(p + jb);
        else         v[t] = make_float4(0.f, 0.f, 0.f, 0.f);
    }

    float mx = -CUDART_INF_F;
#pragma unroll
    for (int t = 0; t < 2; t++) {
        const float* f = (const float*)&v[t];
        if (full[t]) {
            mx = fmaxf(mx, fmaxf(fmaxf(f[0], f[1]), fmaxf(f[2], f[3])));
        } else if (have[t]) {
            const int jb = j0 + t * 1024;
#pragma unroll
            for (int e = 0; e < 4; e++)
                if (jb + e < nk) mx = fmaxf(mx, f[e]);
        }
    }
#pragma unroll
    for (int o = 16; o > 0; o >>= 1)
        mx = fmaxf(mx, __shfl_xor_sync(0xFFFFFFFFu, mx, o));
    if (lane == 0) red[wrp] = mx;
    __syncthreads();
    {
        float m = red[0];
#pragma unroll
        for (int i = 1; i < 8; i++) m = fmaxf(m, red[i]);
        mx = m;
    }
    __syncthreads();

    float ev[2][4];
    float sm = 0.0f;
#pragma unroll
    for (int t = 0; t < 2; t++) {
        const float* f = (const float*)&v[t];
        if (full[t]) {
#pragma unroll
            for (int e = 0; e < 4; e++) {
                float x = __expf(f[e] - mx);
                ev[t][e] = x;
                sm += x;
            }
        } else if (have[t]) {
            const int jb = j0 + t * 1024;
#pragma unroll
            for (int e = 0; e < 4; e++) {
                float x = (jb + e < nk) ? __expf(f[e] - mx) : 0.0f;
                ev[t][e] = x;
                sm += x;
            }
        } else {
            ev[t][0] = ev[t][1] = ev[t][2] = ev[t][3] = 0.0f;
        }
    }
#pragma unroll
    for (int o = 16; o > 0; o >>= 1)
        sm += __shfl_xor_sync(0xFFFFFFFFu, sm, o);
    if (lane == 0) red[wrp] = sm;
    __syncthreads();
    {
        float s = red[0];
#pragma unroll
        for (int i = 1; i < 8; i++) s += red[i];
        sm = s;
    }
    const float inv = 1.0f / sm;

#pragma unroll
    for (int t = 0; t < 2; t++) {
        if (!have[t]) continue;
        const int jb = j0 + t * 1024;
        __half2 o0 = __halves2half2(__float2half_rn(ev[t][0] * inv),
                                    __float2half_rn(ev[t][1] * inv));
        __half2 o1 = __halves2half2(__float2half_rn(ev[t][2] * inv),
                                    __float2half_rn(ev[t][3] * inv));
        __half2* dst = (__half2*)(ph + jb);
        dst[0] = o0;
        dst[1] = o1;
    }
}

// ---------------- launch ----------------
extern "C" void kernel_launch(void* const* d_in, const int* in_sizes, int n_in,
                              void* d_out, int out_size)
{
    const float* qkv  = (const float*)d_in[0];
    const void*  mask = d_in[1];
    const float* W    = (const float*)d_in[2];
    const float* bqkv = (const float*)d_in[3];
    float* out = (float*)d_out;

    cudaFuncSetAttribute(hmma_gemm<1>, cudaFuncAttributeMaxDynamicSharedMemorySize, SMEM_TOT);
    cudaFuncSetAttribute(hmma_gemm<2>, cudaFuncAttributeMaxDynamicSharedMemorySize, SMEM_TOT);
    cudaFuncSetAttribute(hmma_gemm<4>, cudaFuncAttributeMaxDynamicSharedMemorySize, SMEM_TOT);

    // fused prep: scan (4) + split (8192) + transposeW (3072)
    prep_kernel<<<4 + 8192 + 3072, 256>>>(mask, qkv, W);

    // MERGED projections (pad-zeroing folded in)
    hmma_gemm<4><<<1536, 128, SMEM_TOT>>>(bqkv, nullptr);

    // GEMM2 (1024 CTAs) + V-transpose strips (256 CTAs), one launch
    hmma_gemm<1><<<1024 + 256, 128, SMEM_TOT>>>(nullptr, nullptr);

    softmax_kernel<<<BATCH * SEQ, 256>>>();

    // GEMM3: out = P_fp16 @ V^T fp16 (K = nkpad dynamic, 1-pass)
    {
        dim3 grid(HD / 128, SEQ / 128, BATCH);
        hmma_gemm<2><<<grid, 128, SMEM_TOT>>>(nullptr, out);
    }
}